// round 12
// baseline (speedup 1.0000x reference)
#include <cuda_runtime.h>
#include <cuda_bf16.h>
#include <math.h>
#include <stdint.h>

// ---------------- problem constants ----------------
#define BB      2
#define LL      2048
#define HH      32
#define KVH     8
#define PP      64
#define DD      2048           // HH*PP
#define CONV    3072           // (HH+2*KVH)*PP
#define PROJ    5152           // CONV + DD + HH
#define CHUNK   128
#define NC      16             // LL/CHUNK
#define EPS     1e-5f

// ---------------- scratch (device globals; no allocation allowed) ----------------
__device__ __align__(16) float g_proj[(size_t)BB * LL * PROJ];
__device__ __align__(16) float g_dt  [(size_t)BB * LL * HH];
__device__ __align__(16) float g_adt [(size_t)BB * LL * HH];
__device__ __align__(16) float g_acs [(size_t)BB * HH * NC * CHUNK];
__device__ __align__(16) float g_tot [(size_t)BB * HH * NC];
__device__ __align__(16) float g_states[(size_t)BB * NC * HH * PP * PP];
__device__ __align__(16) float g_y   [(size_t)BB * LL * DD];

// post-conv vkq stored directly as bf16 hi/lo
__device__ __align__(16) __nv_bfloat16 g_vkhi[(size_t)BB * LL * CONV], g_vklo[(size_t)BB * LL * CONV];

// split-precision bf16 operands for tensor-core GEMMs
__device__ __align__(16) __nv_bfloat16 g_hhi[(size_t)BB * LL * DD], g_hlo[(size_t)BB * LL * DD];
__device__ __align__(16) __nv_bfloat16 g_whi[(size_t)PROJ * DD],    g_wlo[(size_t)PROJ * DD];
__device__ __align__(16) __nv_bfloat16 g_ohi[(size_t)DD * DD],      g_olo[(size_t)DD * DD];
__device__ __align__(16) __nv_bfloat16 g_yhi[(size_t)BB * LL * DD], g_ylo[(size_t)BB * LL * DD];

// ---------------- helpers ----------------
__device__ __forceinline__ float sigmoidf_(float x) { return 1.f / (1.f + expf(-x)); }
__device__ __forceinline__ float softplusf_(float x) { return (x > 20.f) ? x : log1pf(expf(x)); }

__device__ __forceinline__ uint32_t smem_u32(const void* p) {
    uint32_t a;
    asm("{ .reg .u64 t; cvta.to.shared.u64 t, %1; cvt.u32.u64 %0, t; }" : "=r"(a) : "l"(p));
    return a;
}
__device__ __forceinline__ void cpa16(uint32_t dst, const void* src, int srcsize) {
    asm volatile("cp.async.cg.shared.global [%0], [%1], 16, %2;"
                 :: "r"(dst), "l"(src), "r"(srcsize));
}
__device__ __forceinline__ void cpa_commit() { asm volatile("cp.async.commit_group;"); }
template <int N> __device__ __forceinline__ void cpa_wait() {
    asm volatile("cp.async.wait_group %0;" :: "n"(N));
}
__device__ __forceinline__ void ldsm_x4(uint32_t* r, uint32_t a) {
    asm volatile("ldmatrix.sync.aligned.m8n8.x4.shared.b16 {%0,%1,%2,%3}, [%4];"
                 : "=r"(r[0]), "=r"(r[1]), "=r"(r[2]), "=r"(r[3]) : "r"(a));
}
__device__ __forceinline__ void ldsm_x4_t(uint32_t* r, uint32_t a) {
    asm volatile("ldmatrix.sync.aligned.m8n8.x4.trans.shared.b16 {%0,%1,%2,%3}, [%4];"
                 : "=r"(r[0]), "=r"(r[1]), "=r"(r[2]), "=r"(r[3]) : "r"(a));
}
__device__ __forceinline__ void mma16816(float* c, const uint32_t* a, uint32_t b0, uint32_t b1) {
    asm volatile("mma.sync.aligned.m16n8k16.row.col.f32.bf16.bf16.f32 "
                 "{%0,%1,%2,%3}, {%4,%5,%6,%7}, {%8,%9}, {%0,%1,%2,%3};"
                 : "+f"(c[0]), "+f"(c[1]), "+f"(c[2]), "+f"(c[3])
                 : "r"(a[0]), "r"(a[1]), "r"(a[2]), "r"(a[3]), "r"(b0), "r"(b1));
}
__device__ __forceinline__ void split_pair(float f0, float f1, uint32_t& hp, uint32_t& lp) {
    __nv_bfloat16 h0 = __float2bfloat16(f0);
    __nv_bfloat16 h1 = __float2bfloat16(f1);
    __nv_bfloat16 l0 = __float2bfloat16(f0 - __bfloat162float(h0));
    __nv_bfloat16 l1 = __float2bfloat16(f1 - __bfloat162float(h1));
    hp = (uint32_t)__bfloat16_as_ushort(h0) | ((uint32_t)__bfloat16_as_ushort(h1) << 16);
    lp = (uint32_t)__bfloat16_as_ushort(l0) | ((uint32_t)__bfloat16_as_ushort(l1) << 16);
}
// swizzles: rows of 128B (64 bf16) / 256B (128 bf16); 16B group permute
__device__ __forceinline__ uint32_t swz128(int r, int g) { return (uint32_t)(r * 128 + ((g ^ (r & 7)) << 4)); }
__device__ __forceinline__ uint32_t swz256(int r, int g) { return (uint32_t)(r * 256 + ((g ^ (r & 7)) << 4)); }

// store 32 cols of a 64-col fp32 row into swizzled hi/lo tiles (128B rows)
__device__ __forceinline__ void split_row32(uint32_t dH, uint32_t dL,
                                            const float* __restrict__ src,
                                            int r, int c0, float scale) {
#pragma unroll
    for (int c = 0; c < 32; c += 4) {
        float4 v = *reinterpret_cast<const float4*>(src + c);
        uint32_t h0, l0, h1, l1;
        split_pair(v.x * scale, v.y * scale, h0, l0);
        split_pair(v.z * scale, v.w * scale, h1, l1);
        const int col = c0 + c;
        const uint32_t a = swz128(r, col >> 3) + ((col & 7) << 1);
        asm volatile("st.shared.v2.b32 [%0], {%1,%2};" :: "r"(dH + a), "r"(h0), "r"(h1));
        asm volatile("st.shared.v2.b32 [%0], {%1,%2};" :: "r"(dL + a), "r"(l0), "r"(l1));
    }
}

// same but reconstructing fp32 = hi + lo from bf16 pair source (row-offset pointers)
__device__ __forceinline__ void split_row32_rec(uint32_t dH, uint32_t dL,
                                                const __nv_bfloat16* __restrict__ hsrc,
                                                const __nv_bfloat16* __restrict__ lsrc,
                                                int r, int c0, float scale) {
#pragma unroll
    for (int c = 0; c < 32; c += 8) {
        uint4 hv = *reinterpret_cast<const uint4*>(hsrc + c);
        uint4 lv = *reinterpret_cast<const uint4*>(lsrc + c);
        const uint32_t hw[4] = {hv.x, hv.y, hv.z, hv.w};
        const uint32_t lw[4] = {lv.x, lv.y, lv.z, lv.w};
        uint32_t hp[4], lp[4];
#pragma unroll
        for (int j = 0; j < 4; j++) {
            float f0 = __bfloat162float(__ushort_as_bfloat16((unsigned short)(hw[j] & 0xFFFF)))
                     + __bfloat162float(__ushort_as_bfloat16((unsigned short)(lw[j] & 0xFFFF)));
            float f1 = __bfloat162float(__ushort_as_bfloat16((unsigned short)(hw[j] >> 16)))
                     + __bfloat162float(__ushort_as_bfloat16((unsigned short)(lw[j] >> 16)));
            split_pair(f0 * scale, f1 * scale, hp[j], lp[j]);
        }
        const int col = c0 + c;     // multiple of 8
        const uint32_t a = swz128(r, col >> 3);
        asm volatile("st.shared.v4.b32 [%0], {%1,%2,%3,%4};"
                     :: "r"(dH + a), "r"(hp[0]), "r"(hp[1]), "r"(hp[2]), "r"(hp[3]));
        asm volatile("st.shared.v4.b32 [%0], {%1,%2,%3,%4};"
                     :: "r"(dL + a), "r"(lp[0]), "r"(lp[1]), "r"(lp[2]), "r"(lp[3]));
    }
}

// ============================================================
// fp32 -> (bf16 hi, bf16 lo) split, vectorized x4
// ============================================================
__global__ void split_kernel(const float* __restrict__ src,
                             __nv_bfloat16* __restrict__ hi,
                             __nv_bfloat16* __restrict__ lo, int n4) {
    const int i = blockIdx.x * blockDim.x + threadIdx.x;
    if (i >= n4) return;
    const float4 v = reinterpret_cast<const float4*>(src)[i];
    uint32_t h0, l0, h1, l1;
    split_pair(v.x, v.y, h0, l0);
    split_pair(v.z, v.w, h1, l1);
    reinterpret_cast<uint2*>(hi)[i] = make_uint2(h0, h1);
    reinterpret_cast<uint2*>(lo)[i] = make_uint2(l0, l1);
}

// ============================================================
// mma.sync bf16 split-precision GEMM (R7 passing config, frozen)
// ============================================================
#define TILE_BYTES 8192
#define STAGE_BYTES (4 * TILE_BYTES)
#define NSTAGE 3
#define GEMM_SMEM (NSTAGE * STAGE_BYTES)

__device__ __forceinline__ uint32_t sw_off(int r, int g) {
    return (uint32_t)(r * 64 + ((g ^ ((r >> 1) & 3)) << 4));
}

__device__ __forceinline__ void load_stage(
    uint32_t sb, const __nv_bfloat16* __restrict__ Ahi, const __nv_bfloat16* __restrict__ Alo,
    const __nv_bfloat16* __restrict__ Bhi, const __nv_bfloat16* __restrict__ Blo,
    int mBase, int nBase, int Nd, int Kd, int kBase, int tid) {
#pragma unroll
    for (int t = 0; t < 2; t++) {
        const int idx = tid + (t << 8);
        const int r = idx >> 2;
        const int g = idx & 3;
        const uint32_t off = sw_off(r, g);
        const size_t srcA = (size_t)(mBase + r) * Kd + kBase + g * 8;
        cpa16(sb + off, Ahi + srcA, 16);
        cpa16(sb + TILE_BYTES + off, Alo + srcA, 16);
        const int brow = nBase + r;
        const int ok = (brow < Nd) ? 16 : 0;
        const size_t srcB = (size_t)(ok ? brow : (Nd - 1)) * Kd + kBase + g * 8;
        cpa16(sb + 2 * TILE_BYTES + off, Bhi + srcB, ok);
        cpa16(sb + 3 * TILE_BYTES + off, Blo + srcB, ok);
    }
}

__global__ __launch_bounds__(256, 2) void gemm_mma(
    float* __restrict__ C,
    const __nv_bfloat16* __restrict__ Ahi, const __nv_bfloat16* __restrict__ Alo,
    const __nv_bfloat16* __restrict__ Bhi, const __nv_bfloat16* __restrict__ Blo,
    int Nd, int Kd) {
    extern __shared__ __align__(16) char dsm[];
    const int tid  = threadIdx.x;
    const int warp = tid >> 5;
    const int lane = tid & 31;
    const int mBase = blockIdx.y << 7;
    const int nBase = blockIdx.x << 7;
    const int wm = (warp >> 2) << 6;
    const int wn = (warp & 3) << 5;

    const uint32_t smem0 = smem_u32(dsm);

    float acc[4][4][4];
#pragma unroll
    for (int i = 0; i < 4; i++)
#pragma unroll
        for (int j = 0; j < 4; j++)
#pragma unroll
            for (int k = 0; k < 4; k++) acc[i][j][k] = 0.f;

    const int a_r = lane & 15;
    const int a_gsel = lane >> 4;
    const int b_r = (lane & 7) + ((lane & 16) >> 1);
    const int b_gsel = (lane >> 3) & 1;

    const int nk = Kd >> 5;
    load_stage(smem0, Ahi, Alo, Bhi, Blo, mBase, nBase, Nd, Kd, 0, tid);
    cpa_commit();
    load_stage(smem0 + STAGE_BYTES, Ahi, Alo, Bhi, Blo, mBase, nBase, Nd, Kd, 32, tid);
    cpa_commit();

    int bufc = 0;
    for (int s = 0; s < nk; s++) {
        if (s == nk - 1) cpa_wait<0>(); else cpa_wait<1>();
        __syncthreads();
        if (s + 2 < nk) {
            int bufn = bufc + 2; if (bufn >= NSTAGE) bufn -= NSTAGE;
            load_stage(smem0 + bufn * STAGE_BYTES, Ahi, Alo, Bhi, Blo,
                       mBase, nBase, Nd, Kd, (s + 2) << 5, tid);
            cpa_commit();
        }

        const uint32_t sb = smem0 + bufc * STAGE_BYTES;
        const uint32_t tAh = sb, tAl = sb + TILE_BYTES;
        const uint32_t tBh = sb + 2 * TILE_BYTES, tBl = sb + 3 * TILE_BYTES;

#pragma unroll
        for (int ks = 0; ks < 2; ks++) {
            uint32_t a[4][4], b[2][4];
            const int ag = 2 * ks + a_gsel;
            const int bg = 2 * ks + b_gsel;
#pragma unroll
            for (int mt = 0; mt < 4; mt++)
                ldsm_x4(a[mt], tAh + sw_off(wm + mt * 16 + a_r, ag));
#pragma unroll
            for (int p = 0; p < 2; p++)
                ldsm_x4(b[p], tBh + sw_off(wn + p * 16 + b_r, bg));
#pragma unroll
            for (int mt = 0; mt < 4; mt++)
#pragma unroll
                for (int nt = 0; nt < 4; nt++)
                    mma16816(acc[mt][nt], a[mt], b[nt >> 1][(nt & 1) * 2], b[nt >> 1][(nt & 1) * 2 + 1]);
#pragma unroll
            for (int p = 0; p < 2; p++)
                ldsm_x4(b[p], tBl + sw_off(wn + p * 16 + b_r, bg));
#pragma unroll
            for (int mt = 0; mt < 4; mt++)
#pragma unroll
                for (int nt = 0; nt < 4; nt++)
                    mma16816(acc[mt][nt], a[mt], b[nt >> 1][(nt & 1) * 2], b[nt >> 1][(nt & 1) * 2 + 1]);
#pragma unroll
            for (int mt = 0; mt < 4; mt++)
                ldsm_x4(a[mt], tAl + sw_off(wm + mt * 16 + a_r, ag));
#pragma unroll
            for (int p = 0; p < 2; p++)
                ldsm_x4(b[p], tBh + sw_off(wn + p * 16 + b_r, bg));
#pragma unroll
            for (int mt = 0; mt < 4; mt++)
#pragma unroll
                for (int nt = 0; nt < 4; nt++)
                    mma16816(acc[mt][nt], a[mt], b[nt >> 1][(nt & 1) * 2], b[nt >> 1][(nt & 1) * 2 + 1]);
        }
        if (++bufc == NSTAGE) bufc = 0;
    }

    const int gid = lane >> 2, tig = lane & 3;
#pragma unroll
    for (int mt = 0; mt < 4; mt++) {
        const int row0 = mBase + wm + mt * 16 + gid;
#pragma unroll
        for (int nt = 0; nt < 4; nt++) {
            const int col = nBase + wn + nt * 8 + tig * 2;
            if (col < Nd) {
                float2 v01 = make_float2(acc[mt][nt][0], acc[mt][nt][1]);
                float2 v23 = make_float2(acc[mt][nt][2], acc[mt][nt][3]);
                *reinterpret_cast<float2*>(C + (size_t)row0 * Nd + col) = v01;
                *reinterpret_cast<float2*>(C + (size_t)(row0 + 8) * Nd + col) = v23;
            }
        }
    }
}

// ============================================================
// Conv (kernel=2, causal) + SiLU -> bf16 hi/lo directly
// ============================================================
__global__ void conv_silu_kernel(const float* __restrict__ conv_w,
                                 const float* __restrict__ conv_b) {
    const size_t idx = (size_t)blockIdx.x * blockDim.x + threadIdx.x;
    if (idx >= (size_t)BB * LL * CONV) return;
    const int c = (int)(idx % CONV);
    const size_t bl = idx / CONV;
    const int l = (int)(bl % LL);
    const float cur = g_proj[bl * PROJ + c];
    const float prev = (l > 0) ? g_proj[(bl - 1) * PROJ + c] : 0.f;
    const float v = prev * conv_w[c * 2] + cur * conv_w[c * 2 + 1] + conv_b[c];
    const float o = v * sigmoidf_(v);
    __nv_bfloat16 hi = __float2bfloat16(o);
    g_vkhi[idx] = hi;
    g_vklo[idx] = __float2bfloat16(o - __bfloat162float(hi));
}

__global__ void dt_kernel(const float* __restrict__ dt_bias,
                          const float* __restrict__ A_log_bias) {
    const int idx = blockIdx.x * blockDim.x + threadIdx.x;
    if (idx >= BB * LL * HH) return;
    const int h = idx % HH;
    const size_t bl = idx / HH;
    const float raw = g_proj[bl * PROJ + (CONV + DD) + h];
    const float dtv = softplusf_(raw + dt_bias[h]);
    g_dt[idx] = dtv;
    g_adt[idx] = dtv * (-expf(A_log_bias[h]));
}

// ============================================================
// Pass A (mma): per-(b,c,h) parallel cumsum + local chunk state
// ============================================================
#define CS_KH   0
#define CS_KL   16384
#define CS_XH   32768
#define CS_XL   49152
#define CS_ACS  65536
#define CS_SMEM (65536 + 512)

__global__ __launch_bounds__(128) void chunk_state_mma() {
    extern __shared__ __align__(16) char dsm[];
    const uint32_t sb = smem_u32(dsm);
    float* sAcs = reinterpret_cast<float*>(dsm + CS_ACS);

    const int h = blockIdx.x, c = blockIdx.y, b = blockIdx.z;
    const int tid = threadIdx.x;
    const int kvh = h >> 2;

    sAcs[tid] = g_adt[((size_t)b * LL + c * CHUNK + tid) * HH + h];
    __syncthreads();
    // Hillis-Steele inclusive scan over 128 elements
#pragma unroll
    for (int off = 1; off < CHUNK; off <<= 1) {
        const float v = sAcs[tid];
        const float u = (tid >= off) ? sAcs[tid - off] : 0.f;
        __syncthreads();
        sAcs[tid] = v + u;
        __syncthreads();
    }
    const float total = sAcs[CHUNK - 1];
    g_acs[(((size_t)b * HH + h) * NC + c) * CHUNK + tid] = sAcs[tid];
    if (tid == 0)
        g_tot[((size_t)b * HH + h) * NC + c] = total;

    {
        const int l = tid;
        const size_t base = ((size_t)b * LL + c * CHUNK + l) * CONV;
        const float w = expf(total - sAcs[l]);
        const float dtv = g_dt[((size_t)b * LL + c * CHUNK + l) * HH + h];
        const size_t ko = base + KVH * PP + kvh * PP;
        const size_t vo = base + kvh * PP;
        const float ws = w * dtv;
        split_row32_rec(sb + CS_KH, sb + CS_KL, g_vkhi + ko,      g_vklo + ko,      l, 0,  ws);
        split_row32_rec(sb + CS_KH, sb + CS_KL, g_vkhi + ko + 32, g_vklo + ko + 32, l, 32, ws);
        split_row32_rec(sb + CS_XH, sb + CS_XL, g_vkhi + vo,      g_vklo + vo,      l, 0,  1.f);
        split_row32_rec(sb + CS_XH, sb + CS_XL, g_vkhi + vo + 32, g_vklo + vo + 32, l, 32, 1.f);
    }
    __syncthreads();

    const int warp = tid >> 5, lane = tid & 31;
    const int wn = warp * 16;
    const int tA_kr = (lane & 7) + ((lane >> 4) & 1) * 8;
    const int tA_mg = (lane >> 3) & 1;
    const int tB_kr = (lane & 7) + ((lane >> 3) & 1) * 8;
    const int tB_ng = (lane >> 4) & 1;

    float acc[4][2][4];
#pragma unroll
    for (int i = 0; i < 4; i++)
#pragma unroll
        for (int j = 0; j < 2; j++)
#pragma unroll
            for (int k = 0; k < 4; k++) acc[i][j][k] = 0.f;

#pragma unroll
    for (int ks = 0; ks < 8; ks++) {
        const int kra = ks * 16 + tA_kr;
        const int krb = ks * 16 + tB_kr;
        uint32_t ah[4][4], al[4][4], bh[4], bl[4];
#pragma unroll
        for (int mt = 0; mt < 4; mt++)
            ldsm_x4_t(ah[mt], sb + CS_KH + swz128(kra, mt * 2 + tA_mg));
        ldsm_x4_t(bh, sb + CS_XH + swz128(krb, (wn >> 3) + tB_ng));
#pragma unroll
        for (int mt = 0; mt < 4; mt++)
#pragma unroll
            for (int nt = 0; nt < 2; nt++)
                mma16816(acc[mt][nt], ah[mt], bh[nt * 2], bh[nt * 2 + 1]);
#pragma unroll
        for (int mt = 0; mt < 4; mt++)
            ldsm_x4_t(al[mt], sb + CS_KL + swz128(kra, mt * 2 + tA_mg));
#pragma unroll
        for (int mt = 0; mt < 4; mt++)
#pragma unroll
            for (int nt = 0; nt < 2; nt++)
                mma16816(acc[mt][nt], al[mt], bh[nt * 2], bh[nt * 2 + 1]);
        ldsm_x4_t(bl, sb + CS_XL + swz128(krb, (wn >> 3) + tB_ng));
#pragma unroll
        for (int mt = 0; mt < 4; mt++)
#pragma unroll
            for (int nt = 0; nt < 2; nt++)
                mma16816(acc[mt][nt], ah[mt], bl[nt * 2], bl[nt * 2 + 1]);
    }

    const int gid = lane >> 2, tig = lane & 3;
    const size_t so = (((size_t)b * NC + c) * HH + h) * (PP * PP);
#pragma unroll
    for (int mt = 0; mt < 4; mt++) {
        const int n0 = mt * 16 + gid;
#pragma unroll
        for (int nt = 0; nt < 2; nt++) {
            const int p = wn + nt * 8 + tig * 2;
            *reinterpret_cast<float2*>(&g_states[so + (size_t)n0 * PP + p]) =
                make_float2(acc[mt][nt][0], acc[mt][nt][1]);
            *reinterpret_cast<float2*>(&g_states[so + (size_t)(n0 + 8) * PP + p]) =
                make_float2(acc[mt][nt][2], acc[mt][nt][3]);
        }
    }
}

// ============================================================
// Pass B: inter-chunk scan, parallelized over element slabs
// ============================================================
__global__ void state_scan_kernel() {
    __shared__ float et[NC];
    const int bh = blockIdx.x >> 3;
    const int slab = blockIdx.x & 7;
    const int b = bh / HH, h = bh % HH;
    if (threadIdx.x < NC)
        et[threadIdx.x] = expf(g_tot[(size_t)bh * NC + threadIdx.x]);
    __syncthreads();
    const int e0 = slab * 512;
    for (int e = e0 + threadIdx.x; e < e0 + 512; e += blockDim.x) {
        float S = 0.f;
        for (int c = 0; c < NC; c++) {
            const size_t idx = (((size_t)b * NC + c) * HH + h) * (PP * PP) + e;
            const float loc = g_states[idx];
            g_states[idx] = S;
            S = et[c] * S + loc;
        }
    }
}

// ============================================================
// Pass C (mma): Y = (mask(C.B^T)·decay·dt) X + exp(Acs) C.S_start
// G overlays C+B; forced 2 CTAs/SM (smem fits: 2x115.8KB < 228KB).
// ============================================================
#define Y_CH   0
#define Y_CL   16384
#define Y_BH   32768
#define Y_BL   49152
#define Y_XH   65536
#define Y_XL   81920
#define Y_SH   98304
#define Y_SL   106496
#define Y_GH   0            // overlays C (hi+lo)
#define Y_GL   32768        // overlays B (hi+lo)
#define Y_ACS  114688
#define Y_DT   (114688 + 512)
#define Y_SMEM (114688 + 1024 + 64)

__global__ __launch_bounds__(256, 2) void y_mma() {
    extern __shared__ __align__(16) char dsm[];
    const uint32_t sb = smem_u32(dsm);
    float* sAcs = reinterpret_cast<float*>(dsm + Y_ACS);
    float* sDt  = reinterpret_cast<float*>(dsm + Y_DT);

    const int h = blockIdx.x, c = blockIdx.y, b = blockIdx.z;
    const int tid = threadIdx.x;
    const int kvh = h >> 2;

    // async tile loads: C, B, X hi/lo straight from bf16 arrays
    {
        const size_t rowbase = ((size_t)b * LL + c * CHUNK) * CONV;
        const uint32_t offC = 2 * KVH * PP + h * PP;
        const uint32_t offB = KVH * PP + kvh * PP;
        const uint32_t offX = kvh * PP;
        for (int i = tid; i < 1024; i += 256) {
            const int r = i >> 3, g = i & 7;
            const uint32_t d = swz128(r, g);
            const size_t s = rowbase + (size_t)r * CONV + g * 8;
            cpa16(sb + Y_CH + d, g_vkhi + s + offC, 16);
            cpa16(sb + Y_CL + d, g_vklo + s + offC, 16);
            cpa16(sb + Y_BH + d, g_vkhi + s + offB, 16);
            cpa16(sb + Y_BL + d, g_vklo + s + offB, 16);
            cpa16(sb + Y_XH + d, g_vkhi + s + offX, 16);
            cpa16(sb + Y_XL + d, g_vklo + s + offX, 16);
        }
        cpa_commit();
    }

    if (tid < CHUNK) {
        sAcs[tid] = g_acs[(((size_t)b * HH + h) * NC + c) * CHUNK + tid];
        sDt[tid]  = g_dt[((size_t)b * LL + c * CHUNK + tid) * HH + h];
    }
    if (tid < 128) {
        const int r = tid >> 1;
        const int c0 = (tid & 1) * 32;
        const size_t st = (((size_t)b * NC + c) * HH + h) * (PP * PP) + (size_t)r * PP;
        split_row32(sb + Y_SH, sb + Y_SL, g_states + st + c0, r, c0, 1.f);
    }
    cpa_wait<0>();
    __syncthreads();

    const int warp = tid >> 5, lane = tid & 31;
    const int wm = (warp >> 2) * 64;
    const int wn32 = (warp & 3) * 32;
    const int wn16 = (warp & 3) * 16;
    const int gid = lane >> 2, tig = lane & 3;

    const int a_r = lane & 15, a_g = lane >> 4;
    const int b_r = (lane & 7) + ((lane & 16) >> 1), b_g = (lane >> 3) & 1;
    const int tB_kr = (lane & 7) + ((lane >> 3) & 1) * 8;
    const int tB_ng = (lane >> 4) & 1;

    // -------- pass 1b FIRST: Yo = C . S^T --------
    float accY[4][2][4];
#pragma unroll
    for (int i = 0; i < 4; i++)
#pragma unroll
        for (int j = 0; j < 2; j++)
#pragma unroll
            for (int k = 0; k < 4; k++) accY[i][j][k] = 0.f;

#pragma unroll
    for (int ks = 0; ks < 4; ks++) {
        uint32_t ah[4][4], al[4][4], bh[4], bl[4];
        const int ag = 2 * ks + a_g;
        const int krb = ks * 16 + tB_kr;
#pragma unroll
        for (int mt = 0; mt < 4; mt++)
            ldsm_x4(ah[mt], sb + Y_CH + swz128(wm + mt * 16 + a_r, ag));
        ldsm_x4_t(bh, sb + Y_SH + swz128(krb, (wn16 >> 3) + tB_ng));
#pragma unroll
        for (int mt = 0; mt < 4; mt++)
#pragma unroll
            for (int nt = 0; nt < 2; nt++)
                mma16816(accY[mt][nt], ah[mt], bh[nt * 2], bh[nt * 2 + 1]);
#pragma unroll
        for (int mt = 0; mt < 4; mt++)
            ldsm_x4(al[mt], sb + Y_CL + swz128(wm + mt * 16 + a_r, ag));
#pragma unroll
        for (int mt = 0; mt < 4; mt++)
#pragma unroll
            for (int nt = 0; nt < 2; nt++)
                mma16816(accY[mt][nt], al[mt], bh[nt * 2], bh[nt * 2 + 1]);
        ldsm_x4_t(bl, sb + Y_SL + swz128(krb, (wn16 >> 3) + tB_ng));
#pragma unroll
        for (int mt = 0; mt < 4; mt++)
#pragma unroll
            for (int nt = 0; nt < 2; nt++)
                mma16816(accY[mt][nt], ah[mt], bl[nt * 2], bl[nt * 2 + 1]);
    }

#pragma unroll
    for (int mt = 0; mt < 4; mt++) {
        const float e0 = expf(sAcs[wm + mt * 16 + gid]);
        const float e1 = expf(sAcs[wm + mt * 16 + gid + 8]);
#pragma unroll
        for (int nt = 0; nt < 2; nt++) {
            accY[mt][nt][0] *= e0; accY[mt][nt][1] *= e0;
            accY[mt][nt][2] *= e1; accY[mt][nt][3] *= e1;
        }
    }

    // -------- pass 1a: G = C . Bt^T --------
    {
        float accG[4][4][4];
#pragma unroll
        for (int i = 0; i < 4; i++)
#pragma unroll
            for (int j = 0; j < 4; j++)
#pragma unroll
                for (int k = 0; k < 4; k++) accG[i][j][k] = 0.f;

#pragma unroll
        for (int ks = 0; ks < 4; ks++) {
            uint32_t ah[4][4], al[4][4], bh[2][4], bl[2][4];
            const int ag = 2 * ks + a_g, bg = 2 * ks + b_g;
#pragma unroll
            for (int mt = 0; mt < 4; mt++)
                ldsm_x4(ah[mt], sb + Y_CH + swz128(wm + mt * 16 + a_r, ag));
#pragma unroll
            for (int p = 0; p < 2; p++)
                ldsm_x4(bh[p], sb + Y_BH + swz128(wn32 + p * 16 + b_r, bg));
#pragma unroll
            for (int mt = 0; mt < 4; mt++)
#pragma unroll
                for (int nt = 0; nt < 4; nt++)
                    mma16816(accG[mt][nt], ah[mt], bh[nt >> 1][(nt & 1) * 2], bh[nt >> 1][(nt & 1) * 2 + 1]);
#pragma unroll
            for (int mt = 0; mt < 4; mt++)
                ldsm_x4(al[mt], sb + Y_CL + swz128(wm + mt * 16 + a_r, ag));
#pragma unroll
            for (int mt = 0; mt < 4; mt++)
#pragma unroll
                for (int nt = 0; nt < 4; nt++)
                    mma16816(accG[mt][nt], al[mt], bh[nt >> 1][(nt & 1) * 2], bh[nt >> 1][(nt & 1) * 2 + 1]);
#pragma unroll
            for (int p = 0; p < 2; p++)
                ldsm_x4(bl[p], sb + Y_BL + swz128(wn32 + p * 16 + b_r, bg));
#pragma unroll
            for (int mt = 0; mt < 4; mt++)
#pragma unroll
                for (int nt = 0; nt < 4; nt++)
                    mma16816(accG[mt][nt], ah[mt], bl[nt >> 1][(nt & 1) * 2], bl[nt >> 1][(nt & 1) * 2 + 1]);
        }

        __syncthreads();   // all warps done reading C/B before overlay

#pragma unroll
        for (int mt = 0; mt < 4; mt++) {
            const int l0 = wm + mt * 16 + gid;
            const int l1 = l0 + 8;
            const float A0 = sAcs[l0], A1 = sAcs[l1];
#pragma unroll
            for (int nt = 0; nt < 4; nt++) {
                const int s0 = wn32 + nt * 8 + tig * 2;
                const int s1 = s0 + 1;
                const float As0 = sAcs[s0], As1 = sAcs[s1];
                const float d0 = sDt[s0], d1 = sDt[s1];
                float g00 = (s0 <= l0) ? accG[mt][nt][0] * expf(A0 - As0) * d0 : 0.f;
                float g01 = (s1 <= l0) ? accG[mt][nt][1] * expf(A0 - As1) * d1 : 0.f;
                float g10 = (s0 <= l1) ? accG[mt][nt][2] * expf(A1 - As0) * d0 : 0.f;
                float g11 = (s1 <= l1) ? accG[mt][nt][3] * expf(A1 - As1) * d1 : 0.f;
                uint32_t hp, lp;
                const uint32_t a0 = swz256(l0, s0 >> 3) + ((s0 & 7) << 1);
                split_pair(g00, g01, hp, lp);
                asm volatile("st.shared.b32 [%0], %1;" :: "r"(sb + Y_GH + a0), "r"(hp));
                asm volatile("st.shared.b32 [%0], %1;" :: "r"(sb + Y_GL + a0), "r"(lp));
                const uint32_t a1 = swz256(l1, s0 >> 3) + ((s0 & 7) << 1);
                split_pair(g10, g11, hp, lp);
                asm volatile("st.shared.b32 [%0], %1;" :: "r"(sb + Y_GH + a1), "r"(hp));
                asm volatile("st.shared.b32 [%0], %1;" :: "r"(sb + Y_GL + a1), "r"(lp));
            }
        }
    }

    __syncthreads();

    // -------- pass 2: Y += G' . X^T  (X = raw v) --------
#pragma unroll
    for (int ks = 0; ks < 8; ks++) {
        uint32_t ah[4][4], al[4][4], bh[4], bl[4];
        const int ag = 2 * ks + a_g;
        const int krb = ks * 16 + tB_kr;
#pragma unroll
        for (int mt = 0; mt < 4; mt++)
            ldsm_x4(ah[mt], sb + Y_GH + swz256(wm + mt * 16 + a_r, ag));
        ldsm_x4_t(bh, sb + Y_XH + swz128(krb, (wn16 >> 3) + tB_ng));
#pragma unroll
        for (int mt = 0; mt < 4; mt++)
#pragma unroll
            for (int nt = 0; nt < 2; nt++)
                mma16816(accY[mt][nt], ah[mt], bh[nt * 2], bh[nt * 2 + 1]);
#pragma unroll
        for (int mt = 0; mt < 4; mt++)
            ldsm_x4(al[mt], sb + Y_GL + swz256(wm + mt * 16 + a_r, ag));
#pragma unroll
        for (int mt = 0; mt < 4; mt++)
#pragma unroll
            for (int nt = 0; nt < 2; nt++)
                mma16816(accY[mt][nt], al[mt], bh[nt * 2], bh[nt * 2 + 1]);
        ldsm_x4_t(bl, sb + Y_XL + swz128(krb, (wn16 >> 3) + tB_ng));
#pragma unroll
        for (int mt = 0; mt < 4; mt++)
#pragma unroll
            for (int nt = 0; nt < 2; nt++)
                mma16816(accY[mt][nt], ah[mt], bl[nt * 2], bl[nt * 2 + 1]);
    }

#pragma unroll
    for (int mt = 0; mt < 4; mt++) {
        const int l0 = wm + mt * 16 + gid;
#pragma unroll
        for (int nt = 0; nt < 2; nt++) {
            const int p = wn16 + nt * 8 + tig * 2;
            const size_t y0 = ((size_t)b * LL + c * CHUNK + l0) * DD + h * PP + p;
            const size_t y1 = ((size_t)b * LL + c * CHUNK + l0 + 8) * DD + h * PP + p;
            *reinterpret_cast<float2*>(&g_y[y0]) = make_float2(accY[mt][nt][0], accY[mt][nt][1]);
            *reinterpret_cast<float2*>(&g_y[y1]) = make_float2(accY[mt][nt][2], accY[mt][nt][3]);
        }
    }
}

// ============================================================
// Pass D: RMSNorm + swish gate -> bf16 hi/lo; warp-per-row
// ============================================================
__global__ __launch_bounds__(256) void normgate_kernel(const float* __restrict__ gnorm_w) {
    const int r = blockIdx.x * 8 + (threadIdx.x >> 5);   // row = (b*L + l)*H + h
    const int lane = threadIdx.x & 31;
    const int h = r % HH;
    const size_t bl = (size_t)r / HH;
    const size_t yb = bl * DD + (size_t)h * PP;
    const float y0 = g_y[yb + lane];
    const float y1 = g_y[yb + lane + 32];
    float s = y0 * y0 + y1 * y1;
#pragma unroll
    for (int o = 16; o > 0; o >>= 1) s += __shfl_xor_sync(0xffffffffu, s, o);
    const float rms = rsqrtf(s / (float)PP + EPS);
    const size_t gb = bl * PROJ + CONV + (size_t)h * PP;
#pragma unroll
    for (int q = 0; q < 2; q++) {
        const int p = lane + q * 32;
        const float yv = (q == 0) ? y0 : y1;
        const float gv = g_proj[gb + p];
        const float out = yv * rms * gnorm_w[p] * (gv * sigmoidf_(gv));
        __nv_bfloat16 hi = __float2bfloat16(out);
        g_yhi[yb + p] = hi;
        g_ylo[yb + p] = __float2bfloat16(out - __bfloat162float(hi));
    }
}

// ============================================================
// launch
// ============================================================
extern "C" void kernel_launch(void* const* d_in, const int* in_sizes, int n_in,
                              void* d_out, int out_size) {
    const float* hidden   = (const float*)d_in[0];
    const float* W_vkqgdt = (const float*)d_in[1];
    const float* conv_w   = (const float*)d_in[2];
    const float* conv_b   = (const float*)d_in[3];
    const float* dt_bias  = (const float*)d_in[4];
    const float* A_logb   = (const float*)d_in[5];
    const float* gnorm_w  = (const float*)d_in[6];
    const float* W_o      = (const float*)d_in[7];
    float* out = (float*)d_out;

    float* proj_ptr;
    cudaGetSymbolAddress((void**)&proj_ptr, g_proj);
    __nv_bfloat16 *hhi, *hlo, *whi, *wlo, *ohi, *olo, *yhi, *ylo;
    cudaGetSymbolAddress((void**)&hhi, g_hhi);
    cudaGetSymbolAddress((void**)&hlo, g_hlo);
    cudaGetSymbolAddress((void**)&whi, g_whi);
    cudaGetSymbolAddress((void**)&wlo, g_wlo);
    cudaGetSymbolAddress((void**)&ohi, g_ohi);
    cudaGetSymbolAddress((void**)&olo, g_olo);
    cudaGetSymbolAddress((void**)&yhi, g_yhi);
    cudaGetSymbolAddress((void**)&ylo, g_ylo);

    cudaFuncSetAttribute(gemm_mma, cudaFuncAttributeMaxDynamicSharedMemorySize, GEMM_SMEM);
    cudaFuncSetAttribute(chunk_state_mma, cudaFuncAttributeMaxDynamicSharedMemorySize, CS_SMEM);
    cudaFuncSetAttribute(y_mma, cudaFuncAttributeMaxDynamicSharedMemorySize, Y_SMEM);

    // 0) split inputs
    {
        const int n4a = (BB * LL * DD) / 4;
        split_kernel<<<(n4a + 255) / 256, 256>>>(hidden, hhi, hlo, n4a);
        const int n4w = (PROJ * DD) / 4;
        split_kernel<<<(n4w + 255) / 256, 256>>>(W_vkqgdt, whi, wlo, n4w);
        const int n4o = (DD * DD) / 4;
        split_kernel<<<(n4o + 255) / 256, 256>>>(W_o, ohi, olo, n4o);
    }

    // 1) in-projection
    gemm_mma<<<dim3((PROJ + 127) / 128, (BB * LL) / 128), 256, GEMM_SMEM>>>(
        proj_ptr, hhi, hlo, whi, wlo, PROJ, DD);

    // 2) conv + silu (emits bf16 hi/lo), dt
    {
        const size_t tot = (size_t)BB * LL * CONV;
        conv_silu_kernel<<<(unsigned)((tot + 255) / 256), 256>>>(conv_w, conv_b);
        dt_kernel<<<(BB * LL * HH + 255) / 256, 256>>>(dt_bias, A_logb);
    }

    // 3) SSD (tensor-core)
    chunk_state_mma<<<dim3(HH, NC, BB), 128, CS_SMEM>>>();
    state_scan_kernel<<<BB * HH * 8, 256>>>();
    y_mma<<<dim3(HH, NC, BB), 256, Y_SMEM>>>();

    // 4) norm + gate (warp-per-row, emits bf16 hi/lo)
    normgate_kernel<<<BB * LL * HH / 8, 256>>>(gnorm_w);

    // 5) out-projection
    gemm_mma<<<dim3(DD / 128, (BB * LL) / 128), 256, GEMM_SMEM>>>(
        out, yhi, ylo, ohi, olo, DD, DD);
}

// round 13
// speedup vs baseline: 1.0289x; 1.0289x over previous
#include <cuda_runtime.h>
#include <cuda_bf16.h>
#include <math.h>
#include <stdint.h>

// ---------------- problem constants ----------------
#define BB      2
#define LL      2048
#define HH      32
#define KVH     8
#define PP      64
#define DD      2048           // HH*PP
#define CONV    3072           // (HH+2*KVH)*PP
#define PROJ    5152           // CONV + DD + HH
#define CHUNK   128
#define NC      16             // LL/CHUNK
#define EPS     1e-5f

// ---------------- scratch (device globals; no allocation allowed) ----------------
__device__ __align__(16) float g_proj[(size_t)BB * LL * PROJ];
__device__ __align__(16) float g_dt  [(size_t)BB * LL * HH];
__device__ __align__(16) float g_adt [(size_t)BB * LL * HH];
__device__ __align__(16) float g_acs [(size_t)BB * HH * NC * CHUNK];
__device__ __align__(16) float g_tot [(size_t)BB * HH * NC];
__device__ __align__(16) float g_states[(size_t)BB * NC * HH * PP * PP];
__device__ __align__(16) float g_y   [(size_t)BB * LL * DD];

// chunk-start states pre-split to bf16 hi/lo by the scan
__device__ __align__(16) __nv_bfloat16 g_shi[(size_t)BB * NC * HH * PP * PP];
__device__ __align__(16) __nv_bfloat16 g_slo[(size_t)BB * NC * HH * PP * PP];

// post-conv vkq stored directly as bf16 hi/lo
__device__ __align__(16) __nv_bfloat16 g_vkhi[(size_t)BB * LL * CONV], g_vklo[(size_t)BB * LL * CONV];

// split-precision bf16 operands for tensor-core GEMMs
__device__ __align__(16) __nv_bfloat16 g_hhi[(size_t)BB * LL * DD], g_hlo[(size_t)BB * LL * DD];
__device__ __align__(16) __nv_bfloat16 g_whi[(size_t)PROJ * DD],    g_wlo[(size_t)PROJ * DD];
__device__ __align__(16) __nv_bfloat16 g_ohi[(size_t)DD * DD],      g_olo[(size_t)DD * DD];
__device__ __align__(16) __nv_bfloat16 g_yhi[(size_t)BB * LL * DD], g_ylo[(size_t)BB * LL * DD];

// ---------------- helpers ----------------
__device__ __forceinline__ float sigmoidf_(float x) { return 1.f / (1.f + expf(-x)); }
__device__ __forceinline__ float softplusf_(float x) { return (x > 20.f) ? x : log1pf(expf(x)); }

__device__ __forceinline__ uint32_t smem_u32(const void* p) {
    uint32_t a;
    asm("{ .reg .u64 t; cvta.to.shared.u64 t, %1; cvt.u32.u64 %0, t; }" : "=r"(a) : "l"(p));
    return a;
}
__device__ __forceinline__ void cpa16(uint32_t dst, const void* src, int srcsize) {
    asm volatile("cp.async.cg.shared.global [%0], [%1], 16, %2;"
                 :: "r"(dst), "l"(src), "r"(srcsize));
}
__device__ __forceinline__ void cpa_commit() { asm volatile("cp.async.commit_group;"); }
template <int N> __device__ __forceinline__ void cpa_wait() {
    asm volatile("cp.async.wait_group %0;" :: "n"(N));
}
__device__ __forceinline__ void ldsm_x4(uint32_t* r, uint32_t a) {
    asm volatile("ldmatrix.sync.aligned.m8n8.x4.shared.b16 {%0,%1,%2,%3}, [%4];"
                 : "=r"(r[0]), "=r"(r[1]), "=r"(r[2]), "=r"(r[3]) : "r"(a));
}
__device__ __forceinline__ void ldsm_x4_t(uint32_t* r, uint32_t a) {
    asm volatile("ldmatrix.sync.aligned.m8n8.x4.trans.shared.b16 {%0,%1,%2,%3}, [%4];"
                 : "=r"(r[0]), "=r"(r[1]), "=r"(r[2]), "=r"(r[3]) : "r"(a));
}
__device__ __forceinline__ void mma16816(float* c, const uint32_t* a, uint32_t b0, uint32_t b1) {
    asm volatile("mma.sync.aligned.m16n8k16.row.col.f32.bf16.bf16.f32 "
                 "{%0,%1,%2,%3}, {%4,%5,%6,%7}, {%8,%9}, {%0,%1,%2,%3};"
                 : "+f"(c[0]), "+f"(c[1]), "+f"(c[2]), "+f"(c[3])
                 : "r"(a[0]), "r"(a[1]), "r"(a[2]), "r"(a[3]), "r"(b0), "r"(b1));
}
__device__ __forceinline__ void split_pair(float f0, float f1, uint32_t& hp, uint32_t& lp) {
    __nv_bfloat16 h0 = __float2bfloat16(f0);
    __nv_bfloat16 h1 = __float2bfloat16(f1);
    __nv_bfloat16 l0 = __float2bfloat16(f0 - __bfloat162float(h0));
    __nv_bfloat16 l1 = __float2bfloat16(f1 - __bfloat162float(h1));
    hp = (uint32_t)__bfloat16_as_ushort(h0) | ((uint32_t)__bfloat16_as_ushort(h1) << 16);
    lp = (uint32_t)__bfloat16_as_ushort(l0) | ((uint32_t)__bfloat16_as_ushort(l1) << 16);
}
// swizzles: rows of 128B (64 bf16) / 256B (128 bf16); 16B group permute
__device__ __forceinline__ uint32_t swz128(int r, int g) { return (uint32_t)(r * 128 + ((g ^ (r & 7)) << 4)); }
__device__ __forceinline__ uint32_t swz256(int r, int g) { return (uint32_t)(r * 256 + ((g ^ (r & 7)) << 4)); }

// same but reconstructing fp32 = hi + lo from bf16 pair source (row-offset pointers)
__device__ __forceinline__ void split_row32_rec(uint32_t dH, uint32_t dL,
                                                const __nv_bfloat16* __restrict__ hsrc,
                                                const __nv_bfloat16* __restrict__ lsrc,
                                                int r, int c0, float scale) {
#pragma unroll
    for (int c = 0; c < 32; c += 8) {
        uint4 hv = *reinterpret_cast<const uint4*>(hsrc + c);
        uint4 lv = *reinterpret_cast<const uint4*>(lsrc + c);
        const uint32_t hw[4] = {hv.x, hv.y, hv.z, hv.w};
        const uint32_t lw[4] = {lv.x, lv.y, lv.z, lv.w};
        uint32_t hp[4], lp[4];
#pragma unroll
        for (int j = 0; j < 4; j++) {
            float f0 = __bfloat162float(__ushort_as_bfloat16((unsigned short)(hw[j] & 0xFFFF)))
                     + __bfloat162float(__ushort_as_bfloat16((unsigned short)(lw[j] & 0xFFFF)));
            float f1 = __bfloat162float(__ushort_as_bfloat16((unsigned short)(hw[j] >> 16)))
                     + __bfloat162float(__ushort_as_bfloat16((unsigned short)(lw[j] >> 16)));
            split_pair(f0 * scale, f1 * scale, hp[j], lp[j]);
        }
        const int col = c0 + c;     // multiple of 8
        const uint32_t a = swz128(r, col >> 3);
        asm volatile("st.shared.v4.b32 [%0], {%1,%2,%3,%4};"
                     :: "r"(dH + a), "r"(hp[0]), "r"(hp[1]), "r"(hp[2]), "r"(hp[3]));
        asm volatile("st.shared.v4.b32 [%0], {%1,%2,%3,%4};"
                     :: "r"(dL + a), "r"(lp[0]), "r"(lp[1]), "r"(lp[2]), "r"(lp[3]));
    }
}

// ============================================================
// fp32 -> (bf16 hi, bf16 lo) split, vectorized x4
// ============================================================
__global__ void split_kernel(const float* __restrict__ src,
                             __nv_bfloat16* __restrict__ hi,
                             __nv_bfloat16* __restrict__ lo, int n4) {
    const int i = blockIdx.x * blockDim.x + threadIdx.x;
    if (i >= n4) return;
    const float4 v = reinterpret_cast<const float4*>(src)[i];
    uint32_t h0, l0, h1, l1;
    split_pair(v.x, v.y, h0, l0);
    split_pair(v.z, v.w, h1, l1);
    reinterpret_cast<uint2*>(hi)[i] = make_uint2(h0, h1);
    reinterpret_cast<uint2*>(lo)[i] = make_uint2(l0, l1);
}

// ============================================================
// mma.sync bf16 split-precision GEMM (R7 passing config, frozen)
// ============================================================
#define TILE_BYTES 8192
#define STAGE_BYTES (4 * TILE_BYTES)
#define NSTAGE 3
#define GEMM_SMEM (NSTAGE * STAGE_BYTES)

__device__ __forceinline__ uint32_t sw_off(int r, int g) {
    return (uint32_t)(r * 64 + ((g ^ ((r >> 1) & 3)) << 4));
}

__device__ __forceinline__ void load_stage(
    uint32_t sb, const __nv_bfloat16* __restrict__ Ahi, const __nv_bfloat16* __restrict__ Alo,
    const __nv_bfloat16* __restrict__ Bhi, const __nv_bfloat16* __restrict__ Blo,
    int mBase, int nBase, int Nd, int Kd, int kBase, int tid) {
#pragma unroll
    for (int t = 0; t < 2; t++) {
        const int idx = tid + (t << 8);
        const int r = idx >> 2;
        const int g = idx & 3;
        const uint32_t off = sw_off(r, g);
        const size_t srcA = (size_t)(mBase + r) * Kd + kBase + g * 8;
        cpa16(sb + off, Ahi + srcA, 16);
        cpa16(sb + TILE_BYTES + off, Alo + srcA, 16);
        const int brow = nBase + r;
        const int ok = (brow < Nd) ? 16 : 0;
        const size_t srcB = (size_t)(ok ? brow : (Nd - 1)) * Kd + kBase + g * 8;
        cpa16(sb + 2 * TILE_BYTES + off, Bhi + srcB, ok);
        cpa16(sb + 3 * TILE_BYTES + off, Blo + srcB, ok);
    }
}

__global__ __launch_bounds__(256, 2) void gemm_mma(
    float* __restrict__ C,
    const __nv_bfloat16* __restrict__ Ahi, const __nv_bfloat16* __restrict__ Alo,
    const __nv_bfloat16* __restrict__ Bhi, const __nv_bfloat16* __restrict__ Blo,
    int Nd, int Kd) {
    extern __shared__ __align__(16) char dsm[];
    const int tid  = threadIdx.x;
    const int warp = tid >> 5;
    const int lane = tid & 31;
    const int mBase = blockIdx.y << 7;
    const int nBase = blockIdx.x << 7;
    const int wm = (warp >> 2) << 6;
    const int wn = (warp & 3) << 5;

    const uint32_t smem0 = smem_u32(dsm);

    float acc[4][4][4];
#pragma unroll
    for (int i = 0; i < 4; i++)
#pragma unroll
        for (int j = 0; j < 4; j++)
#pragma unroll
            for (int k = 0; k < 4; k++) acc[i][j][k] = 0.f;

    const int a_r = lane & 15;
    const int a_gsel = lane >> 4;
    const int b_r = (lane & 7) + ((lane & 16) >> 1);
    const int b_gsel = (lane >> 3) & 1;

    const int nk = Kd >> 5;
    load_stage(smem0, Ahi, Alo, Bhi, Blo, mBase, nBase, Nd, Kd, 0, tid);
    cpa_commit();
    load_stage(smem0 + STAGE_BYTES, Ahi, Alo, Bhi, Blo, mBase, nBase, Nd, Kd, 32, tid);
    cpa_commit();

    int bufc = 0;
    for (int s = 0; s < nk; s++) {
        if (s == nk - 1) cpa_wait<0>(); else cpa_wait<1>();
        __syncthreads();
        if (s + 2 < nk) {
            int bufn = bufc + 2; if (bufn >= NSTAGE) bufn -= NSTAGE;
            load_stage(smem0 + bufn * STAGE_BYTES, Ahi, Alo, Bhi, Blo,
                       mBase, nBase, Nd, Kd, (s + 2) << 5, tid);
            cpa_commit();
        }

        const uint32_t sb = smem0 + bufc * STAGE_BYTES;
        const uint32_t tAh = sb, tAl = sb + TILE_BYTES;
        const uint32_t tBh = sb + 2 * TILE_BYTES, tBl = sb + 3 * TILE_BYTES;

#pragma unroll
        for (int ks = 0; ks < 2; ks++) {
            uint32_t a[4][4], b[2][4];
            const int ag = 2 * ks + a_gsel;
            const int bg = 2 * ks + b_gsel;
#pragma unroll
            for (int mt = 0; mt < 4; mt++)
                ldsm_x4(a[mt], tAh + sw_off(wm + mt * 16 + a_r, ag));
#pragma unroll
            for (int p = 0; p < 2; p++)
                ldsm_x4(b[p], tBh + sw_off(wn + p * 16 + b_r, bg));
#pragma unroll
            for (int mt = 0; mt < 4; mt++)
#pragma unroll
                for (int nt = 0; nt < 4; nt++)
                    mma16816(acc[mt][nt], a[mt], b[nt >> 1][(nt & 1) * 2], b[nt >> 1][(nt & 1) * 2 + 1]);
#pragma unroll
            for (int p = 0; p < 2; p++)
                ldsm_x4(b[p], tBl + sw_off(wn + p * 16 + b_r, bg));
#pragma unroll
            for (int mt = 0; mt < 4; mt++)
#pragma unroll
                for (int nt = 0; nt < 4; nt++)
                    mma16816(acc[mt][nt], a[mt], b[nt >> 1][(nt & 1) * 2], b[nt >> 1][(nt & 1) * 2 + 1]);
#pragma unroll
            for (int mt = 0; mt < 4; mt++)
                ldsm_x4(a[mt], tAl + sw_off(wm + mt * 16 + a_r, ag));
#pragma unroll
            for (int p = 0; p < 2; p++)
                ldsm_x4(b[p], tBh + sw_off(wn + p * 16 + b_r, bg));
#pragma unroll
            for (int mt = 0; mt < 4; mt++)
#pragma unroll
                for (int nt = 0; nt < 4; nt++)
                    mma16816(acc[mt][nt], a[mt], b[nt >> 1][(nt & 1) * 2], b[nt >> 1][(nt & 1) * 2 + 1]);
        }
        if (++bufc == NSTAGE) bufc = 0;
    }

    const int gid = lane >> 2, tig = lane & 3;
#pragma unroll
    for (int mt = 0; mt < 4; mt++) {
        const int row0 = mBase + wm + mt * 16 + gid;
#pragma unroll
        for (int nt = 0; nt < 4; nt++) {
            const int col = nBase + wn + nt * 8 + tig * 2;
            if (col < Nd) {
                float2 v01 = make_float2(acc[mt][nt][0], acc[mt][nt][1]);
                float2 v23 = make_float2(acc[mt][nt][2], acc[mt][nt][3]);
                *reinterpret_cast<float2*>(C + (size_t)row0 * Nd + col) = v01;
                *reinterpret_cast<float2*>(C + (size_t)(row0 + 8) * Nd + col) = v23;
            }
        }
    }
}

// ============================================================
// Conv (kernel=2, causal) + SiLU -> bf16 hi/lo directly
// ============================================================
__global__ void conv_silu_kernel(const float* __restrict__ conv_w,
                                 const float* __restrict__ conv_b) {
    const size_t idx = (size_t)blockIdx.x * blockDim.x + threadIdx.x;
    if (idx >= (size_t)BB * LL * CONV) return;
    const int c = (int)(idx % CONV);
    const size_t bl = idx / CONV;
    const int l = (int)(bl % LL);
    const float cur = g_proj[bl * PROJ + c];
    const float prev = (l > 0) ? g_proj[(bl - 1) * PROJ + c] : 0.f;
    const float v = prev * conv_w[c * 2] + cur * conv_w[c * 2 + 1] + conv_b[c];
    const float o = v * sigmoidf_(v);
    __nv_bfloat16 hi = __float2bfloat16(o);
    g_vkhi[idx] = hi;
    g_vklo[idx] = __float2bfloat16(o - __bfloat162float(hi));
}

__global__ void dt_kernel(const float* __restrict__ dt_bias,
                          const float* __restrict__ A_log_bias) {
    const int idx = blockIdx.x * blockDim.x + threadIdx.x;
    if (idx >= BB * LL * HH) return;
    const int h = idx % HH;
    const size_t bl = idx / HH;
    const float raw = g_proj[bl * PROJ + (CONV + DD) + h];
    const float dtv = softplusf_(raw + dt_bias[h]);
    g_dt[idx] = dtv;
    g_adt[idx] = dtv * (-expf(A_log_bias[h]));
}

// ============================================================
// Pass A (mma): per-(b,c,h) parallel cumsum + local chunk state
// ============================================================
#define CS_KH   0
#define CS_KL   16384
#define CS_XH   32768
#define CS_XL   49152
#define CS_ACS  65536
#define CS_SMEM (65536 + 512)

__global__ __launch_bounds__(128) void chunk_state_mma() {
    extern __shared__ __align__(16) char dsm[];
    const uint32_t sb = smem_u32(dsm);
    float* sAcs = reinterpret_cast<float*>(dsm + CS_ACS);

    const int h = blockIdx.x, c = blockIdx.y, b = blockIdx.z;
    const int tid = threadIdx.x;
    const int kvh = h >> 2;

    sAcs[tid] = g_adt[((size_t)b * LL + c * CHUNK + tid) * HH + h];
    __syncthreads();
    // Hillis-Steele inclusive scan over 128 elements
#pragma unroll
    for (int off = 1; off < CHUNK; off <<= 1) {
        const float v = sAcs[tid];
        const float u = (tid >= off) ? sAcs[tid - off] : 0.f;
        __syncthreads();
        sAcs[tid] = v + u;
        __syncthreads();
    }
    const float total = sAcs[CHUNK - 1];
    g_acs[(((size_t)b * HH + h) * NC + c) * CHUNK + tid] = sAcs[tid];
    if (tid == 0)
        g_tot[((size_t)b * HH + h) * NC + c] = total;

    {
        const int l = tid;
        const size_t base = ((size_t)b * LL + c * CHUNK + l) * CONV;
        const float w = expf(total - sAcs[l]);
        const float dtv = g_dt[((size_t)b * LL + c * CHUNK + l) * HH + h];
        const size_t ko = base + KVH * PP + kvh * PP;
        const size_t vo = base + kvh * PP;
        const float ws = w * dtv;
        split_row32_rec(sb + CS_KH, sb + CS_KL, g_vkhi + ko,      g_vklo + ko,      l, 0,  ws);
        split_row32_rec(sb + CS_KH, sb + CS_KL, g_vkhi + ko + 32, g_vklo + ko + 32, l, 32, ws);
        split_row32_rec(sb + CS_XH, sb + CS_XL, g_vkhi + vo,      g_vklo + vo,      l, 0,  1.f);
        split_row32_rec(sb + CS_XH, sb + CS_XL, g_vkhi + vo + 32, g_vklo + vo + 32, l, 32, 1.f);
    }
    __syncthreads();

    const int warp = tid >> 5, lane = tid & 31;
    const int wn = warp * 16;
    const int tA_kr = (lane & 7) + ((lane >> 4) & 1) * 8;
    const int tA_mg = (lane >> 3) & 1;
    const int tB_kr = (lane & 7) + ((lane >> 3) & 1) * 8;
    const int tB_ng = (lane >> 4) & 1;

    float acc[4][2][4];
#pragma unroll
    for (int i = 0; i < 4; i++)
#pragma unroll
        for (int j = 0; j < 2; j++)
#pragma unroll
            for (int k = 0; k < 4; k++) acc[i][j][k] = 0.f;

#pragma unroll
    for (int ks = 0; ks < 8; ks++) {
        const int kra = ks * 16 + tA_kr;
        const int krb = ks * 16 + tB_kr;
        uint32_t ah[4][4], al[4][4], bh[4], bl[4];
#pragma unroll
        for (int mt = 0; mt < 4; mt++)
            ldsm_x4_t(ah[mt], sb + CS_KH + swz128(kra, mt * 2 + tA_mg));
        ldsm_x4_t(bh, sb + CS_XH + swz128(krb, (wn >> 3) + tB_ng));
#pragma unroll
        for (int mt = 0; mt < 4; mt++)
#pragma unroll
            for (int nt = 0; nt < 2; nt++)
                mma16816(acc[mt][nt], ah[mt], bh[nt * 2], bh[nt * 2 + 1]);
#pragma unroll
        for (int mt = 0; mt < 4; mt++)
            ldsm_x4_t(al[mt], sb + CS_KL + swz128(kra, mt * 2 + tA_mg));
#pragma unroll
        for (int mt = 0; mt < 4; mt++)
#pragma unroll
            for (int nt = 0; nt < 2; nt++)
                mma16816(acc[mt][nt], al[mt], bh[nt * 2], bh[nt * 2 + 1]);
        ldsm_x4_t(bl, sb + CS_XL + swz128(krb, (wn >> 3) + tB_ng));
#pragma unroll
        for (int mt = 0; mt < 4; mt++)
#pragma unroll
            for (int nt = 0; nt < 2; nt++)
                mma16816(acc[mt][nt], ah[mt], bl[nt * 2], bl[nt * 2 + 1]);
    }

    const int gid = lane >> 2, tig = lane & 3;
    const size_t so = (((size_t)b * NC + c) * HH + h) * (PP * PP);
#pragma unroll
    for (int mt = 0; mt < 4; mt++) {
        const int n0 = mt * 16 + gid;
#pragma unroll
        for (int nt = 0; nt < 2; nt++) {
            const int p = wn + nt * 8 + tig * 2;
            *reinterpret_cast<float2*>(&g_states[so + (size_t)n0 * PP + p]) =
                make_float2(acc[mt][nt][0], acc[mt][nt][1]);
            *reinterpret_cast<float2*>(&g_states[so + (size_t)(n0 + 8) * PP + p]) =
                make_float2(acc[mt][nt][2], acc[mt][nt][3]);
        }
    }
}

// ============================================================
// Pass B: inter-chunk scan; emits chunk-start states directly as
// bf16 hi/lo (same split y_mma used to do in-kernel).
// ============================================================
__global__ void state_scan_kernel() {
    __shared__ float et[NC];
    const int bh = blockIdx.x >> 3;
    const int slab = blockIdx.x & 7;
    const int b = bh / HH, h = bh % HH;
    if (threadIdx.x < NC)
        et[threadIdx.x] = expf(g_tot[(size_t)bh * NC + threadIdx.x]);
    __syncthreads();
    const int e0 = slab * 512;
    for (int e = e0 + threadIdx.x; e < e0 + 512; e += blockDim.x) {
        float S = 0.f;
        for (int c = 0; c < NC; c++) {
            const size_t idx = (((size_t)b * NC + c) * HH + h) * (PP * PP) + e;
            const float loc = g_states[idx];
            const __nv_bfloat16 hi = __float2bfloat16(S);
            g_shi[idx] = hi;
            g_slo[idx] = __float2bfloat16(S - __bfloat162float(hi));
            S = et[c] * S + loc;
        }
    }
}

// ============================================================
// Pass C (mma): Y = (mask(C.B^T)·decay·dt) X + exp(Acs) C.S_start
// All operand tiles (C,B,X,S) via swizzled cp.async; G overlays C+B.
// R11 occupancy config (no launch-bounds cap).
// ============================================================
#define Y_CH   0
#define Y_CL   16384
#define Y_BH   32768
#define Y_BL   49152
#define Y_XH   65536
#define Y_XL   81920
#define Y_SH   98304
#define Y_SL   106496
#define Y_GH   0            // overlays C (hi+lo)
#define Y_GL   32768        // overlays B (hi+lo)
#define Y_ACS  114688
#define Y_DT   (114688 + 512)
#define Y_SMEM (114688 + 1024 + 64)

__global__ __launch_bounds__(256) void y_mma() {
    extern __shared__ __align__(16) char dsm[];
    const uint32_t sb = smem_u32(dsm);
    float* sAcs = reinterpret_cast<float*>(dsm + Y_ACS);
    float* sDt  = reinterpret_cast<float*>(dsm + Y_DT);

    const int h = blockIdx.x, c = blockIdx.y, b = blockIdx.z;
    const int tid = threadIdx.x;
    const int kvh = h >> 2;

    // async tile loads: C, B, X, S hi/lo straight from bf16 arrays
    {
        const size_t rowbase = ((size_t)b * LL + c * CHUNK) * CONV;
        const uint32_t offC = 2 * KVH * PP + h * PP;
        const uint32_t offB = KVH * PP + kvh * PP;
        const uint32_t offX = kvh * PP;
        for (int i = tid; i < 1024; i += 256) {
            const int r = i >> 3, g = i & 7;
            const uint32_t d = swz128(r, g);
            const size_t s = rowbase + (size_t)r * CONV + g * 8;
            cpa16(sb + Y_CH + d, g_vkhi + s + offC, 16);
            cpa16(sb + Y_CL + d, g_vklo + s + offC, 16);
            cpa16(sb + Y_BH + d, g_vkhi + s + offB, 16);
            cpa16(sb + Y_BL + d, g_vklo + s + offB, 16);
            cpa16(sb + Y_XH + d, g_vkhi + s + offX, 16);
            cpa16(sb + Y_XL + d, g_vklo + s + offX, 16);
        }
        const size_t stbase = (((size_t)b * NC + c) * HH + h) * (PP * PP);
        for (int i = tid; i < 512; i += 256) {
            const int r = i >> 3, g = i & 7;       // r = n row 0..63
            const uint32_t d = swz128(r, g);
            const size_t s = stbase + (size_t)r * PP + g * 8;
            cpa16(sb + Y_SH + d, g_shi + s, 16);
            cpa16(sb + Y_SL + d, g_slo + s, 16);
        }
        cpa_commit();
    }

    if (tid < CHUNK) {
        sAcs[tid] = g_acs[(((size_t)b * HH + h) * NC + c) * CHUNK + tid];
        sDt[tid]  = g_dt[((size_t)b * LL + c * CHUNK + tid) * HH + h];
    }
    cpa_wait<0>();
    __syncthreads();

    const int warp = tid >> 5, lane = tid & 31;
    const int wm = (warp >> 2) * 64;
    const int wn32 = (warp & 3) * 32;
    const int wn16 = (warp & 3) * 16;
    const int gid = lane >> 2, tig = lane & 3;

    const int a_r = lane & 15, a_g = lane >> 4;
    const int b_r = (lane & 7) + ((lane & 16) >> 1), b_g = (lane >> 3) & 1;
    const int tB_kr = (lane & 7) + ((lane >> 3) & 1) * 8;
    const int tB_ng = (lane >> 4) & 1;

    // -------- pass 1b FIRST: Yo = C . S^T --------
    float accY[4][2][4];
#pragma unroll
    for (int i = 0; i < 4; i++)
#pragma unroll
        for (int j = 0; j < 2; j++)
#pragma unroll
            for (int k = 0; k < 4; k++) accY[i][j][k] = 0.f;

#pragma unroll
    for (int ks = 0; ks < 4; ks++) {
        uint32_t ah[4][4], al[4][4], bh[4], bl[4];
        const int ag = 2 * ks + a_g;
        const int krb = ks * 16 + tB_kr;
#pragma unroll
        for (int mt = 0; mt < 4; mt++)
            ldsm_x4(ah[mt], sb + Y_CH + swz128(wm + mt * 16 + a_r, ag));
        ldsm_x4_t(bh, sb + Y_SH + swz128(krb, (wn16 >> 3) + tB_ng));
#pragma unroll
        for (int mt = 0; mt < 4; mt++)
#pragma unroll
            for (int nt = 0; nt < 2; nt++)
                mma16816(accY[mt][nt], ah[mt], bh[nt * 2], bh[nt * 2 + 1]);
#pragma unroll
        for (int mt = 0; mt < 4; mt++)
            ldsm_x4(al[mt], sb + Y_CL + swz128(wm + mt * 16 + a_r, ag));
#pragma unroll
        for (int mt = 0; mt < 4; mt++)
#pragma unroll
            for (int nt = 0; nt < 2; nt++)
                mma16816(accY[mt][nt], al[mt], bh[nt * 2], bh[nt * 2 + 1]);
        ldsm_x4_t(bl, sb + Y_SL + swz128(krb, (wn16 >> 3) + tB_ng));
#pragma unroll
        for (int mt = 0; mt < 4; mt++)
#pragma unroll
            for (int nt = 0; nt < 2; nt++)
                mma16816(accY[mt][nt], ah[mt], bl[nt * 2], bl[nt * 2 + 1]);
    }

#pragma unroll
    for (int mt = 0; mt < 4; mt++) {
        const float e0 = expf(sAcs[wm + mt * 16 + gid]);
        const float e1 = expf(sAcs[wm + mt * 16 + gid + 8]);
#pragma unroll
        for (int nt = 0; nt < 2; nt++) {
            accY[mt][nt][0] *= e0; accY[mt][nt][1] *= e0;
            accY[mt][nt][2] *= e1; accY[mt][nt][3] *= e1;
        }
    }

    // -------- pass 1a: G = C . Bt^T --------
    {
        float accG[4][4][4];
#pragma unroll
        for (int i = 0; i < 4; i++)
#pragma unroll
            for (int j = 0; j < 4; j++)
#pragma unroll
                for (int k = 0; k < 4; k++) accG[i][j][k] = 0.f;

#pragma unroll
        for (int ks = 0; ks < 4; ks++) {
            uint32_t ah[4][4], al[4][4], bh[2][4], bl[2][4];
            const int ag = 2 * ks + a_g, bg = 2 * ks + b_g;
#pragma unroll
            for (int mt = 0; mt < 4; mt++)
                ldsm_x4(ah[mt], sb + Y_CH + swz128(wm + mt * 16 + a_r, ag));
#pragma unroll
            for (int p = 0; p < 2; p++)
                ldsm_x4(bh[p], sb + Y_BH + swz128(wn32 + p * 16 + b_r, bg));
#pragma unroll
            for (int mt = 0; mt < 4; mt++)
#pragma unroll
                for (int nt = 0; nt < 4; nt++)
                    mma16816(accG[mt][nt], ah[mt], bh[nt >> 1][(nt & 1) * 2], bh[nt >> 1][(nt & 1) * 2 + 1]);
#pragma unroll
            for (int mt = 0; mt < 4; mt++)
                ldsm_x4(al[mt], sb + Y_CL + swz128(wm + mt * 16 + a_r, ag));
#pragma unroll
            for (int mt = 0; mt < 4; mt++)
#pragma unroll
                for (int nt = 0; nt < 4; nt++)
                    mma16816(accG[mt][nt], al[mt], bh[nt >> 1][(nt & 1) * 2], bh[nt >> 1][(nt & 1) * 2 + 1]);
#pragma unroll
            for (int p = 0; p < 2; p++)
                ldsm_x4(bl[p], sb + Y_BL + swz128(wn32 + p * 16 + b_r, bg));
#pragma unroll
            for (int mt = 0; mt < 4; mt++)
#pragma unroll
                for (int nt = 0; nt < 4; nt++)
                    mma16816(accG[mt][nt], ah[mt], bl[nt >> 1][(nt & 1) * 2], bl[nt >> 1][(nt & 1) * 2 + 1]);
        }

        __syncthreads();   // all warps done reading C/B before overlay

#pragma unroll
        for (int mt = 0; mt < 4; mt++) {
            const int l0 = wm + mt * 16 + gid;
            const int l1 = l0 + 8;
            const float A0 = sAcs[l0], A1 = sAcs[l1];
#pragma unroll
            for (int nt = 0; nt < 4; nt++) {
                const int s0 = wn32 + nt * 8 + tig * 2;
                const int s1 = s0 + 1;
                const float As0 = sAcs[s0], As1 = sAcs[s1];
                const float d0 = sDt[s0], d1 = sDt[s1];
                float g00 = (s0 <= l0) ? accG[mt][nt][0] * expf(A0 - As0) * d0 : 0.f;
                float g01 = (s1 <= l0) ? accG[mt][nt][1] * expf(A0 - As1) * d1 : 0.f;
                float g10 = (s0 <= l1) ? accG[mt][nt][2] * expf(A1 - As0) * d0 : 0.f;
                float g11 = (s1 <= l1) ? accG[mt][nt][3] * expf(A1 - As1) * d1 : 0.f;
                uint32_t hp, lp;
                const uint32_t a0 = swz256(l0, s0 >> 3) + ((s0 & 7) << 1);
                split_pair(g00, g01, hp, lp);
                asm volatile("st.shared.b32 [%0], %1;" :: "r"(sb + Y_GH + a0), "r"(hp));
                asm volatile("st.shared.b32 [%0], %1;" :: "r"(sb + Y_GL + a0), "r"(lp));
                const uint32_t a1 = swz256(l1, s0 >> 3) + ((s0 & 7) << 1);
                split_pair(g10, g11, hp, lp);
                asm volatile("st.shared.b32 [%0], %1;" :: "r"(sb + Y_GH + a1), "r"(hp));
                asm volatile("st.shared.b32 [%0], %1;" :: "r"(sb + Y_GL + a1), "r"(lp));
            }
        }
    }

    __syncthreads();

    // -------- pass 2: Y += G' . X^T  (X = raw v) --------
#pragma unroll
    for (int ks = 0; ks < 8; ks++) {
        uint32_t ah[4][4], al[4][4], bh[4], bl[4];
        const int ag = 2 * ks + a_g;
        const int krb = ks * 16 + tB_kr;
#pragma unroll
        for (int mt = 0; mt < 4; mt++)
            ldsm_x4(ah[mt], sb + Y_GH + swz256(wm + mt * 16 + a_r, ag));
        ldsm_x4_t(bh, sb + Y_XH + swz128(krb, (wn16 >> 3) + tB_ng));
#pragma unroll
        for (int mt = 0; mt < 4; mt++)
#pragma unroll
            for (int nt = 0; nt < 2; nt++)
                mma16816(accY[mt][nt], ah[mt], bh[nt * 2], bh[nt * 2 + 1]);
#pragma unroll
        for (int mt = 0; mt < 4; mt++)
            ldsm_x4(al[mt], sb + Y_GL + swz256(wm + mt * 16 + a_r, ag));
#pragma unroll
        for (int mt = 0; mt < 4; mt++)
#pragma unroll
            for (int nt = 0; nt < 2; nt++)
                mma16816(accY[mt][nt], al[mt], bh[nt * 2], bh[nt * 2 + 1]);
        ldsm_x4_t(bl, sb + Y_XL + swz128(krb, (wn16 >> 3) + tB_ng));
#pragma unroll
        for (int mt = 0; mt < 4; mt++)
#pragma unroll
            for (int nt = 0; nt < 2; nt++)
                mma16816(accY[mt][nt], ah[mt], bl[nt * 2], bl[nt * 2 + 1]);
    }

#pragma unroll
    for (int mt = 0; mt < 4; mt++) {
        const int l0 = wm + mt * 16 + gid;
#pragma unroll
        for (int nt = 0; nt < 2; nt++) {
            const int p = wn16 + nt * 8 + tig * 2;
            const size_t y0 = ((size_t)b * LL + c * CHUNK + l0) * DD + h * PP + p;
            const size_t y1 = ((size_t)b * LL + c * CHUNK + l0 + 8) * DD + h * PP + p;
            *reinterpret_cast<float2*>(&g_y[y0]) = make_float2(accY[mt][nt][0], accY[mt][nt][1]);
            *reinterpret_cast<float2*>(&g_y[y1]) = make_float2(accY[mt][nt][2], accY[mt][nt][3]);
        }
    }
}

// ============================================================
// Pass D: RMSNorm + swish gate -> bf16 hi/lo; warp-per-row
// ============================================================
__global__ __launch_bounds__(256) void normgate_kernel(const float* __restrict__ gnorm_w) {
    const int r = blockIdx.x * 8 + (threadIdx.x >> 5);   // row = (b*L + l)*H + h
    const int lane = threadIdx.x & 31;
    const int h = r % HH;
    const size_t bl = (size_t)r / HH;
    const size_t yb = bl * DD + (size_t)h * PP;
    const float y0 = g_y[yb + lane];
    const float y1 = g_y[yb + lane + 32];
    float s = y0 * y0 + y1 * y1;
#pragma unroll
    for (int o = 16; o > 0; o >>= 1) s += __shfl_xor_sync(0xffffffffu, s, o);
    const float rms = rsqrtf(s / (float)PP + EPS);
    const size_t gb = bl * PROJ + CONV + (size_t)h * PP;
#pragma unroll
    for (int q = 0; q < 2; q++) {
        const int p = lane + q * 32;
        const float yv = (q == 0) ? y0 : y1;
        const float gv = g_proj[gb + p];
        const float out = yv * rms * gnorm_w[p] * (gv * sigmoidf_(gv));
        __nv_bfloat16 hi = __float2bfloat16(out);
        g_yhi[yb + p] = hi;
        g_ylo[yb + p] = __float2bfloat16(out - __bfloat162float(hi));
    }
}

// ============================================================
// launch
// ============================================================
extern "C" void kernel_launch(void* const* d_in, const int* in_sizes, int n_in,
                              void* d_out, int out_size) {
    const float* hidden   = (const float*)d_in[0];
    const float* W_vkqgdt = (const float*)d_in[1];
    const float* conv_w   = (const float*)d_in[2];
    const float* conv_b   = (const float*)d_in[3];
    const float* dt_bias  = (const float*)d_in[4];
    const float* A_logb   = (const float*)d_in[5];
    const float* gnorm_w  = (const float*)d_in[6];
    const float* W_o      = (const float*)d_in[7];
    float* out = (float*)d_out;

    float* proj_ptr;
    cudaGetSymbolAddress((void**)&proj_ptr, g_proj);
    __nv_bfloat16 *hhi, *hlo, *whi, *wlo, *ohi, *olo, *yhi, *ylo;
    cudaGetSymbolAddress((void**)&hhi, g_hhi);
    cudaGetSymbolAddress((void**)&hlo, g_hlo);
    cudaGetSymbolAddress((void**)&whi, g_whi);
    cudaGetSymbolAddress((void**)&wlo, g_wlo);
    cudaGetSymbolAddress((void**)&ohi, g_ohi);
    cudaGetSymbolAddress((void**)&olo, g_olo);
    cudaGetSymbolAddress((void**)&yhi, g_yhi);
    cudaGetSymbolAddress((void**)&ylo, g_ylo);

    cudaFuncSetAttribute(gemm_mma, cudaFuncAttributeMaxDynamicSharedMemorySize, GEMM_SMEM);
    cudaFuncSetAttribute(chunk_state_mma, cudaFuncAttributeMaxDynamicSharedMemorySize, CS_SMEM);
    cudaFuncSetAttribute(y_mma, cudaFuncAttributeMaxDynamicSharedMemorySize, Y_SMEM);

    // 0) split inputs
    {
        const int n4a = (BB * LL * DD) / 4;
        split_kernel<<<(n4a + 255) / 256, 256>>>(hidden, hhi, hlo, n4a);
        const int n4w = (PROJ * DD) / 4;
        split_kernel<<<(n4w + 255) / 256, 256>>>(W_vkqgdt, whi, wlo, n4w);
        const int n4o = (DD * DD) / 4;
        split_kernel<<<(n4o + 255) / 256, 256>>>(W_o, ohi, olo, n4o);
    }

    // 1) in-projection
    gemm_mma<<<dim3((PROJ + 127) / 128, (BB * LL) / 128), 256, GEMM_SMEM>>>(
        proj_ptr, hhi, hlo, whi, wlo, PROJ, DD);

    // 2) conv + silu (emits bf16 hi/lo), dt
    {
        const size_t tot = (size_t)BB * LL * CONV;
        conv_silu_kernel<<<(unsigned)((tot + 255) / 256), 256>>>(conv_w, conv_b);
        dt_kernel<<<(BB * LL * HH + 255) / 256, 256>>>(dt_bias, A_logb);
    }

    // 3) SSD (tensor-core)
    chunk_state_mma<<<dim3(HH, NC, BB), 128, CS_SMEM>>>();
    state_scan_kernel<<<BB * HH * 8, 256>>>();
    y_mma<<<dim3(HH, NC, BB), 256, Y_SMEM>>>();

    // 4) norm + gate (warp-per-row, emits bf16 hi/lo)
    normgate_kernel<<<BB * LL * HH / 8, 256>>>(gnorm_w);

    // 5) out-projection
    gemm_mma<<<dim3(DD / 128, (BB * LL) / 128), 256, GEMM_SMEM>>>(
        out, yhi, ylo, ohi, olo, DD, DD);
}

// round 14
// speedup vs baseline: 1.0440x; 1.0147x over previous
#include <cuda_runtime.h>
#include <cuda_bf16.h>
#include <math.h>
#include <stdint.h>

// ---------------- problem constants ----------------
#define BB      2
#define LL      2048
#define HH      32
#define KVH     8
#define PP      64
#define DD      2048           // HH*PP
#define CONV    3072           // (HH+2*KVH)*PP
#define PROJ    5152           // CONV + DD + HH
#define CHUNK   128
#define NC      16             // LL/CHUNK
#define EPS     1e-5f

// ---------------- scratch (device globals; no allocation allowed) ----------------
__device__ __align__(16) float g_proj[(size_t)BB * LL * PROJ];
__device__ __align__(16) float g_dt  [(size_t)BB * LL * HH];
__device__ __align__(16) float g_adt [(size_t)BB * LL * HH];
__device__ __align__(16) float g_acs [(size_t)BB * HH * NC * CHUNK];
__device__ __align__(16) float g_tot [(size_t)BB * HH * NC];
__device__ __align__(16) float g_states[(size_t)BB * NC * HH * PP * PP];
__device__ __align__(16) float g_y   [(size_t)BB * LL * DD];

// chunk-start states pre-split to bf16 hi/lo by the scan
__device__ __align__(16) __nv_bfloat16 g_shi[(size_t)BB * NC * HH * PP * PP];
__device__ __align__(16) __nv_bfloat16 g_slo[(size_t)BB * NC * HH * PP * PP];

// post-conv vkq stored directly as bf16 hi/lo
__device__ __align__(16) __nv_bfloat16 g_vkhi[(size_t)BB * LL * CONV], g_vklo[(size_t)BB * LL * CONV];

// split-precision bf16 operands for tensor-core GEMMs
__device__ __align__(16) __nv_bfloat16 g_hhi[(size_t)BB * LL * DD], g_hlo[(size_t)BB * LL * DD];
__device__ __align__(16) __nv_bfloat16 g_whi[(size_t)PROJ * DD],    g_wlo[(size_t)PROJ * DD];
__device__ __align__(16) __nv_bfloat16 g_ohi[(size_t)DD * DD],      g_olo[(size_t)DD * DD];
__device__ __align__(16) __nv_bfloat16 g_yhi[(size_t)BB * LL * DD], g_ylo[(size_t)BB * LL * DD];

// ---------------- helpers ----------------
__device__ __forceinline__ float sigmoidf_(float x) { return 1.f / (1.f + expf(-x)); }
__device__ __forceinline__ float softplusf_(float x) { return (x > 20.f) ? x : log1pf(expf(x)); }

__device__ __forceinline__ uint32_t smem_u32(const void* p) {
    uint32_t a;
    asm("{ .reg .u64 t; cvta.to.shared.u64 t, %1; cvt.u32.u64 %0, t; }" : "=r"(a) : "l"(p));
    return a;
}
__device__ __forceinline__ void cpa16(uint32_t dst, const void* src, int srcsize) {
    asm volatile("cp.async.cg.shared.global [%0], [%1], 16, %2;"
                 :: "r"(dst), "l"(src), "r"(srcsize));
}
__device__ __forceinline__ void cpa_commit() { asm volatile("cp.async.commit_group;"); }
template <int N> __device__ __forceinline__ void cpa_wait() {
    asm volatile("cp.async.wait_group %0;" :: "n"(N));
}
__device__ __forceinline__ void ldsm_x4(uint32_t* r, uint32_t a) {
    asm volatile("ldmatrix.sync.aligned.m8n8.x4.shared.b16 {%0,%1,%2,%3}, [%4];"
                 : "=r"(r[0]), "=r"(r[1]), "=r"(r[2]), "=r"(r[3]) : "r"(a));
}
__device__ __forceinline__ void ldsm_x4_t(uint32_t* r, uint32_t a) {
    asm volatile("ldmatrix.sync.aligned.m8n8.x4.trans.shared.b16 {%0,%1,%2,%3}, [%4];"
                 : "=r"(r[0]), "=r"(r[1]), "=r"(r[2]), "=r"(r[3]) : "r"(a));
}
__device__ __forceinline__ void mma16816(float* c, const uint32_t* a, uint32_t b0, uint32_t b1) {
    asm volatile("mma.sync.aligned.m16n8k16.row.col.f32.bf16.bf16.f32 "
                 "{%0,%1,%2,%3}, {%4,%5,%6,%7}, {%8,%9}, {%0,%1,%2,%3};"
                 : "+f"(c[0]), "+f"(c[1]), "+f"(c[2]), "+f"(c[3])
                 : "r"(a[0]), "r"(a[1]), "r"(a[2]), "r"(a[3]), "r"(b0), "r"(b1));
}
__device__ __forceinline__ void split_pair(float f0, float f1, uint32_t& hp, uint32_t& lp) {
    __nv_bfloat16 h0 = __float2bfloat16(f0);
    __nv_bfloat16 h1 = __float2bfloat16(f1);
    __nv_bfloat16 l0 = __float2bfloat16(f0 - __bfloat162float(h0));
    __nv_bfloat16 l1 = __float2bfloat16(f1 - __bfloat162float(h1));
    hp = (uint32_t)__bfloat16_as_ushort(h0) | ((uint32_t)__bfloat16_as_ushort(h1) << 16);
    lp = (uint32_t)__bfloat16_as_ushort(l0) | ((uint32_t)__bfloat16_as_ushort(l1) << 16);
}
// swizzles: rows of 128B (64 bf16) / 256B (128 bf16); 16B group permute
__device__ __forceinline__ uint32_t swz128(int r, int g) { return (uint32_t)(r * 128 + ((g ^ (r & 7)) << 4)); }
__device__ __forceinline__ uint32_t swz256(int r, int g) { return (uint32_t)(r * 256 + ((g ^ (r & 7)) << 4)); }

// reconstruct fp32 = hi + lo from bf16 pair source, scale, re-split to smem
__device__ __forceinline__ void split_row32_rec(uint32_t dH, uint32_t dL,
                                                const __nv_bfloat16* __restrict__ hsrc,
                                                const __nv_bfloat16* __restrict__ lsrc,
                                                int r, int c0, float scale) {
#pragma unroll
    for (int c = 0; c < 32; c += 8) {
        uint4 hv = *reinterpret_cast<const uint4*>(hsrc + c);
        uint4 lv = *reinterpret_cast<const uint4*>(lsrc + c);
        const uint32_t hw[4] = {hv.x, hv.y, hv.z, hv.w};
        const uint32_t lw[4] = {lv.x, lv.y, lv.z, lv.w};
        uint32_t hp[4], lp[4];
#pragma unroll
        for (int j = 0; j < 4; j++) {
            float f0 = __bfloat162float(__ushort_as_bfloat16((unsigned short)(hw[j] & 0xFFFF)))
                     + __bfloat162float(__ushort_as_bfloat16((unsigned short)(lw[j] & 0xFFFF)));
            float f1 = __bfloat162float(__ushort_as_bfloat16((unsigned short)(hw[j] >> 16)))
                     + __bfloat162float(__ushort_as_bfloat16((unsigned short)(lw[j] >> 16)));
            split_pair(f0 * scale, f1 * scale, hp[j], lp[j]);
        }
        const int col = c0 + c;     // multiple of 8
        const uint32_t a = swz128(r, col >> 3);
        asm volatile("st.shared.v4.b32 [%0], {%1,%2,%3,%4};"
                     :: "r"(dH + a), "r"(hp[0]), "r"(hp[1]), "r"(hp[2]), "r"(hp[3]));
        asm volatile("st.shared.v4.b32 [%0], {%1,%2,%3,%4};"
                     :: "r"(dL + a), "r"(lp[0]), "r"(lp[1]), "r"(lp[2]), "r"(lp[3]));
    }
}

// ============================================================
// fp32 -> (bf16 hi, bf16 lo) split, vectorized x4
// ============================================================
__global__ void split_kernel(const float* __restrict__ src,
                             __nv_bfloat16* __restrict__ hi,
                             __nv_bfloat16* __restrict__ lo, int n4) {
    const int i = blockIdx.x * blockDim.x + threadIdx.x;
    if (i >= n4) return;
    const float4 v = reinterpret_cast<const float4*>(src)[i];
    uint32_t h0, l0, h1, l1;
    split_pair(v.x, v.y, h0, l0);
    split_pair(v.z, v.w, h1, l1);
    reinterpret_cast<uint2*>(hi)[i] = make_uint2(h0, h1);
    reinterpret_cast<uint2*>(lo)[i] = make_uint2(l0, l1);
}

// ============================================================
// mma.sync bf16 split-precision GEMM (R7 passing config, frozen)
// ============================================================
#define TILE_BYTES 8192
#define STAGE_BYTES (4 * TILE_BYTES)
#define NSTAGE 3
#define GEMM_SMEM (NSTAGE * STAGE_BYTES)

__device__ __forceinline__ uint32_t sw_off(int r, int g) {
    return (uint32_t)(r * 64 + ((g ^ ((r >> 1) & 3)) << 4));
}

__device__ __forceinline__ void load_stage(
    uint32_t sb, const __nv_bfloat16* __restrict__ Ahi, const __nv_bfloat16* __restrict__ Alo,
    const __nv_bfloat16* __restrict__ Bhi, const __nv_bfloat16* __restrict__ Blo,
    int mBase, int nBase, int Nd, int Kd, int kBase, int tid) {
#pragma unroll
    for (int t = 0; t < 2; t++) {
        const int idx = tid + (t << 8);
        const int r = idx >> 2;
        const int g = idx & 3;
        const uint32_t off = sw_off(r, g);
        const size_t srcA = (size_t)(mBase + r) * Kd + kBase + g * 8;
        cpa16(sb + off, Ahi + srcA, 16);
        cpa16(sb + TILE_BYTES + off, Alo + srcA, 16);
        const int brow = nBase + r;
        const int ok = (brow < Nd) ? 16 : 0;
        const size_t srcB = (size_t)(ok ? brow : (Nd - 1)) * Kd + kBase + g * 8;
        cpa16(sb + 2 * TILE_BYTES + off, Bhi + srcB, ok);
        cpa16(sb + 3 * TILE_BYTES + off, Blo + srcB, ok);
    }
}

__global__ __launch_bounds__(256, 2) void gemm_mma(
    float* __restrict__ C,
    const __nv_bfloat16* __restrict__ Ahi, const __nv_bfloat16* __restrict__ Alo,
    const __nv_bfloat16* __restrict__ Bhi, const __nv_bfloat16* __restrict__ Blo,
    int Nd, int Kd) {
    extern __shared__ __align__(16) char dsm[];
    const int tid  = threadIdx.x;
    const int warp = tid >> 5;
    const int lane = tid & 31;
    const int mBase = blockIdx.y << 7;
    const int nBase = blockIdx.x << 7;
    const int wm = (warp >> 2) << 6;
    const int wn = (warp & 3) << 5;

    const uint32_t smem0 = smem_u32(dsm);

    float acc[4][4][4];
#pragma unroll
    for (int i = 0; i < 4; i++)
#pragma unroll
        for (int j = 0; j < 4; j++)
#pragma unroll
            for (int k = 0; k < 4; k++) acc[i][j][k] = 0.f;

    const int a_r = lane & 15;
    const int a_gsel = lane >> 4;
    const int b_r = (lane & 7) + ((lane & 16) >> 1);
    const int b_gsel = (lane >> 3) & 1;

    const int nk = Kd >> 5;
    load_stage(smem0, Ahi, Alo, Bhi, Blo, mBase, nBase, Nd, Kd, 0, tid);
    cpa_commit();
    load_stage(smem0 + STAGE_BYTES, Ahi, Alo, Bhi, Blo, mBase, nBase, Nd, Kd, 32, tid);
    cpa_commit();

    int bufc = 0;
    for (int s = 0; s < nk; s++) {
        if (s == nk - 1) cpa_wait<0>(); else cpa_wait<1>();
        __syncthreads();
        if (s + 2 < nk) {
            int bufn = bufc + 2; if (bufn >= NSTAGE) bufn -= NSTAGE;
            load_stage(smem0 + bufn * STAGE_BYTES, Ahi, Alo, Bhi, Blo,
                       mBase, nBase, Nd, Kd, (s + 2) << 5, tid);
            cpa_commit();
        }

        const uint32_t sb = smem0 + bufc * STAGE_BYTES;
        const uint32_t tAh = sb, tAl = sb + TILE_BYTES;
        const uint32_t tBh = sb + 2 * TILE_BYTES, tBl = sb + 3 * TILE_BYTES;

#pragma unroll
        for (int ks = 0; ks < 2; ks++) {
            uint32_t a[4][4], b[2][4];
            const int ag = 2 * ks + a_gsel;
            const int bg = 2 * ks + b_gsel;
#pragma unroll
            for (int mt = 0; mt < 4; mt++)
                ldsm_x4(a[mt], tAh + sw_off(wm + mt * 16 + a_r, ag));
#pragma unroll
            for (int p = 0; p < 2; p++)
                ldsm_x4(b[p], tBh + sw_off(wn + p * 16 + b_r, bg));
#pragma unroll
            for (int mt = 0; mt < 4; mt++)
#pragma unroll
                for (int nt = 0; nt < 4; nt++)
                    mma16816(acc[mt][nt], a[mt], b[nt >> 1][(nt & 1) * 2], b[nt >> 1][(nt & 1) * 2 + 1]);
#pragma unroll
            for (int p = 0; p < 2; p++)
                ldsm_x4(b[p], tBl + sw_off(wn + p * 16 + b_r, bg));
#pragma unroll
            for (int mt = 0; mt < 4; mt++)
#pragma unroll
                for (int nt = 0; nt < 4; nt++)
                    mma16816(acc[mt][nt], a[mt], b[nt >> 1][(nt & 1) * 2], b[nt >> 1][(nt & 1) * 2 + 1]);
#pragma unroll
            for (int mt = 0; mt < 4; mt++)
                ldsm_x4(a[mt], tAl + sw_off(wm + mt * 16 + a_r, ag));
#pragma unroll
            for (int p = 0; p < 2; p++)
                ldsm_x4(b[p], tBh + sw_off(wn + p * 16 + b_r, bg));
#pragma unroll
            for (int mt = 0; mt < 4; mt++)
#pragma unroll
                for (int nt = 0; nt < 4; nt++)
                    mma16816(acc[mt][nt], a[mt], b[nt >> 1][(nt & 1) * 2], b[nt >> 1][(nt & 1) * 2 + 1]);
        }
        if (++bufc == NSTAGE) bufc = 0;
    }

    const int gid = lane >> 2, tig = lane & 3;
#pragma unroll
    for (int mt = 0; mt < 4; mt++) {
        const int row0 = mBase + wm + mt * 16 + gid;
#pragma unroll
        for (int nt = 0; nt < 4; nt++) {
            const int col = nBase + wn + nt * 8 + tig * 2;
            if (col < Nd) {
                float2 v01 = make_float2(acc[mt][nt][0], acc[mt][nt][1]);
                float2 v23 = make_float2(acc[mt][nt][2], acc[mt][nt][3]);
                *reinterpret_cast<float2*>(C + (size_t)row0 * Nd + col) = v01;
                *reinterpret_cast<float2*>(C + (size_t)(row0 + 8) * Nd + col) = v23;
            }
        }
    }
}

// ============================================================
// Conv (kernel=2, causal) + SiLU -> bf16 hi/lo directly
// ============================================================
__global__ void conv_silu_kernel(const float* __restrict__ conv_w,
                                 const float* __restrict__ conv_b) {
    const size_t idx = (size_t)blockIdx.x * blockDim.x + threadIdx.x;
    if (idx >= (size_t)BB * LL * CONV) return;
    const int c = (int)(idx % CONV);
    const size_t bl = idx / CONV;
    const int l = (int)(bl % LL);
    const float cur = g_proj[bl * PROJ + c];
    const float prev = (l > 0) ? g_proj[(bl - 1) * PROJ + c] : 0.f;
    const float v = prev * conv_w[c * 2] + cur * conv_w[c * 2 + 1] + conv_b[c];
    const float o = v * sigmoidf_(v);
    __nv_bfloat16 hi = __float2bfloat16(o);
    g_vkhi[idx] = hi;
    g_vklo[idx] = __float2bfloat16(o - __bfloat162float(hi));
}

__global__ void dt_kernel(const float* __restrict__ dt_bias,
                          const float* __restrict__ A_log_bias) {
    const int idx = blockIdx.x * blockDim.x + threadIdx.x;
    if (idx >= BB * LL * HH) return;
    const int h = idx % HH;
    const size_t bl = idx / HH;
    const float raw = g_proj[bl * PROJ + (CONV + DD) + h];
    const float dtv = softplusf_(raw + dt_bias[h]);
    g_dt[idx] = dtv;
    g_adt[idx] = dtv * (-expf(A_log_bias[h]));
}

// ============================================================
// Pass A (mma): per-(b,c,h) parallel cumsum + local chunk state
// X tile via direct cp.async (scale=1 => stored hi/lo pair is exact);
// K tile rescaled in-kernel by w*dt. X load overlaps the cumsum.
// ============================================================
#define CS_KH   0
#define CS_KL   16384
#define CS_XH   32768
#define CS_XL   49152
#define CS_ACS  65536
#define CS_SMEM (65536 + 512)

__global__ __launch_bounds__(128) void chunk_state_mma() {
    extern __shared__ __align__(16) char dsm[];
    const uint32_t sb = smem_u32(dsm);
    float* sAcs = reinterpret_cast<float*>(dsm + CS_ACS);

    const int h = blockIdx.x, c = blockIdx.y, b = blockIdx.z;
    const int tid = threadIdx.x;
    const int kvh = h >> 2;

    // issue X tile loads immediately (overlap with cumsum)
    {
        const size_t rowbase = ((size_t)b * LL + c * CHUNK) * CONV + (size_t)kvh * PP;
        for (int i = tid; i < 1024; i += 128) {
            const int r = i >> 3, g = i & 7;
            const uint32_t d = swz128(r, g);
            const size_t s = rowbase + (size_t)r * CONV + g * 8;
            cpa16(sb + CS_XH + d, g_vkhi + s, 16);
            cpa16(sb + CS_XL + d, g_vklo + s, 16);
        }
        cpa_commit();
    }

    sAcs[tid] = g_adt[((size_t)b * LL + c * CHUNK + tid) * HH + h];
    __syncthreads();
    // Hillis-Steele inclusive scan over 128 elements
#pragma unroll
    for (int off = 1; off < CHUNK; off <<= 1) {
        const float v = sAcs[tid];
        const float u = (tid >= off) ? sAcs[tid - off] : 0.f;
        __syncthreads();
        sAcs[tid] = v + u;
        __syncthreads();
    }
    const float total = sAcs[CHUNK - 1];
    g_acs[(((size_t)b * HH + h) * NC + c) * CHUNK + tid] = sAcs[tid];
    if (tid == 0)
        g_tot[((size_t)b * HH + h) * NC + c] = total;

    // K tile: reconstruct + scale by w*dt + split
    {
        const int l = tid;
        const size_t base = ((size_t)b * LL + c * CHUNK + l) * CONV;
        const float w = expf(total - sAcs[l]);
        const float dtv = g_dt[((size_t)b * LL + c * CHUNK + l) * HH + h];
        const size_t ko = base + KVH * PP + kvh * PP;
        const float ws = w * dtv;
        split_row32_rec(sb + CS_KH, sb + CS_KL, g_vkhi + ko,      g_vklo + ko,      l, 0,  ws);
        split_row32_rec(sb + CS_KH, sb + CS_KL, g_vkhi + ko + 32, g_vklo + ko + 32, l, 32, ws);
    }
    cpa_wait<0>();
    __syncthreads();

    const int warp = tid >> 5, lane = tid & 31;
    const int wn = warp * 16;
    const int tA_kr = (lane & 7) + ((lane >> 4) & 1) * 8;
    const int tA_mg = (lane >> 3) & 1;
    const int tB_kr = (lane & 7) + ((lane >> 3) & 1) * 8;
    const int tB_ng = (lane >> 4) & 1;

    float acc[4][2][4];
#pragma unroll
    for (int i = 0; i < 4; i++)
#pragma unroll
        for (int j = 0; j < 2; j++)
#pragma unroll
            for (int k = 0; k < 4; k++) acc[i][j][k] = 0.f;

#pragma unroll
    for (int ks = 0; ks < 8; ks++) {
        const int kra = ks * 16 + tA_kr;
        const int krb = ks * 16 + tB_kr;
        uint32_t ah[4][4], al[4][4], bh[4], bl[4];
#pragma unroll
        for (int mt = 0; mt < 4; mt++)
            ldsm_x4_t(ah[mt], sb + CS_KH + swz128(kra, mt * 2 + tA_mg));
        ldsm_x4_t(bh, sb + CS_XH + swz128(krb, (wn >> 3) + tB_ng));
#pragma unroll
        for (int mt = 0; mt < 4; mt++)
#pragma unroll
            for (int nt = 0; nt < 2; nt++)
                mma16816(acc[mt][nt], ah[mt], bh[nt * 2], bh[nt * 2 + 1]);
#pragma unroll
        for (int mt = 0; mt < 4; mt++)
            ldsm_x4_t(al[mt], sb + CS_KL + swz128(kra, mt * 2 + tA_mg));
#pragma unroll
        for (int mt = 0; mt < 4; mt++)
#pragma unroll
            for (int nt = 0; nt < 2; nt++)
                mma16816(acc[mt][nt], al[mt], bh[nt * 2], bh[nt * 2 + 1]);
        ldsm_x4_t(bl, sb + CS_XL + swz128(krb, (wn >> 3) + tB_ng));
#pragma unroll
        for (int mt = 0; mt < 4; mt++)
#pragma unroll
            for (int nt = 0; nt < 2; nt++)
                mma16816(acc[mt][nt], ah[mt], bl[nt * 2], bl[nt * 2 + 1]);
    }

    const int gid = lane >> 2, tig = lane & 3;
    const size_t so = (((size_t)b * NC + c) * HH + h) * (PP * PP);
#pragma unroll
    for (int mt = 0; mt < 4; mt++) {
        const int n0 = mt * 16 + gid;
#pragma unroll
        for (int nt = 0; nt < 2; nt++) {
            const int p = wn + nt * 8 + tig * 2;
            *reinterpret_cast<float2*>(&g_states[so + (size_t)n0 * PP + p]) =
                make_float2(acc[mt][nt][0], acc[mt][nt][1]);
            *reinterpret_cast<float2*>(&g_states[so + (size_t)(n0 + 8) * PP + p]) =
                make_float2(acc[mt][nt][2], acc[mt][nt][3]);
        }
    }
}

// ============================================================
// Pass B: inter-chunk scan; emits chunk-start states as bf16 hi/lo
// ============================================================
__global__ void state_scan_kernel() {
    __shared__ float et[NC];
    const int bh = blockIdx.x >> 3;
    const int slab = blockIdx.x & 7;
    const int b = bh / HH, h = bh % HH;
    if (threadIdx.x < NC)
        et[threadIdx.x] = expf(g_tot[(size_t)bh * NC + threadIdx.x]);
    __syncthreads();
    const int e0 = slab * 512;
    for (int e = e0 + threadIdx.x; e < e0 + 512; e += blockDim.x) {
        float S = 0.f;
        for (int c = 0; c < NC; c++) {
            const size_t idx = (((size_t)b * NC + c) * HH + h) * (PP * PP) + e;
            const float loc = g_states[idx];
            const __nv_bfloat16 hi = __float2bfloat16(S);
            g_shi[idx] = hi;
            g_slo[idx] = __float2bfloat16(S - __bfloat162float(hi));
            S = et[c] * S + loc;
        }
    }
}

// ============================================================
// Pass C (mma): Y = (mask(C.B^T)·decay·dt) X + exp(Acs) C.S_start
// All operand tiles via swizzled cp.async; G overlays C+B.
// ============================================================
#define Y_CH   0
#define Y_CL   16384
#define Y_BH   32768
#define Y_BL   49152
#define Y_XH   65536
#define Y_XL   81920
#define Y_SH   98304
#define Y_SL   106496
#define Y_GH   0            // overlays C (hi+lo)
#define Y_GL   32768        // overlays B (hi+lo)
#define Y_ACS  114688
#define Y_DT   (114688 + 512)
#define Y_SMEM (114688 + 1024 + 64)

__global__ __launch_bounds__(256) void y_mma() {
    extern __shared__ __align__(16) char dsm[];
    const uint32_t sb = smem_u32(dsm);
    float* sAcs = reinterpret_cast<float*>(dsm + Y_ACS);
    float* sDt  = reinterpret_cast<float*>(dsm + Y_DT);

    const int h = blockIdx.x, c = blockIdx.y, b = blockIdx.z;
    const int tid = threadIdx.x;
    const int kvh = h >> 2;

    // async tile loads: C, B, X, S hi/lo straight from bf16 arrays
    {
        const size_t rowbase = ((size_t)b * LL + c * CHUNK) * CONV;
        const uint32_t offC = 2 * KVH * PP + h * PP;
        const uint32_t offB = KVH * PP + kvh * PP;
        const uint32_t offX = kvh * PP;
        for (int i = tid; i < 1024; i += 256) {
            const int r = i >> 3, g = i & 7;
            const uint32_t d = swz128(r, g);
            const size_t s = rowbase + (size_t)r * CONV + g * 8;
            cpa16(sb + Y_CH + d, g_vkhi + s + offC, 16);
            cpa16(sb + Y_CL + d, g_vklo + s + offC, 16);
            cpa16(sb + Y_BH + d, g_vkhi + s + offB, 16);
            cpa16(sb + Y_BL + d, g_vklo + s + offB, 16);
            cpa16(sb + Y_XH + d, g_vkhi + s + offX, 16);
            cpa16(sb + Y_XL + d, g_vklo + s + offX, 16);
        }
        const size_t stbase = (((size_t)b * NC + c) * HH + h) * (PP * PP);
        for (int i = tid; i < 512; i += 256) {
            const int r = i >> 3, g = i & 7;       // r = n row 0..63
            const uint32_t d = swz128(r, g);
            const size_t s = stbase + (size_t)r * PP + g * 8;
            cpa16(sb + Y_SH + d, g_shi + s, 16);
            cpa16(sb + Y_SL + d, g_slo + s, 16);
        }
        cpa_commit();
    }

    if (tid < CHUNK) {
        sAcs[tid] = g_acs[(((size_t)b * HH + h) * NC + c) * CHUNK + tid];
        sDt[tid]  = g_dt[((size_t)b * LL + c * CHUNK + tid) * HH + h];
    }
    cpa_wait<0>();
    __syncthreads();

    const int warp = tid >> 5, lane = tid & 31;
    const int wm = (warp >> 2) * 64;
    const int wn32 = (warp & 3) * 32;
    const int wn16 = (warp & 3) * 16;
    const int gid = lane >> 2, tig = lane & 3;

    const int a_r = lane & 15, a_g = lane >> 4;
    const int b_r = (lane & 7) + ((lane & 16) >> 1), b_g = (lane >> 3) & 1;
    const int tB_kr = (lane & 7) + ((lane >> 3) & 1) * 8;
    const int tB_ng = (lane >> 4) & 1;

    // -------- pass 1b FIRST: Yo = C . S^T --------
    float accY[4][2][4];
#pragma unroll
    for (int i = 0; i < 4; i++)
#pragma unroll
        for (int j = 0; j < 2; j++)
#pragma unroll
            for (int k = 0; k < 4; k++) accY[i][j][k] = 0.f;

#pragma unroll
    for (int ks = 0; ks < 4; ks++) {
        uint32_t ah[4][4], al[4][4], bh[4], bl[4];
        const int ag = 2 * ks + a_g;
        const int krb = ks * 16 + tB_kr;
#pragma unroll
        for (int mt = 0; mt < 4; mt++)
            ldsm_x4(ah[mt], sb + Y_CH + swz128(wm + mt * 16 + a_r, ag));
        ldsm_x4_t(bh, sb + Y_SH + swz128(krb, (wn16 >> 3) + tB_ng));
#pragma unroll
        for (int mt = 0; mt < 4; mt++)
#pragma unroll
            for (int nt = 0; nt < 2; nt++)
                mma16816(accY[mt][nt], ah[mt], bh[nt * 2], bh[nt * 2 + 1]);
#pragma unroll
        for (int mt = 0; mt < 4; mt++)
            ldsm_x4(al[mt], sb + Y_CL + swz128(wm + mt * 16 + a_r, ag));
#pragma unroll
        for (int mt = 0; mt < 4; mt++)
#pragma unroll
            for (int nt = 0; nt < 2; nt++)
                mma16816(accY[mt][nt], al[mt], bh[nt * 2], bh[nt * 2 + 1]);
        ldsm_x4_t(bl, sb + Y_SL + swz128(krb, (wn16 >> 3) + tB_ng));
#pragma unroll
        for (int mt = 0; mt < 4; mt++)
#pragma unroll
            for (int nt = 0; nt < 2; nt++)
                mma16816(accY[mt][nt], ah[mt], bl[nt * 2], bl[nt * 2 + 1]);
    }

#pragma unroll
    for (int mt = 0; mt < 4; mt++) {
        const float e0 = expf(sAcs[wm + mt * 16 + gid]);
        const float e1 = expf(sAcs[wm + mt * 16 + gid + 8]);
#pragma unroll
        for (int nt = 0; nt < 2; nt++) {
            accY[mt][nt][0] *= e0; accY[mt][nt][1] *= e0;
            accY[mt][nt][2] *= e1; accY[mt][nt][3] *= e1;
        }
    }

    // -------- pass 1a: G = C . Bt^T --------
    {
        float accG[4][4][4];
#pragma unroll
        for (int i = 0; i < 4; i++)
#pragma unroll
            for (int j = 0; j < 4; j++)
#pragma unroll
                for (int k = 0; k < 4; k++) accG[i][j][k] = 0.f;

#pragma unroll
        for (int ks = 0; ks < 4; ks++) {
            uint32_t ah[4][4], al[4][4], bh[2][4], bl[2][4];
            const int ag = 2 * ks + a_g, bg = 2 * ks + b_g;
#pragma unroll
            for (int mt = 0; mt < 4; mt++)
                ldsm_x4(ah[mt], sb + Y_CH + swz128(wm + mt * 16 + a_r, ag));
#pragma unroll
            for (int p = 0; p < 2; p++)
                ldsm_x4(bh[p], sb + Y_BH + swz128(wn32 + p * 16 + b_r, bg));
#pragma unroll
            for (int mt = 0; mt < 4; mt++)
#pragma unroll
                for (int nt = 0; nt < 4; nt++)
                    mma16816(accG[mt][nt], ah[mt], bh[nt >> 1][(nt & 1) * 2], bh[nt >> 1][(nt & 1) * 2 + 1]);
#pragma unroll
            for (int mt = 0; mt < 4; mt++)
                ldsm_x4(al[mt], sb + Y_CL + swz128(wm + mt * 16 + a_r, ag));
#pragma unroll
            for (int mt = 0; mt < 4; mt++)
#pragma unroll
                for (int nt = 0; nt < 4; nt++)
                    mma16816(accG[mt][nt], al[mt], bh[nt >> 1][(nt & 1) * 2], bh[nt >> 1][(nt & 1) * 2 + 1]);
#pragma unroll
            for (int p = 0; p < 2; p++)
                ldsm_x4(bl[p], sb + Y_BL + swz128(wn32 + p * 16 + b_r, bg));
#pragma unroll
            for (int mt = 0; mt < 4; mt++)
#pragma unroll
                for (int nt = 0; nt < 4; nt++)
                    mma16816(accG[mt][nt], ah[mt], bl[nt >> 1][(nt & 1) * 2], bl[nt >> 1][(nt & 1) * 2 + 1]);
        }

        __syncthreads();   // all warps done reading C/B before overlay

#pragma unroll
        for (int mt = 0; mt < 4; mt++) {
            const int l0 = wm + mt * 16 + gid;
            const int l1 = l0 + 8;
            const float A0 = sAcs[l0], A1 = sAcs[l1];
#pragma unroll
            for (int nt = 0; nt < 4; nt++) {
                const int s0 = wn32 + nt * 8 + tig * 2;
                const int s1 = s0 + 1;
                const float As0 = sAcs[s0], As1 = sAcs[s1];
                const float d0 = sDt[s0], d1 = sDt[s1];
                float g00 = (s0 <= l0) ? accG[mt][nt][0] * expf(A0 - As0) * d0 : 0.f;
                float g01 = (s1 <= l0) ? accG[mt][nt][1] * expf(A0 - As1) * d1 : 0.f;
                float g10 = (s0 <= l1) ? accG[mt][nt][2] * expf(A1 - As0) * d0 : 0.f;
                float g11 = (s1 <= l1) ? accG[mt][nt][3] * expf(A1 - As1) * d1 : 0.f;
                uint32_t hp, lp;
                const uint32_t a0 = swz256(l0, s0 >> 3) + ((s0 & 7) << 1);
                split_pair(g00, g01, hp, lp);
                asm volatile("st.shared.b32 [%0], %1;" :: "r"(sb + Y_GH + a0), "r"(hp));
                asm volatile("st.shared.b32 [%0], %1;" :: "r"(sb + Y_GL + a0), "r"(lp));
                const uint32_t a1 = swz256(l1, s0 >> 3) + ((s0 & 7) << 1);
                split_pair(g10, g11, hp, lp);
                asm volatile("st.shared.b32 [%0], %1;" :: "r"(sb + Y_GH + a1), "r"(hp));
                asm volatile("st.shared.b32 [%0], %1;" :: "r"(sb + Y_GL + a1), "r"(lp));
            }
        }
    }

    __syncthreads();

    // -------- pass 2: Y += G' . X^T  (X = raw v) --------
#pragma unroll
    for (int ks = 0; ks < 8; ks++) {
        uint32_t ah[4][4], al[4][4], bh[4], bl[4];
        const int ag = 2 * ks + a_g;
        const int krb = ks * 16 + tB_kr;
#pragma unroll
        for (int mt = 0; mt < 4; mt++)
            ldsm_x4(ah[mt], sb + Y_GH + swz256(wm + mt * 16 + a_r, ag));
        ldsm_x4_t(bh, sb + Y_XH + swz128(krb, (wn16 >> 3) + tB_ng));
#pragma unroll
        for (int mt = 0; mt < 4; mt++)
#pragma unroll
            for (int nt = 0; nt < 2; nt++)
                mma16816(accY[mt][nt], ah[mt], bh[nt * 2], bh[nt * 2 + 1]);
#pragma unroll
        for (int mt = 0; mt < 4; mt++)
            ldsm_x4(al[mt], sb + Y_GL + swz256(wm + mt * 16 + a_r, ag));
#pragma unroll
        for (int mt = 0; mt < 4; mt++)
#pragma unroll
            for (int nt = 0; nt < 2; nt++)
                mma16816(accY[mt][nt], al[mt], bh[nt * 2], bh[nt * 2 + 1]);
        ldsm_x4_t(bl, sb + Y_XL + swz128(krb, (wn16 >> 3) + tB_ng));
#pragma unroll
        for (int mt = 0; mt < 4; mt++)
#pragma unroll
            for (int nt = 0; nt < 2; nt++)
                mma16816(accY[mt][nt], ah[mt], bl[nt * 2], bl[nt * 2 + 1]);
    }

#pragma unroll
    for (int mt = 0; mt < 4; mt++) {
        const int l0 = wm + mt * 16 + gid;
#pragma unroll
        for (int nt = 0; nt < 2; nt++) {
            const int p = wn16 + nt * 8 + tig * 2;
            const size_t y0 = ((size_t)b * LL + c * CHUNK + l0) * DD + h * PP + p;
            const size_t y1 = ((size_t)b * LL + c * CHUNK + l0 + 8) * DD + h * PP + p;
            *reinterpret_cast<float2*>(&g_y[y0]) = make_float2(accY[mt][nt][0], accY[mt][nt][1]);
            *reinterpret_cast<float2*>(&g_y[y1]) = make_float2(accY[mt][nt][2], accY[mt][nt][3]);
        }
    }
}

// ============================================================
// Pass D: RMSNorm + swish gate -> bf16 hi/lo; warp-per-row
// ============================================================
__global__ __launch_bounds__(256) void normgate_kernel(const float* __restrict__ gnorm_w) {
    const int r = blockIdx.x * 8 + (threadIdx.x >> 5);   // row = (b*L + l)*H + h
    const int lane = threadIdx.x & 31;
    const int h = r % HH;
    const size_t bl = (size_t)r / HH;
    const size_t yb = bl * DD + (size_t)h * PP;
    const float y0 = g_y[yb + lane];
    const float y1 = g_y[yb + lane + 32];
    float s = y0 * y0 + y1 * y1;
#pragma unroll
    for (int o = 16; o > 0; o >>= 1) s += __shfl_xor_sync(0xffffffffu, s, o);
    const float rms = rsqrtf(s / (float)PP + EPS);
    const size_t gb = bl * PROJ + CONV + (size_t)h * PP;
#pragma unroll
    for (int q = 0; q < 2; q++) {
        const int p = lane + q * 32;
        const float yv = (q == 0) ? y0 : y1;
        const float gv = g_proj[gb + p];
        const float out = yv * rms * gnorm_w[p] * (gv * sigmoidf_(gv));
        __nv_bfloat16 hi = __float2bfloat16(out);
        g_yhi[yb + p] = hi;
        g_ylo[yb + p] = __float2bfloat16(out - __bfloat162float(hi));
    }
}

// ============================================================
// launch
// ============================================================
extern "C" void kernel_launch(void* const* d_in, const int* in_sizes, int n_in,
                              void* d_out, int out_size) {
    const float* hidden   = (const float*)d_in[0];
    const float* W_vkqgdt = (const float*)d_in[1];
    const float* conv_w   = (const float*)d_in[2];
    const float* conv_b   = (const float*)d_in[3];
    const float* dt_bias  = (const float*)d_in[4];
    const float* A_logb   = (const float*)d_in[5];
    const float* gnorm_w  = (const float*)d_in[6];
    const float* W_o      = (const float*)d_in[7];
    float* out = (float*)d_out;

    float* proj_ptr;
    cudaGetSymbolAddress((void**)&proj_ptr, g_proj);
    __nv_bfloat16 *hhi, *hlo, *whi, *wlo, *ohi, *olo, *yhi, *ylo;
    cudaGetSymbolAddress((void**)&hhi, g_hhi);
    cudaGetSymbolAddress((void**)&hlo, g_hlo);
    cudaGetSymbolAddress((void**)&whi, g_whi);
    cudaGetSymbolAddress((void**)&wlo, g_wlo);
    cudaGetSymbolAddress((void**)&ohi, g_ohi);
    cudaGetSymbolAddress((void**)&olo, g_olo);
    cudaGetSymbolAddress((void**)&yhi, g_yhi);
    cudaGetSymbolAddress((void**)&ylo, g_ylo);

    cudaFuncSetAttribute(gemm_mma, cudaFuncAttributeMaxDynamicSharedMemorySize, GEMM_SMEM);
    cudaFuncSetAttribute(chunk_state_mma, cudaFuncAttributeMaxDynamicSharedMemorySize, CS_SMEM);
    cudaFuncSetAttribute(y_mma, cudaFuncAttributeMaxDynamicSharedMemorySize, Y_SMEM);

    // 0) split inputs
    {
        const int n4a = (BB * LL * DD) / 4;
        split_kernel<<<(n4a + 255) / 256, 256>>>(hidden, hhi, hlo, n4a);
        const int n4w = (PROJ * DD) / 4;
        split_kernel<<<(n4w + 255) / 256, 256>>>(W_vkqgdt, whi, wlo, n4w);
        const int n4o = (DD * DD) / 4;
        split_kernel<<<(n4o + 255) / 256, 256>>>(W_o, ohi, olo, n4o);
    }

    // 1) in-projection
    gemm_mma<<<dim3((PROJ + 127) / 128, (BB * LL) / 128), 256, GEMM_SMEM>>>(
        proj_ptr, hhi, hlo, whi, wlo, PROJ, DD);

    // 2) conv + silu (emits bf16 hi/lo), dt
    {
        const size_t tot = (size_t)BB * LL * CONV;
        conv_silu_kernel<<<(unsigned)((tot + 255) / 256), 256>>>(conv_w, conv_b);
        dt_kernel<<<(BB * LL * HH + 255) / 256, 256>>>(dt_bias, A_logb);
    }

    // 3) SSD (tensor-core)
    chunk_state_mma<<<dim3(HH, NC, BB), 128, CS_SMEM>>>();
    state_scan_kernel<<<BB * HH * 8, 256>>>();
    y_mma<<<dim3(HH, NC, BB), 256, Y_SMEM>>>();

    // 4) norm + gate (warp-per-row, emits bf16 hi/lo)
    normgate_kernel<<<BB * LL * HH / 8, 256>>>(gnorm_w);

    // 5) out-projection
    gemm_mma<<<dim3(DD / 128, (BB * LL) / 128), 256, GEMM_SMEM>>>(
        out, yhi, ylo, ohi, olo, DD, DD);
}

// round 15
// speedup vs baseline: 1.0553x; 1.0108x over previous
#include <cuda_runtime.h>
#include <cuda_bf16.h>
#include <math.h>
#include <stdint.h>

// ---------------- problem constants ----------------
#define BB      2
#define LL      2048
#define HH      32
#define KVH     8
#define PP      64
#define DD      2048           // HH*PP
#define CONV    3072           // (HH+2*KVH)*PP
#define PROJ    5152           // CONV + DD + HH
#define CHUNK   128
#define NC      16             // LL/CHUNK
#define EPS     1e-5f

// ---------------- scratch (device globals; no allocation allowed) ----------------
__device__ __align__(16) float g_proj[(size_t)BB * LL * PROJ];
__device__ __align__(16) float g_dt  [(size_t)BB * LL * HH];
__device__ __align__(16) float g_adt [(size_t)BB * LL * HH];
__device__ __align__(16) float g_acs [(size_t)BB * HH * NC * CHUNK];
__device__ __align__(16) float g_tot [(size_t)BB * HH * NC];
__device__ __align__(16) float g_states[(size_t)BB * NC * HH * PP * PP];
__device__ __align__(16) float g_y   [(size_t)BB * LL * DD];

// chunk-start states pre-split to bf16 hi/lo by the scan
__device__ __align__(16) __nv_bfloat16 g_shi[(size_t)BB * NC * HH * PP * PP];
__device__ __align__(16) __nv_bfloat16 g_slo[(size_t)BB * NC * HH * PP * PP];

// post-conv vkq stored directly as bf16 hi/lo
__device__ __align__(16) __nv_bfloat16 g_vkhi[(size_t)BB * LL * CONV], g_vklo[(size_t)BB * LL * CONV];

// split-precision bf16 operands for tensor-core GEMMs
__device__ __align__(16) __nv_bfloat16 g_hhi[(size_t)BB * LL * DD], g_hlo[(size_t)BB * LL * DD];
__device__ __align__(16) __nv_bfloat16 g_whi[(size_t)PROJ * DD],    g_wlo[(size_t)PROJ * DD];
__device__ __align__(16) __nv_bfloat16 g_ohi[(size_t)DD * DD],      g_olo[(size_t)DD * DD];
__device__ __align__(16) __nv_bfloat16 g_yhi[(size_t)BB * LL * DD], g_ylo[(size_t)BB * LL * DD];

// ---------------- helpers ----------------
__device__ __forceinline__ float sigmoidf_(float x) { return 1.f / (1.f + expf(-x)); }
__device__ __forceinline__ float softplusf_(float x) { return (x > 20.f) ? x : log1pf(expf(x)); }

__device__ __forceinline__ uint32_t smem_u32(const void* p) {
    uint32_t a;
    asm("{ .reg .u64 t; cvta.to.shared.u64 t, %1; cvt.u32.u64 %0, t; }" : "=r"(a) : "l"(p));
    return a;
}
__device__ __forceinline__ void cpa16(uint32_t dst, const void* src, int srcsize) {
    asm volatile("cp.async.cg.shared.global [%0], [%1], 16, %2;"
                 :: "r"(dst), "l"(src), "r"(srcsize));
}
__device__ __forceinline__ void cpa_commit() { asm volatile("cp.async.commit_group;"); }
template <int N> __device__ __forceinline__ void cpa_wait() {
    asm volatile("cp.async.wait_group %0;" :: "n"(N));
}
__device__ __forceinline__ void ldsm_x4(uint32_t* r, uint32_t a) {
    asm volatile("ldmatrix.sync.aligned.m8n8.x4.shared.b16 {%0,%1,%2,%3}, [%4];"
                 : "=r"(r[0]), "=r"(r[1]), "=r"(r[2]), "=r"(r[3]) : "r"(a));
}
__device__ __forceinline__ void ldsm_x4_t(uint32_t* r, uint32_t a) {
    asm volatile("ldmatrix.sync.aligned.m8n8.x4.trans.shared.b16 {%0,%1,%2,%3}, [%4];"
                 : "=r"(r[0]), "=r"(r[1]), "=r"(r[2]), "=r"(r[3]) : "r"(a));
}
__device__ __forceinline__ void mma16816(float* c, const uint32_t* a, uint32_t b0, uint32_t b1) {
    asm volatile("mma.sync.aligned.m16n8k16.row.col.f32.bf16.bf16.f32 "
                 "{%0,%1,%2,%3}, {%4,%5,%6,%7}, {%8,%9}, {%0,%1,%2,%3};"
                 : "+f"(c[0]), "+f"(c[1]), "+f"(c[2]), "+f"(c[3])
                 : "r"(a[0]), "r"(a[1]), "r"(a[2]), "r"(a[3]), "r"(b0), "r"(b1));
}
__device__ __forceinline__ void split_pair(float f0, float f1, uint32_t& hp, uint32_t& lp) {
    __nv_bfloat16 h0 = __float2bfloat16(f0);
    __nv_bfloat16 h1 = __float2bfloat16(f1);
    __nv_bfloat16 l0 = __float2bfloat16(f0 - __bfloat162float(h0));
    __nv_bfloat16 l1 = __float2bfloat16(f1 - __bfloat162float(h1));
    hp = (uint32_t)__bfloat16_as_ushort(h0) | ((uint32_t)__bfloat16_as_ushort(h1) << 16);
    lp = (uint32_t)__bfloat16_as_ushort(l0) | ((uint32_t)__bfloat16_as_ushort(l1) << 16);
}
// swizzles: rows of 128B (64 bf16) / 256B (128 bf16); 16B group permute
__device__ __forceinline__ uint32_t swz128(int r, int g) { return (uint32_t)(r * 128 + ((g ^ (r & 7)) << 4)); }
__device__ __forceinline__ uint32_t swz256(int r, int g) { return (uint32_t)(r * 256 + ((g ^ (r & 7)) << 4)); }

// reconstruct fp32 = hi + lo from bf16 pair source, scale, re-split to smem
__device__ __forceinline__ void split_row32_rec(uint32_t dH, uint32_t dL,
                                                const __nv_bfloat16* __restrict__ hsrc,
                                                const __nv_bfloat16* __restrict__ lsrc,
                                                int r, int c0, float scale) {
#pragma unroll
    for (int c = 0; c < 32; c += 8) {
        uint4 hv = *reinterpret_cast<const uint4*>(hsrc + c);
        uint4 lv = *reinterpret_cast<const uint4*>(lsrc + c);
        const uint32_t hw[4] = {hv.x, hv.y, hv.z, hv.w};
        const uint32_t lw[4] = {lv.x, lv.y, lv.z, lv.w};
        uint32_t hp[4], lp[4];
#pragma unroll
        for (int j = 0; j < 4; j++) {
            float f0 = __bfloat162float(__ushort_as_bfloat16((unsigned short)(hw[j] & 0xFFFF)))
                     + __bfloat162float(__ushort_as_bfloat16((unsigned short)(lw[j] & 0xFFFF)));
            float f1 = __bfloat162float(__ushort_as_bfloat16((unsigned short)(hw[j] >> 16)))
                     + __bfloat162float(__ushort_as_bfloat16((unsigned short)(lw[j] >> 16)));
            split_pair(f0 * scale, f1 * scale, hp[j], lp[j]);
        }
        const int col = c0 + c;     // multiple of 8
        const uint32_t a = swz128(r, col >> 3);
        asm volatile("st.shared.v4.b32 [%0], {%1,%2,%3,%4};"
                     :: "r"(dH + a), "r"(hp[0]), "r"(hp[1]), "r"(hp[2]), "r"(hp[3]));
        asm volatile("st.shared.v4.b32 [%0], {%1,%2,%3,%4};"
                     :: "r"(dL + a), "r"(lp[0]), "r"(lp[1]), "r"(lp[2]), "r"(lp[3]));
    }
}

// ============================================================
// fp32 -> (bf16 hi, bf16 lo) split, vectorized x4
// ============================================================
__global__ void split_kernel(const float* __restrict__ src,
                             __nv_bfloat16* __restrict__ hi,
                             __nv_bfloat16* __restrict__ lo, int n4) {
    const int i = blockIdx.x * blockDim.x + threadIdx.x;
    if (i >= n4) return;
    const float4 v = reinterpret_cast<const float4*>(src)[i];
    uint32_t h0, l0, h1, l1;
    split_pair(v.x, v.y, h0, l0);
    split_pair(v.z, v.w, h1, l1);
    reinterpret_cast<uint2*>(hi)[i] = make_uint2(h0, h1);
    reinterpret_cast<uint2*>(lo)[i] = make_uint2(l0, l1);
}

// ============================================================
// mma.sync bf16 split-precision GEMM (R7 passing config, frozen)
// ============================================================
#define TILE_BYTES 8192
#define STAGE_BYTES (4 * TILE_BYTES)
#define NSTAGE 3
#define GEMM_SMEM (NSTAGE * STAGE_BYTES)

__device__ __forceinline__ uint32_t sw_off(int r, int g) {
    return (uint32_t)(r * 64 + ((g ^ ((r >> 1) & 3)) << 4));
}

__device__ __forceinline__ void load_stage(
    uint32_t sb, const __nv_bfloat16* __restrict__ Ahi, const __nv_bfloat16* __restrict__ Alo,
    const __nv_bfloat16* __restrict__ Bhi, const __nv_bfloat16* __restrict__ Blo,
    int mBase, int nBase, int Nd, int Kd, int kBase, int tid) {
#pragma unroll
    for (int t = 0; t < 2; t++) {
        const int idx = tid + (t << 8);
        const int r = idx >> 2;
        const int g = idx & 3;
        const uint32_t off = sw_off(r, g);
        const size_t srcA = (size_t)(mBase + r) * Kd + kBase + g * 8;
        cpa16(sb + off, Ahi + srcA, 16);
        cpa16(sb + TILE_BYTES + off, Alo + srcA, 16);
        const int brow = nBase + r;
        const int ok = (brow < Nd) ? 16 : 0;
        const size_t srcB = (size_t)(ok ? brow : (Nd - 1)) * Kd + kBase + g * 8;
        cpa16(sb + 2 * TILE_BYTES + off, Bhi + srcB, ok);
        cpa16(sb + 3 * TILE_BYTES + off, Blo + srcB, ok);
    }
}

__global__ __launch_bounds__(256, 2) void gemm_mma(
    float* __restrict__ C,
    const __nv_bfloat16* __restrict__ Ahi, const __nv_bfloat16* __restrict__ Alo,
    const __nv_bfloat16* __restrict__ Bhi, const __nv_bfloat16* __restrict__ Blo,
    int Nd, int Kd) {
    extern __shared__ __align__(16) char dsm[];
    const int tid  = threadIdx.x;
    const int warp = tid >> 5;
    const int lane = tid & 31;
    const int mBase = blockIdx.y << 7;
    const int nBase = blockIdx.x << 7;
    const int wm = (warp >> 2) << 6;
    const int wn = (warp & 3) << 5;

    const uint32_t smem0 = smem_u32(dsm);

    float acc[4][4][4];
#pragma unroll
    for (int i = 0; i < 4; i++)
#pragma unroll
        for (int j = 0; j < 4; j++)
#pragma unroll
            for (int k = 0; k < 4; k++) acc[i][j][k] = 0.f;

    const int a_r = lane & 15;
    const int a_gsel = lane >> 4;
    const int b_r = (lane & 7) + ((lane & 16) >> 1);
    const int b_gsel = (lane >> 3) & 1;

    const int nk = Kd >> 5;
    load_stage(smem0, Ahi, Alo, Bhi, Blo, mBase, nBase, Nd, Kd, 0, tid);
    cpa_commit();
    load_stage(smem0 + STAGE_BYTES, Ahi, Alo, Bhi, Blo, mBase, nBase, Nd, Kd, 32, tid);
    cpa_commit();

    int bufc = 0;
    for (int s = 0; s < nk; s++) {
        if (s == nk - 1) cpa_wait<0>(); else cpa_wait<1>();
        __syncthreads();
        if (s + 2 < nk) {
            int bufn = bufc + 2; if (bufn >= NSTAGE) bufn -= NSTAGE;
            load_stage(smem0 + bufn * STAGE_BYTES, Ahi, Alo, Bhi, Blo,
                       mBase, nBase, Nd, Kd, (s + 2) << 5, tid);
            cpa_commit();
        }

        const uint32_t sb = smem0 + bufc * STAGE_BYTES;
        const uint32_t tAh = sb, tAl = sb + TILE_BYTES;
        const uint32_t tBh = sb + 2 * TILE_BYTES, tBl = sb + 3 * TILE_BYTES;

#pragma unroll
        for (int ks = 0; ks < 2; ks++) {
            uint32_t a[4][4], b[2][4];
            const int ag = 2 * ks + a_gsel;
            const int bg = 2 * ks + b_gsel;
#pragma unroll
            for (int mt = 0; mt < 4; mt++)
                ldsm_x4(a[mt], tAh + sw_off(wm + mt * 16 + a_r, ag));
#pragma unroll
            for (int p = 0; p < 2; p++)
                ldsm_x4(b[p], tBh + sw_off(wn + p * 16 + b_r, bg));
#pragma unroll
            for (int mt = 0; mt < 4; mt++)
#pragma unroll
                for (int nt = 0; nt < 4; nt++)
                    mma16816(acc[mt][nt], a[mt], b[nt >> 1][(nt & 1) * 2], b[nt >> 1][(nt & 1) * 2 + 1]);
#pragma unroll
            for (int p = 0; p < 2; p++)
                ldsm_x4(b[p], tBl + sw_off(wn + p * 16 + b_r, bg));
#pragma unroll
            for (int mt = 0; mt < 4; mt++)
#pragma unroll
                for (int nt = 0; nt < 4; nt++)
                    mma16816(acc[mt][nt], a[mt], b[nt >> 1][(nt & 1) * 2], b[nt >> 1][(nt & 1) * 2 + 1]);
#pragma unroll
            for (int mt = 0; mt < 4; mt++)
                ldsm_x4(a[mt], tAl + sw_off(wm + mt * 16 + a_r, ag));
#pragma unroll
            for (int p = 0; p < 2; p++)
                ldsm_x4(b[p], tBh + sw_off(wn + p * 16 + b_r, bg));
#pragma unroll
            for (int mt = 0; mt < 4; mt++)
#pragma unroll
                for (int nt = 0; nt < 4; nt++)
                    mma16816(acc[mt][nt], a[mt], b[nt >> 1][(nt & 1) * 2], b[nt >> 1][(nt & 1) * 2 + 1]);
        }
        if (++bufc == NSTAGE) bufc = 0;
    }

    const int gid = lane >> 2, tig = lane & 3;
#pragma unroll
    for (int mt = 0; mt < 4; mt++) {
        const int row0 = mBase + wm + mt * 16 + gid;
#pragma unroll
        for (int nt = 0; nt < 4; nt++) {
            const int col = nBase + wn + nt * 8 + tig * 2;
            if (col < Nd) {
                float2 v01 = make_float2(acc[mt][nt][0], acc[mt][nt][1]);
                float2 v23 = make_float2(acc[mt][nt][2], acc[mt][nt][3]);
                *reinterpret_cast<float2*>(C + (size_t)row0 * Nd + col) = v01;
                *reinterpret_cast<float2*>(C + (size_t)(row0 + 8) * Nd + col) = v23;
            }
        }
    }
}

// ============================================================
// Conv (kernel=2, causal) + SiLU -> bf16 hi/lo directly
// ============================================================
__global__ void conv_silu_kernel(const float* __restrict__ conv_w,
                                 const float* __restrict__ conv_b) {
    const size_t idx = (size_t)blockIdx.x * blockDim.x + threadIdx.x;
    if (idx >= (size_t)BB * LL * CONV) return;
    const int c = (int)(idx % CONV);
    const size_t bl = idx / CONV;
    const int l = (int)(bl % LL);
    const float cur = g_proj[bl * PROJ + c];
    const float prev = (l > 0) ? g_proj[(bl - 1) * PROJ + c] : 0.f;
    const float v = prev * conv_w[c * 2] + cur * conv_w[c * 2 + 1] + conv_b[c];
    const float o = v * sigmoidf_(v);
    __nv_bfloat16 hi = __float2bfloat16(o);
    g_vkhi[idx] = hi;
    g_vklo[idx] = __float2bfloat16(o - __bfloat162float(hi));
}

__global__ void dt_kernel(const float* __restrict__ dt_bias,
                          const float* __restrict__ A_log_bias) {
    const int idx = blockIdx.x * blockDim.x + threadIdx.x;
    if (idx >= BB * LL * HH) return;
    const int h = idx % HH;
    const size_t bl = idx / HH;
    const float raw = g_proj[bl * PROJ + (CONV + DD) + h];
    const float dtv = softplusf_(raw + dt_bias[h]);
    g_dt[idx] = dtv;
    g_adt[idx] = dtv * (-expf(A_log_bias[h]));
}

// ============================================================
// Pass A (mma): per-(b,c,h) parallel cumsum + local chunk state
// ============================================================
#define CS_KH   0
#define CS_KL   16384
#define CS_XH   32768
#define CS_XL   49152
#define CS_ACS  65536
#define CS_SMEM (65536 + 512)

__global__ __launch_bounds__(128) void chunk_state_mma() {
    extern __shared__ __align__(16) char dsm[];
    const uint32_t sb = smem_u32(dsm);
    float* sAcs = reinterpret_cast<float*>(dsm + CS_ACS);

    const int h = blockIdx.x, c = blockIdx.y, b = blockIdx.z;
    const int tid = threadIdx.x;
    const int kvh = h >> 2;

    // issue X tile loads immediately (overlap with cumsum)
    {
        const size_t rowbase = ((size_t)b * LL + c * CHUNK) * CONV + (size_t)kvh * PP;
        for (int i = tid; i < 1024; i += 128) {
            const int r = i >> 3, g = i & 7;
            const uint32_t d = swz128(r, g);
            const size_t s = rowbase + (size_t)r * CONV + g * 8;
            cpa16(sb + CS_XH + d, g_vkhi + s, 16);
            cpa16(sb + CS_XL + d, g_vklo + s, 16);
        }
        cpa_commit();
    }

    sAcs[tid] = g_adt[((size_t)b * LL + c * CHUNK + tid) * HH + h];
    __syncthreads();
    // Hillis-Steele inclusive scan over 128 elements
#pragma unroll
    for (int off = 1; off < CHUNK; off <<= 1) {
        const float v = sAcs[tid];
        const float u = (tid >= off) ? sAcs[tid - off] : 0.f;
        __syncthreads();
        sAcs[tid] = v + u;
        __syncthreads();
    }
    const float total = sAcs[CHUNK - 1];
    g_acs[(((size_t)b * HH + h) * NC + c) * CHUNK + tid] = sAcs[tid];
    if (tid == 0)
        g_tot[((size_t)b * HH + h) * NC + c] = total;

    // K tile: reconstruct + scale by w*dt + split
    {
        const int l = tid;
        const size_t base = ((size_t)b * LL + c * CHUNK + l) * CONV;
        const float w = expf(total - sAcs[l]);
        const float dtv = g_dt[((size_t)b * LL + c * CHUNK + l) * HH + h];
        const size_t ko = base + KVH * PP + kvh * PP;
        const float ws = w * dtv;
        split_row32_rec(sb + CS_KH, sb + CS_KL, g_vkhi + ko,      g_vklo + ko,      l, 0,  ws);
        split_row32_rec(sb + CS_KH, sb + CS_KL, g_vkhi + ko + 32, g_vklo + ko + 32, l, 32, ws);
    }
    cpa_wait<0>();
    __syncthreads();

    const int warp = tid >> 5, lane = tid & 31;
    const int wn = warp * 16;
    const int tA_kr = (lane & 7) + ((lane >> 4) & 1) * 8;
    const int tA_mg = (lane >> 3) & 1;
    const int tB_kr = (lane & 7) + ((lane >> 3) & 1) * 8;
    const int tB_ng = (lane >> 4) & 1;

    float acc[4][2][4];
#pragma unroll
    for (int i = 0; i < 4; i++)
#pragma unroll
        for (int j = 0; j < 2; j++)
#pragma unroll
            for (int k = 0; k < 4; k++) acc[i][j][k] = 0.f;

#pragma unroll
    for (int ks = 0; ks < 8; ks++) {
        const int kra = ks * 16 + tA_kr;
        const int krb = ks * 16 + tB_kr;
        uint32_t ah[4][4], al[4][4], bh[4], bl[4];
#pragma unroll
        for (int mt = 0; mt < 4; mt++)
            ldsm_x4_t(ah[mt], sb + CS_KH + swz128(kra, mt * 2 + tA_mg));
        ldsm_x4_t(bh, sb + CS_XH + swz128(krb, (wn >> 3) + tB_ng));
#pragma unroll
        for (int mt = 0; mt < 4; mt++)
#pragma unroll
            for (int nt = 0; nt < 2; nt++)
                mma16816(acc[mt][nt], ah[mt], bh[nt * 2], bh[nt * 2 + 1]);
#pragma unroll
        for (int mt = 0; mt < 4; mt++)
            ldsm_x4_t(al[mt], sb + CS_KL + swz128(kra, mt * 2 + tA_mg));
#pragma unroll
        for (int mt = 0; mt < 4; mt++)
#pragma unroll
            for (int nt = 0; nt < 2; nt++)
                mma16816(acc[mt][nt], al[mt], bh[nt * 2], bh[nt * 2 + 1]);
        ldsm_x4_t(bl, sb + CS_XL + swz128(krb, (wn >> 3) + tB_ng));
#pragma unroll
        for (int mt = 0; mt < 4; mt++)
#pragma unroll
            for (int nt = 0; nt < 2; nt++)
                mma16816(acc[mt][nt], ah[mt], bl[nt * 2], bl[nt * 2 + 1]);
    }

    const int gid = lane >> 2, tig = lane & 3;
    const size_t so = (((size_t)b * NC + c) * HH + h) * (PP * PP);
#pragma unroll
    for (int mt = 0; mt < 4; mt++) {
        const int n0 = mt * 16 + gid;
#pragma unroll
        for (int nt = 0; nt < 2; nt++) {
            const int p = wn + nt * 8 + tig * 2;
            *reinterpret_cast<float2*>(&g_states[so + (size_t)n0 * PP + p]) =
                make_float2(acc[mt][nt][0], acc[mt][nt][1]);
            *reinterpret_cast<float2*>(&g_states[so + (size_t)(n0 + 8) * PP + p]) =
                make_float2(acc[mt][nt][2], acc[mt][nt][3]);
        }
    }
}

// ============================================================
// Pass B: inter-chunk scan; emits chunk-start states as bf16 hi/lo
// ============================================================
__global__ void state_scan_kernel() {
    __shared__ float et[NC];
    const int bh = blockIdx.x >> 3;
    const int slab = blockIdx.x & 7;
    const int b = bh / HH, h = bh % HH;
    if (threadIdx.x < NC)
        et[threadIdx.x] = expf(g_tot[(size_t)bh * NC + threadIdx.x]);
    __syncthreads();
    const int e0 = slab * 512;
    for (int e = e0 + threadIdx.x; e < e0 + 512; e += blockDim.x) {
        float S = 0.f;
        for (int c = 0; c < NC; c++) {
            const size_t idx = (((size_t)b * NC + c) * HH + h) * (PP * PP) + e;
            const float loc = g_states[idx];
            const __nv_bfloat16 hi = __float2bfloat16(S);
            g_shi[idx] = hi;
            g_slo[idx] = __float2bfloat16(S - __bfloat162float(hi));
            S = et[c] * S + loc;
        }
    }
}

// ============================================================
// Pass C (mma): Y = (mask(C.B^T)·decay·dt) X + exp(Acs) C.S_start
// 512 threads, 16 warps (4m x 4n, warp tile 32x32/32x16): doubled
// latency hiding at 1 CTA/SM without extra smem or reg caps.
// ============================================================
#define Y_CH   0
#define Y_CL   16384
#define Y_BH   32768
#define Y_BL   49152
#define Y_XH   65536
#define Y_XL   81920
#define Y_SH   98304
#define Y_SL   106496
#define Y_GH   0            // overlays C (hi+lo)
#define Y_GL   32768        // overlays B (hi+lo)
#define Y_ACS  114688
#define Y_DT   (114688 + 512)
#define Y_SMEM (114688 + 1024 + 64)

__global__ __launch_bounds__(512) void y_mma() {
    extern __shared__ __align__(16) char dsm[];
    const uint32_t sb = smem_u32(dsm);
    float* sAcs = reinterpret_cast<float*>(dsm + Y_ACS);
    float* sDt  = reinterpret_cast<float*>(dsm + Y_DT);

    const int h = blockIdx.x, c = blockIdx.y, b = blockIdx.z;
    const int tid = threadIdx.x;
    const int kvh = h >> 2;

    // async tile loads: C, B, X, S hi/lo straight from bf16 arrays
    {
        const size_t rowbase = ((size_t)b * LL + c * CHUNK) * CONV;
        const uint32_t offC = 2 * KVH * PP + h * PP;
        const uint32_t offB = KVH * PP + kvh * PP;
        const uint32_t offX = kvh * PP;
        for (int i = tid; i < 1024; i += 512) {
            const int r = i >> 3, g = i & 7;
            const uint32_t d = swz128(r, g);
            const size_t s = rowbase + (size_t)r * CONV + g * 8;
            cpa16(sb + Y_CH + d, g_vkhi + s + offC, 16);
            cpa16(sb + Y_CL + d, g_vklo + s + offC, 16);
            cpa16(sb + Y_BH + d, g_vkhi + s + offB, 16);
            cpa16(sb + Y_BL + d, g_vklo + s + offB, 16);
            cpa16(sb + Y_XH + d, g_vkhi + s + offX, 16);
            cpa16(sb + Y_XL + d, g_vklo + s + offX, 16);
        }
        const size_t stbase = (((size_t)b * NC + c) * HH + h) * (PP * PP);
        if (tid < 512) {
            const int r = tid >> 3, g = tid & 7;    // r = n row 0..63
            const uint32_t d = swz128(r, g);
            const size_t s = stbase + (size_t)r * PP + g * 8;
            cpa16(sb + Y_SH + d, g_shi + s, 16);
            cpa16(sb + Y_SL + d, g_slo + s, 16);
        }
        cpa_commit();
    }

    if (tid < CHUNK) {
        sAcs[tid] = g_acs[(((size_t)b * HH + h) * NC + c) * CHUNK + tid];
        sDt[tid]  = g_dt[((size_t)b * LL + c * CHUNK + tid) * HH + h];
    }
    cpa_wait<0>();
    __syncthreads();

    const int warp = tid >> 5, lane = tid & 31;    // warp 0..15
    const int wm = (warp >> 2) * 32;               // m tile base (4 groups of 32)
    const int wn32 = (warp & 3) * 32;
    const int wn16 = (warp & 3) * 16;
    const int gid = lane >> 2, tig = lane & 3;

    const int a_r = lane & 15, a_g = lane >> 4;
    const int b_r = (lane & 7) + ((lane & 16) >> 1), b_g = (lane >> 3) & 1;
    const int tB_kr = (lane & 7) + ((lane >> 3) & 1) * 8;
    const int tB_ng = (lane >> 4) & 1;

    // -------- pass 1b FIRST: Yo = C . S^T --------
    float accY[2][2][4];
#pragma unroll
    for (int i = 0; i < 2; i++)
#pragma unroll
        for (int j = 0; j < 2; j++)
#pragma unroll
            for (int k = 0; k < 4; k++) accY[i][j][k] = 0.f;

#pragma unroll
    for (int ks = 0; ks < 4; ks++) {
        uint32_t ah[2][4], al[2][4], bh[4], bl[4];
        const int ag = 2 * ks + a_g;
        const int krb = ks * 16 + tB_kr;
#pragma unroll
        for (int mt = 0; mt < 2; mt++)
            ldsm_x4(ah[mt], sb + Y_CH + swz128(wm + mt * 16 + a_r, ag));
        ldsm_x4_t(bh, sb + Y_SH + swz128(krb, (wn16 >> 3) + tB_ng));
#pragma unroll
        for (int mt = 0; mt < 2; mt++)
#pragma unroll
            for (int nt = 0; nt < 2; nt++)
                mma16816(accY[mt][nt], ah[mt], bh[nt * 2], bh[nt * 2 + 1]);
#pragma unroll
        for (int mt = 0; mt < 2; mt++)
            ldsm_x4(al[mt], sb + Y_CL + swz128(wm + mt * 16 + a_r, ag));
#pragma unroll
        for (int mt = 0; mt < 2; mt++)
#pragma unroll
            for (int nt = 0; nt < 2; nt++)
                mma16816(accY[mt][nt], al[mt], bh[nt * 2], bh[nt * 2 + 1]);
        ldsm_x4_t(bl, sb + Y_SL + swz128(krb, (wn16 >> 3) + tB_ng));
#pragma unroll
        for (int mt = 0; mt < 2; mt++)
#pragma unroll
            for (int nt = 0; nt < 2; nt++)
                mma16816(accY[mt][nt], ah[mt], bl[nt * 2], bl[nt * 2 + 1]);
    }

#pragma unroll
    for (int mt = 0; mt < 2; mt++) {
        const float e0 = expf(sAcs[wm + mt * 16 + gid]);
        const float e1 = expf(sAcs[wm + mt * 16 + gid + 8]);
#pragma unroll
        for (int nt = 0; nt < 2; nt++) {
            accY[mt][nt][0] *= e0; accY[mt][nt][1] *= e0;
            accY[mt][nt][2] *= e1; accY[mt][nt][3] *= e1;
        }
    }

    // -------- pass 1a: G = C . Bt^T --------
    {
        float accG[2][4][4];
#pragma unroll
        for (int i = 0; i < 2; i++)
#pragma unroll
            for (int j = 0; j < 4; j++)
#pragma unroll
                for (int k = 0; k < 4; k++) accG[i][j][k] = 0.f;

#pragma unroll
        for (int ks = 0; ks < 4; ks++) {
            uint32_t ah[2][4], al[2][4], bh[2][4], bl[2][4];
            const int ag = 2 * ks + a_g, bg = 2 * ks + b_g;
#pragma unroll
            for (int mt = 0; mt < 2; mt++)
                ldsm_x4(ah[mt], sb + Y_CH + swz128(wm + mt * 16 + a_r, ag));
#pragma unroll
            for (int p = 0; p < 2; p++)
                ldsm_x4(bh[p], sb + Y_BH + swz128(wn32 + p * 16 + b_r, bg));
#pragma unroll
            for (int mt = 0; mt < 2; mt++)
#pragma unroll
                for (int nt = 0; nt < 4; nt++)
                    mma16816(accG[mt][nt], ah[mt], bh[nt >> 1][(nt & 1) * 2], bh[nt >> 1][(nt & 1) * 2 + 1]);
#pragma unroll
            for (int mt = 0; mt < 2; mt++)
                ldsm_x4(al[mt], sb + Y_CL + swz128(wm + mt * 16 + a_r, ag));
#pragma unroll
            for (int mt = 0; mt < 2; mt++)
#pragma unroll
                for (int nt = 0; nt < 4; nt++)
                    mma16816(accG[mt][nt], al[mt], bh[nt >> 1][(nt & 1) * 2], bh[nt >> 1][(nt & 1) * 2 + 1]);
#pragma unroll
            for (int p = 0; p < 2; p++)
                ldsm_x4(bl[p], sb + Y_BL + swz128(wn32 + p * 16 + b_r, bg));
#pragma unroll
            for (int mt = 0; mt < 2; mt++)
#pragma unroll
                for (int nt = 0; nt < 4; nt++)
                    mma16816(accG[mt][nt], ah[mt], bl[nt >> 1][(nt & 1) * 2], bl[nt >> 1][(nt & 1) * 2 + 1]);
        }

        __syncthreads();   // all warps done reading C/B before overlay

#pragma unroll
        for (int mt = 0; mt < 2; mt++) {
            const int l0 = wm + mt * 16 + gid;
            const int l1 = l0 + 8;
            const float A0 = sAcs[l0], A1 = sAcs[l1];
#pragma unroll
            for (int nt = 0; nt < 4; nt++) {
                const int s0 = wn32 + nt * 8 + tig * 2;
                const int s1 = s0 + 1;
                const float As0 = sAcs[s0], As1 = sAcs[s1];
                const float d0 = sDt[s0], d1 = sDt[s1];
                float g00 = (s0 <= l0) ? accG[mt][nt][0] * expf(A0 - As0) * d0 : 0.f;
                float g01 = (s1 <= l0) ? accG[mt][nt][1] * expf(A0 - As1) * d1 : 0.f;
                float g10 = (s0 <= l1) ? accG[mt][nt][2] * expf(A1 - As0) * d0 : 0.f;
                float g11 = (s1 <= l1) ? accG[mt][nt][3] * expf(A1 - As1) * d1 : 0.f;
                uint32_t hp, lp;
                const uint32_t a0 = swz256(l0, s0 >> 3) + ((s0 & 7) << 1);
                split_pair(g00, g01, hp, lp);
                asm volatile("st.shared.b32 [%0], %1;" :: "r"(sb + Y_GH + a0), "r"(hp));
                asm volatile("st.shared.b32 [%0], %1;" :: "r"(sb + Y_GL + a0), "r"(lp));
                const uint32_t a1 = swz256(l1, s0 >> 3) + ((s0 & 7) << 1);
                split_pair(g10, g11, hp, lp);
                asm volatile("st.shared.b32 [%0], %1;" :: "r"(sb + Y_GH + a1), "r"(hp));
                asm volatile("st.shared.b32 [%0], %1;" :: "r"(sb + Y_GL + a1), "r"(lp));
            }
        }
    }

    __syncthreads();

    // -------- pass 2: Y += G' . X^T  (X = raw v) --------
#pragma unroll
    for (int ks = 0; ks < 8; ks++) {
        uint32_t ah[2][4], al[2][4], bh[4], bl[4];
        const int ag = 2 * ks + a_g;
        const int krb = ks * 16 + tB_kr;
#pragma unroll
        for (int mt = 0; mt < 2; mt++)
            ldsm_x4(ah[mt], sb + Y_GH + swz256(wm + mt * 16 + a_r, ag));
        ldsm_x4_t(bh, sb + Y_XH + swz128(krb, (wn16 >> 3) + tB_ng));
#pragma unroll
        for (int mt = 0; mt < 2; mt++)
#pragma unroll
            for (int nt = 0; nt < 2; nt++)
                mma16816(accY[mt][nt], ah[mt], bh[nt * 2], bh[nt * 2 + 1]);
#pragma unroll
        for (int mt = 0; mt < 2; mt++)
            ldsm_x4(al[mt], sb + Y_GL + swz256(wm + mt * 16 + a_r, ag));
#pragma unroll
        for (int mt = 0; mt < 2; mt++)
#pragma unroll
            for (int nt = 0; nt < 2; nt++)
                mma16816(accY[mt][nt], al[mt], bh[nt * 2], bh[nt * 2 + 1]);
        ldsm_x4_t(bl, sb + Y_XL + swz128(krb, (wn16 >> 3) + tB_ng));
#pragma unroll
        for (int mt = 0; mt < 2; mt++)
#pragma unroll
            for (int nt = 0; nt < 2; nt++)
                mma16816(accY[mt][nt], ah[mt], bl[nt * 2], bl[nt * 2 + 1]);
    }

#pragma unroll
    for (int mt = 0; mt < 2; mt++) {
        const int l0 = wm + mt * 16 + gid;
#pragma unroll
        for (int nt = 0; nt < 2; nt++) {
            const int p = wn16 + nt * 8 + tig * 2;
            const size_t y0 = ((size_t)b * LL + c * CHUNK + l0) * DD + h * PP + p;
            const size_t y1 = ((size_t)b * LL + c * CHUNK + l0 + 8) * DD + h * PP + p;
            *reinterpret_cast<float2*>(&g_y[y0]) = make_float2(accY[mt][nt][0], accY[mt][nt][1]);
            *reinterpret_cast<float2*>(&g_y[y1]) = make_float2(accY[mt][nt][2], accY[mt][nt][3]);
        }
    }
}

// ============================================================
// Pass D: RMSNorm + swish gate -> bf16 hi/lo; warp-per-row
// ============================================================
__global__ __launch_bounds__(256) void normgate_kernel(const float* __restrict__ gnorm_w) {
    const int r = blockIdx.x * 8 + (threadIdx.x >> 5);   // row = (b*L + l)*H + h
    const int lane = threadIdx.x & 31;
    const int h = r % HH;
    const size_t bl = (size_t)r / HH;
    const size_t yb = bl * DD + (size_t)h * PP;
    const float y0 = g_y[yb + lane];
    const float y1 = g_y[yb + lane + 32];
    float s = y0 * y0 + y1 * y1;
#pragma unroll
    for (int o = 16; o > 0; o >>= 1) s += __shfl_xor_sync(0xffffffffu, s, o);
    const float rms = rsqrtf(s / (float)PP + EPS);
    const size_t gb = bl * PROJ + CONV + (size_t)h * PP;
#pragma unroll
    for (int q = 0; q < 2; q++) {
        const int p = lane + q * 32;
        const float yv = (q == 0) ? y0 : y1;
        const float gv = g_proj[gb + p];
        const float out = yv * rms * gnorm_w[p] * (gv * sigmoidf_(gv));
        __nv_bfloat16 hi = __float2bfloat16(out);
        g_yhi[yb + p] = hi;
        g_ylo[yb + p] = __float2bfloat16(out - __bfloat162float(hi));
    }
}

// ============================================================
// launch
// ============================================================
extern "C" void kernel_launch(void* const* d_in, const int* in_sizes, int n_in,
                              void* d_out, int out_size) {
    const float* hidden   = (const float*)d_in[0];
    const float* W_vkqgdt = (const float*)d_in[1];
    const float* conv_w   = (const float*)d_in[2];
    const float* conv_b   = (const float*)d_in[3];
    const float* dt_bias  = (const float*)d_in[4];
    const float* A_logb   = (const float*)d_in[5];
    const float* gnorm_w  = (const float*)d_in[6];
    const float* W_o      = (const float*)d_in[7];
    float* out = (float*)d_out;

    float* proj_ptr;
    cudaGetSymbolAddress((void**)&proj_ptr, g_proj);
    __nv_bfloat16 *hhi, *hlo, *whi, *wlo, *ohi, *olo, *yhi, *ylo;
    cudaGetSymbolAddress((void**)&hhi, g_hhi);
    cudaGetSymbolAddress((void**)&hlo, g_hlo);
    cudaGetSymbolAddress((void**)&whi, g_whi);
    cudaGetSymbolAddress((void**)&wlo, g_wlo);
    cudaGetSymbolAddress((void**)&ohi, g_ohi);
    cudaGetSymbolAddress((void**)&olo, g_olo);
    cudaGetSymbolAddress((void**)&yhi, g_yhi);
    cudaGetSymbolAddress((void**)&ylo, g_ylo);

    cudaFuncSetAttribute(gemm_mma, cudaFuncAttributeMaxDynamicSharedMemorySize, GEMM_SMEM);
    cudaFuncSetAttribute(chunk_state_mma, cudaFuncAttributeMaxDynamicSharedMemorySize, CS_SMEM);
    cudaFuncSetAttribute(y_mma, cudaFuncAttributeMaxDynamicSharedMemorySize, Y_SMEM);

    // 0) split inputs
    {
        const int n4a = (BB * LL * DD) / 4;
        split_kernel<<<(n4a + 255) / 256, 256>>>(hidden, hhi, hlo, n4a);
        const int n4w = (PROJ * DD) / 4;
        split_kernel<<<(n4w + 255) / 256, 256>>>(W_vkqgdt, whi, wlo, n4w);
        const int n4o = (DD * DD) / 4;
        split_kernel<<<(n4o + 255) / 256, 256>>>(W_o, ohi, olo, n4o);
    }

    // 1) in-projection
    gemm_mma<<<dim3((PROJ + 127) / 128, (BB * LL) / 128), 256, GEMM_SMEM>>>(
        proj_ptr, hhi, hlo, whi, wlo, PROJ, DD);

    // 2) conv + silu (emits bf16 hi/lo), dt
    {
        const size_t tot = (size_t)BB * LL * CONV;
        conv_silu_kernel<<<(unsigned)((tot + 255) / 256), 256>>>(conv_w, conv_b);
        dt_kernel<<<(BB * LL * HH + 255) / 256, 256>>>(dt_bias, A_logb);
    }

    // 3) SSD (tensor-core)
    chunk_state_mma<<<dim3(HH, NC, BB), 128, CS_SMEM>>>();
    state_scan_kernel<<<BB * HH * 8, 256>>>();
    y_mma<<<dim3(HH, NC, BB), 512, Y_SMEM>>>();

    // 4) norm + gate (warp-per-row, emits bf16 hi/lo)
    normgate_kernel<<<BB * LL * HH / 8, 256>>>(gnorm_w);

    // 5) out-projection
    gemm_mma<<<dim3(DD / 128, (BB * LL) / 128), 256, GEMM_SMEM>>>(
        out, yhi, ylo, ohi, olo, DD, DD);
}

// round 16
// speedup vs baseline: 1.0637x; 1.0080x over previous
#include <cuda_runtime.h>
#include <cuda_bf16.h>
#include <math.h>
#include <stdint.h>

// ---------------- problem constants ----------------
#define BB      2
#define LL      2048
#define HH      32
#define KVH     8
#define PP      64
#define DD      2048           // HH*PP
#define CONV    3072           // (HH+2*KVH)*PP
#define PROJ    5152           // CONV + DD + HH
#define CHUNK   128
#define NC      16             // LL/CHUNK
#define EPS     1e-5f

// ---------------- scratch (device globals; no allocation allowed) ----------------
__device__ __align__(16) float g_proj[(size_t)BB * LL * PROJ];
__device__ __align__(16) float g_dt  [(size_t)BB * LL * HH];
__device__ __align__(16) float g_adt [(size_t)BB * LL * HH];
__device__ __align__(16) float g_acs [(size_t)BB * HH * NC * CHUNK];
__device__ __align__(16) float g_tot [(size_t)BB * HH * NC];
__device__ __align__(16) float g_states[(size_t)BB * NC * HH * PP * PP];
__device__ __align__(16) float g_y   [(size_t)BB * LL * DD];

// chunk-start states pre-split to bf16 hi/lo by the scan
__device__ __align__(16) __nv_bfloat16 g_shi[(size_t)BB * NC * HH * PP * PP];
__device__ __align__(16) __nv_bfloat16 g_slo[(size_t)BB * NC * HH * PP * PP];

// post-conv vkq stored directly as bf16 hi/lo
__device__ __align__(16) __nv_bfloat16 g_vkhi[(size_t)BB * LL * CONV], g_vklo[(size_t)BB * LL * CONV];

// split-precision bf16 operands for tensor-core GEMMs
__device__ __align__(16) __nv_bfloat16 g_hhi[(size_t)BB * LL * DD], g_hlo[(size_t)BB * LL * DD];
__device__ __align__(16) __nv_bfloat16 g_whi[(size_t)PROJ * DD],    g_wlo[(size_t)PROJ * DD];
__device__ __align__(16) __nv_bfloat16 g_ohi[(size_t)DD * DD],      g_olo[(size_t)DD * DD];
__device__ __align__(16) __nv_bfloat16 g_yhi[(size_t)BB * LL * DD], g_ylo[(size_t)BB * LL * DD];

// ---------------- helpers ----------------
__device__ __forceinline__ float sigmoidf_(float x) { return 1.f / (1.f + expf(-x)); }
__device__ __forceinline__ float softplusf_(float x) { return (x > 20.f) ? x : log1pf(expf(x)); }

__device__ __forceinline__ uint32_t smem_u32(const void* p) {
    uint32_t a;
    asm("{ .reg .u64 t; cvta.to.shared.u64 t, %1; cvt.u32.u64 %0, t; }" : "=r"(a) : "l"(p));
    return a;
}
__device__ __forceinline__ void cpa16(uint32_t dst, const void* src, int srcsize) {
    asm volatile("cp.async.cg.shared.global [%0], [%1], 16, %2;"
                 :: "r"(dst), "l"(src), "r"(srcsize));
}
__device__ __forceinline__ void cpa_commit() { asm volatile("cp.async.commit_group;"); }
template <int N> __device__ __forceinline__ void cpa_wait() {
    asm volatile("cp.async.wait_group %0;" :: "n"(N));
}
__device__ __forceinline__ void ldsm_x4(uint32_t* r, uint32_t a) {
    asm volatile("ldmatrix.sync.aligned.m8n8.x4.shared.b16 {%0,%1,%2,%3}, [%4];"
                 : "=r"(r[0]), "=r"(r[1]), "=r"(r[2]), "=r"(r[3]) : "r"(a));
}
__device__ __forceinline__ void ldsm_x4_t(uint32_t* r, uint32_t a) {
    asm volatile("ldmatrix.sync.aligned.m8n8.x4.trans.shared.b16 {%0,%1,%2,%3}, [%4];"
                 : "=r"(r[0]), "=r"(r[1]), "=r"(r[2]), "=r"(r[3]) : "r"(a));
}
__device__ __forceinline__ void mma16816(float* c, const uint32_t* a, uint32_t b0, uint32_t b1) {
    asm volatile("mma.sync.aligned.m16n8k16.row.col.f32.bf16.bf16.f32 "
                 "{%0,%1,%2,%3}, {%4,%5,%6,%7}, {%8,%9}, {%0,%1,%2,%3};"
                 : "+f"(c[0]), "+f"(c[1]), "+f"(c[2]), "+f"(c[3])
                 : "r"(a[0]), "r"(a[1]), "r"(a[2]), "r"(a[3]), "r"(b0), "r"(b1));
}
__device__ __forceinline__ void split_pair(float f0, float f1, uint32_t& hp, uint32_t& lp) {
    __nv_bfloat16 h0 = __float2bfloat16(f0);
    __nv_bfloat16 h1 = __float2bfloat16(f1);
    __nv_bfloat16 l0 = __float2bfloat16(f0 - __bfloat162float(h0));
    __nv_bfloat16 l1 = __float2bfloat16(f1 - __bfloat162float(h1));
    hp = (uint32_t)__bfloat16_as_ushort(h0) | ((uint32_t)__bfloat16_as_ushort(h1) << 16);
    lp = (uint32_t)__bfloat16_as_ushort(l0) | ((uint32_t)__bfloat16_as_ushort(l1) << 16);
}
// swizzles: rows of 128B (64 bf16) / 256B (128 bf16); 16B group permute
__device__ __forceinline__ uint32_t swz128(int r, int g) { return (uint32_t)(r * 128 + ((g ^ (r & 7)) << 4)); }
__device__ __forceinline__ uint32_t swz256(int r, int g) { return (uint32_t)(r * 256 + ((g ^ (r & 7)) << 4)); }

// reconstruct fp32 = hi + lo from bf16 pair source, scale, re-split to smem
__device__ __forceinline__ void split_row32_rec(uint32_t dH, uint32_t dL,
                                                const __nv_bfloat16* __restrict__ hsrc,
                                                const __nv_bfloat16* __restrict__ lsrc,
                                                int r, int c0, float scale) {
#pragma unroll
    for (int c = 0; c < 32; c += 8) {
        uint4 hv = *reinterpret_cast<const uint4*>(hsrc + c);
        uint4 lv = *reinterpret_cast<const uint4*>(lsrc + c);
        const uint32_t hw[4] = {hv.x, hv.y, hv.z, hv.w};
        const uint32_t lw[4] = {lv.x, lv.y, lv.z, lv.w};
        uint32_t hp[4], lp[4];
#pragma unroll
        for (int j = 0; j < 4; j++) {
            float f0 = __bfloat162float(__ushort_as_bfloat16((unsigned short)(hw[j] & 0xFFFF)))
                     + __bfloat162float(__ushort_as_bfloat16((unsigned short)(lw[j] & 0xFFFF)));
            float f1 = __bfloat162float(__ushort_as_bfloat16((unsigned short)(hw[j] >> 16)))
                     + __bfloat162float(__ushort_as_bfloat16((unsigned short)(lw[j] >> 16)));
            split_pair(f0 * scale, f1 * scale, hp[j], lp[j]);
        }
        const int col = c0 + c;     // multiple of 8
        const uint32_t a = swz128(r, col >> 3);
        asm volatile("st.shared.v4.b32 [%0], {%1,%2,%3,%4};"
                     :: "r"(dH + a), "r"(hp[0]), "r"(hp[1]), "r"(hp[2]), "r"(hp[3]));
        asm volatile("st.shared.v4.b32 [%0], {%1,%2,%3,%4};"
                     :: "r"(dL + a), "r"(lp[0]), "r"(lp[1]), "r"(lp[2]), "r"(lp[3]));
    }
}

// ============================================================
// fp32 -> (bf16 hi, bf16 lo) split, vectorized x4
// ============================================================
__global__ void split_kernel(const float* __restrict__ src,
                             __nv_bfloat16* __restrict__ hi,
                             __nv_bfloat16* __restrict__ lo, int n4) {
    const int i = blockIdx.x * blockDim.x + threadIdx.x;
    if (i >= n4) return;
    const float4 v = reinterpret_cast<const float4*>(src)[i];
    uint32_t h0, l0, h1, l1;
    split_pair(v.x, v.y, h0, l0);
    split_pair(v.z, v.w, h1, l1);
    reinterpret_cast<uint2*>(hi)[i] = make_uint2(h0, h1);
    reinterpret_cast<uint2*>(lo)[i] = make_uint2(l0, l1);
}

// ============================================================
// mma.sync bf16 split-precision GEMM (R7 passing config, frozen)
// ============================================================
#define TILE_BYTES 8192
#define STAGE_BYTES (4 * TILE_BYTES)
#define NSTAGE 3
#define GEMM_SMEM (NSTAGE * STAGE_BYTES)

__device__ __forceinline__ uint32_t sw_off(int r, int g) {
    return (uint32_t)(r * 64 + ((g ^ ((r >> 1) & 3)) << 4));
}

__device__ __forceinline__ void load_stage(
    uint32_t sb, const __nv_bfloat16* __restrict__ Ahi, const __nv_bfloat16* __restrict__ Alo,
    const __nv_bfloat16* __restrict__ Bhi, const __nv_bfloat16* __restrict__ Blo,
    int mBase, int nBase, int Nd, int Kd, int kBase, int tid) {
#pragma unroll
    for (int t = 0; t < 2; t++) {
        const int idx = tid + (t << 8);
        const int r = idx >> 2;
        const int g = idx & 3;
        const uint32_t off = sw_off(r, g);
        const size_t srcA = (size_t)(mBase + r) * Kd + kBase + g * 8;
        cpa16(sb + off, Ahi + srcA, 16);
        cpa16(sb + TILE_BYTES + off, Alo + srcA, 16);
        const int brow = nBase + r;
        const int ok = (brow < Nd) ? 16 : 0;
        const size_t srcB = (size_t)(ok ? brow : (Nd - 1)) * Kd + kBase + g * 8;
        cpa16(sb + 2 * TILE_BYTES + off, Bhi + srcB, ok);
        cpa16(sb + 3 * TILE_BYTES + off, Blo + srcB, ok);
    }
}

__global__ __launch_bounds__(256, 2) void gemm_mma(
    float* __restrict__ C,
    const __nv_bfloat16* __restrict__ Ahi, const __nv_bfloat16* __restrict__ Alo,
    const __nv_bfloat16* __restrict__ Bhi, const __nv_bfloat16* __restrict__ Blo,
    int Nd, int Kd) {
    extern __shared__ __align__(16) char dsm[];
    const int tid  = threadIdx.x;
    const int warp = tid >> 5;
    const int lane = tid & 31;
    const int mBase = blockIdx.y << 7;
    const int nBase = blockIdx.x << 7;
    const int wm = (warp >> 2) << 6;
    const int wn = (warp & 3) << 5;

    const uint32_t smem0 = smem_u32(dsm);

    float acc[4][4][4];
#pragma unroll
    for (int i = 0; i < 4; i++)
#pragma unroll
        for (int j = 0; j < 4; j++)
#pragma unroll
            for (int k = 0; k < 4; k++) acc[i][j][k] = 0.f;

    const int a_r = lane & 15;
    const int a_gsel = lane >> 4;
    const int b_r = (lane & 7) + ((lane & 16) >> 1);
    const int b_gsel = (lane >> 3) & 1;

    const int nk = Kd >> 5;
    load_stage(smem0, Ahi, Alo, Bhi, Blo, mBase, nBase, Nd, Kd, 0, tid);
    cpa_commit();
    load_stage(smem0 + STAGE_BYTES, Ahi, Alo, Bhi, Blo, mBase, nBase, Nd, Kd, 32, tid);
    cpa_commit();

    int bufc = 0;
    for (int s = 0; s < nk; s++) {
        if (s == nk - 1) cpa_wait<0>(); else cpa_wait<1>();
        __syncthreads();
        if (s + 2 < nk) {
            int bufn = bufc + 2; if (bufn >= NSTAGE) bufn -= NSTAGE;
            load_stage(smem0 + bufn * STAGE_BYTES, Ahi, Alo, Bhi, Blo,
                       mBase, nBase, Nd, Kd, (s + 2) << 5, tid);
            cpa_commit();
        }

        const uint32_t sb = smem0 + bufc * STAGE_BYTES;
        const uint32_t tAh = sb, tAl = sb + TILE_BYTES;
        const uint32_t tBh = sb + 2 * TILE_BYTES, tBl = sb + 3 * TILE_BYTES;

#pragma unroll
        for (int ks = 0; ks < 2; ks++) {
            uint32_t a[4][4], b[2][4];
            const int ag = 2 * ks + a_gsel;
            const int bg = 2 * ks + b_gsel;
#pragma unroll
            for (int mt = 0; mt < 4; mt++)
                ldsm_x4(a[mt], tAh + sw_off(wm + mt * 16 + a_r, ag));
#pragma unroll
            for (int p = 0; p < 2; p++)
                ldsm_x4(b[p], tBh + sw_off(wn + p * 16 + b_r, bg));
#pragma unroll
            for (int mt = 0; mt < 4; mt++)
#pragma unroll
                for (int nt = 0; nt < 4; nt++)
                    mma16816(acc[mt][nt], a[mt], b[nt >> 1][(nt & 1) * 2], b[nt >> 1][(nt & 1) * 2 + 1]);
#pragma unroll
            for (int p = 0; p < 2; p++)
                ldsm_x4(b[p], tBl + sw_off(wn + p * 16 + b_r, bg));
#pragma unroll
            for (int mt = 0; mt < 4; mt++)
#pragma unroll
                for (int nt = 0; nt < 4; nt++)
                    mma16816(acc[mt][nt], a[mt], b[nt >> 1][(nt & 1) * 2], b[nt >> 1][(nt & 1) * 2 + 1]);
#pragma unroll
            for (int mt = 0; mt < 4; mt++)
                ldsm_x4(a[mt], tAl + sw_off(wm + mt * 16 + a_r, ag));
#pragma unroll
            for (int p = 0; p < 2; p++)
                ldsm_x4(b[p], tBh + sw_off(wn + p * 16 + b_r, bg));
#pragma unroll
            for (int mt = 0; mt < 4; mt++)
#pragma unroll
                for (int nt = 0; nt < 4; nt++)
                    mma16816(acc[mt][nt], a[mt], b[nt >> 1][(nt & 1) * 2], b[nt >> 1][(nt & 1) * 2 + 1]);
        }
        if (++bufc == NSTAGE) bufc = 0;
    }

    const int gid = lane >> 2, tig = lane & 3;
#pragma unroll
    for (int mt = 0; mt < 4; mt++) {
        const int row0 = mBase + wm + mt * 16 + gid;
#pragma unroll
        for (int nt = 0; nt < 4; nt++) {
            const int col = nBase + wn + nt * 8 + tig * 2;
            if (col < Nd) {
                float2 v01 = make_float2(acc[mt][nt][0], acc[mt][nt][1]);
                float2 v23 = make_float2(acc[mt][nt][2], acc[mt][nt][3]);
                *reinterpret_cast<float2*>(C + (size_t)row0 * Nd + col) = v01;
                *reinterpret_cast<float2*>(C + (size_t)(row0 + 8) * Nd + col) = v23;
            }
        }
    }
}

// ============================================================
// Conv (kernel=2, causal) + SiLU -> bf16 hi/lo directly
// ============================================================
__global__ void conv_silu_kernel(const float* __restrict__ conv_w,
                                 const float* __restrict__ conv_b) {
    const size_t idx = (size_t)blockIdx.x * blockDim.x + threadIdx.x;
    if (idx >= (size_t)BB * LL * CONV) return;
    const int c = (int)(idx % CONV);
    const size_t bl = idx / CONV;
    const int l = (int)(bl % LL);
    const float cur = g_proj[bl * PROJ + c];
    const float prev = (l > 0) ? g_proj[(bl - 1) * PROJ + c] : 0.f;
    const float v = prev * conv_w[c * 2] + cur * conv_w[c * 2 + 1] + conv_b[c];
    const float o = v * sigmoidf_(v);
    __nv_bfloat16 hi = __float2bfloat16(o);
    g_vkhi[idx] = hi;
    g_vklo[idx] = __float2bfloat16(o - __bfloat162float(hi));
}

__global__ void dt_kernel(const float* __restrict__ dt_bias,
                          const float* __restrict__ A_log_bias) {
    const int idx = blockIdx.x * blockDim.x + threadIdx.x;
    if (idx >= BB * LL * HH) return;
    const int h = idx % HH;
    const size_t bl = idx / HH;
    const float raw = g_proj[bl * PROJ + (CONV + DD) + h];
    const float dtv = softplusf_(raw + dt_bias[h]);
    g_dt[idx] = dtv;
    g_adt[idx] = dtv * (-expf(A_log_bias[h]));
}

// ============================================================
// Pass A (mma): per-(b,c,h) parallel cumsum + local chunk state
// 256 threads, 8 warps (2 n-halves x 4 p-groups, warp tile 32x16).
// ============================================================
#define CS_KH   0
#define CS_KL   16384
#define CS_XH   32768
#define CS_XL   49152
#define CS_ACS  65536
#define CS_SMEM (65536 + 512)

__global__ __launch_bounds__(256) void chunk_state_mma() {
    extern __shared__ __align__(16) char dsm[];
    const uint32_t sb = smem_u32(dsm);
    float* sAcs = reinterpret_cast<float*>(dsm + CS_ACS);

    const int h = blockIdx.x, c = blockIdx.y, b = blockIdx.z;
    const int tid = threadIdx.x;
    const int kvh = h >> 2;

    // issue X tile loads immediately (overlap with cumsum)
    {
        const size_t rowbase = ((size_t)b * LL + c * CHUNK) * CONV + (size_t)kvh * PP;
        for (int i = tid; i < 1024; i += 256) {
            const int r = i >> 3, g = i & 7;
            const uint32_t d = swz128(r, g);
            const size_t s = rowbase + (size_t)r * CONV + g * 8;
            cpa16(sb + CS_XH + d, g_vkhi + s, 16);
            cpa16(sb + CS_XL + d, g_vklo + s, 16);
        }
        cpa_commit();
    }

    if (tid < CHUNK)
        sAcs[tid] = g_adt[((size_t)b * LL + c * CHUNK + tid) * HH + h];
    __syncthreads();
    // Hillis-Steele inclusive scan over 128 elements (all threads hit barriers)
#pragma unroll
    for (int off = 1; off < CHUNK; off <<= 1) {
        float v = 0.f, u = 0.f;
        if (tid < CHUNK) {
            v = sAcs[tid];
            u = (tid >= off) ? sAcs[tid - off] : 0.f;
        }
        __syncthreads();
        if (tid < CHUNK) sAcs[tid] = v + u;
        __syncthreads();
    }
    const float total = sAcs[CHUNK - 1];
    if (tid < CHUNK)
        g_acs[(((size_t)b * HH + h) * NC + c) * CHUNK + tid] = sAcs[tid];
    if (tid == 0)
        g_tot[((size_t)b * HH + h) * NC + c] = total;

    // K tile: reconstruct + scale by w*dt + split; half-row per thread
    {
        const int l = tid >> 1;
        const int c0 = (tid & 1) * 32;
        const size_t base = ((size_t)b * LL + c * CHUNK + l) * CONV;
        const float w = expf(total - sAcs[l]);
        const float dtv = g_dt[((size_t)b * LL + c * CHUNK + l) * HH + h];
        const size_t ko = base + KVH * PP + kvh * PP + c0;
        const float ws = w * dtv;
        split_row32_rec(sb + CS_KH, sb + CS_KL, g_vkhi + ko, g_vklo + ko, l, c0, ws);
    }
    cpa_wait<0>();
    __syncthreads();

    const int warp = tid >> 5, lane = tid & 31;     // warp 0..7
    const int wM = (warp >> 2);                     // n-half 0/1 (32 rows each)
    const int wn = (warp & 3) * 16;                 // p tile base
    const int tA_kr = (lane & 7) + ((lane >> 4) & 1) * 8;
    const int tA_mg = (lane >> 3) & 1;
    const int tB_kr = (lane & 7) + ((lane >> 3) & 1) * 8;
    const int tB_ng = (lane >> 4) & 1;

    float acc[2][2][4];
#pragma unroll
    for (int i = 0; i < 2; i++)
#pragma unroll
        for (int j = 0; j < 2; j++)
#pragma unroll
            for (int k = 0; k < 4; k++) acc[i][j][k] = 0.f;

#pragma unroll
    for (int ks = 0; ks < 8; ks++) {
        const int kra = ks * 16 + tA_kr;
        const int krb = ks * 16 + tB_kr;
        uint32_t ah[2][4], al[2][4], bh[4], bl[4];
#pragma unroll
        for (int mt = 0; mt < 2; mt++)
            ldsm_x4_t(ah[mt], sb + CS_KH + swz128(kra, wM * 4 + mt * 2 + tA_mg));
        ldsm_x4_t(bh, sb + CS_XH + swz128(krb, (wn >> 3) + tB_ng));
#pragma unroll
        for (int mt = 0; mt < 2; mt++)
#pragma unroll
            for (int nt = 0; nt < 2; nt++)
                mma16816(acc[mt][nt], ah[mt], bh[nt * 2], bh[nt * 2 + 1]);
#pragma unroll
        for (int mt = 0; mt < 2; mt++)
            ldsm_x4_t(al[mt], sb + CS_KL + swz128(kra, wM * 4 + mt * 2 + tA_mg));
#pragma unroll
        for (int mt = 0; mt < 2; mt++)
#pragma unroll
            for (int nt = 0; nt < 2; nt++)
                mma16816(acc[mt][nt], al[mt], bh[nt * 2], bh[nt * 2 + 1]);
        ldsm_x4_t(bl, sb + CS_XL + swz128(krb, (wn >> 3) + tB_ng));
#pragma unroll
        for (int mt = 0; mt < 2; mt++)
#pragma unroll
            for (int nt = 0; nt < 2; nt++)
                mma16816(acc[mt][nt], ah[mt], bl[nt * 2], bl[nt * 2 + 1]);
    }

    const int gid = lane >> 2, tig = lane & 3;
    const size_t so = (((size_t)b * NC + c) * HH + h) * (PP * PP);
#pragma unroll
    for (int mt = 0; mt < 2; mt++) {
        const int n0 = wM * 32 + mt * 16 + gid;
#pragma unroll
        for (int nt = 0; nt < 2; nt++) {
            const int p = wn + nt * 8 + tig * 2;
            *reinterpret_cast<float2*>(&g_states[so + (size_t)n0 * PP + p]) =
                make_float2(acc[mt][nt][0], acc[mt][nt][1]);
            *reinterpret_cast<float2*>(&g_states[so + (size_t)(n0 + 8) * PP + p]) =
                make_float2(acc[mt][nt][2], acc[mt][nt][3]);
        }
    }
}

// ============================================================
// Pass B: inter-chunk scan; emits chunk-start states as bf16 hi/lo
// ============================================================
__global__ void state_scan_kernel() {
    __shared__ float et[NC];
    const int bh = blockIdx.x >> 3;
    const int slab = blockIdx.x & 7;
    const int b = bh / HH, h = bh % HH;
    if (threadIdx.x < NC)
        et[threadIdx.x] = expf(g_tot[(size_t)bh * NC + threadIdx.x]);
    __syncthreads();
    const int e0 = slab * 512;
    for (int e = e0 + threadIdx.x; e < e0 + 512; e += blockDim.x) {
        float S = 0.f;
        for (int c = 0; c < NC; c++) {
            const size_t idx = (((size_t)b * NC + c) * HH + h) * (PP * PP) + e;
            const float loc = g_states[idx];
            const __nv_bfloat16 hi = __float2bfloat16(S);
            g_shi[idx] = hi;
            g_slo[idx] = __float2bfloat16(S - __bfloat162float(hi));
            S = et[c] * S + loc;
        }
    }
}

// ============================================================
// Pass C (mma): Y = (mask(C.B^T)·decay·dt) X + exp(Acs) C.S_start
// 512 threads, 16 warps (R15 passing config).
// ============================================================
#define Y_CH   0
#define Y_CL   16384
#define Y_BH   32768
#define Y_BL   49152
#define Y_XH   65536
#define Y_XL   81920
#define Y_SH   98304
#define Y_SL   106496
#define Y_GH   0            // overlays C (hi+lo)
#define Y_GL   32768        // overlays B (hi+lo)
#define Y_ACS  114688
#define Y_DT   (114688 + 512)
#define Y_SMEM (114688 + 1024 + 64)

__global__ __launch_bounds__(512) void y_mma() {
    extern __shared__ __align__(16) char dsm[];
    const uint32_t sb = smem_u32(dsm);
    float* sAcs = reinterpret_cast<float*>(dsm + Y_ACS);
    float* sDt  = reinterpret_cast<float*>(dsm + Y_DT);

    const int h = blockIdx.x, c = blockIdx.y, b = blockIdx.z;
    const int tid = threadIdx.x;
    const int kvh = h >> 2;

    // async tile loads: C, B, X, S hi/lo straight from bf16 arrays
    {
        const size_t rowbase = ((size_t)b * LL + c * CHUNK) * CONV;
        const uint32_t offC = 2 * KVH * PP + h * PP;
        const uint32_t offB = KVH * PP + kvh * PP;
        const uint32_t offX = kvh * PP;
        for (int i = tid; i < 1024; i += 512) {
            const int r = i >> 3, g = i & 7;
            const uint32_t d = swz128(r, g);
            const size_t s = rowbase + (size_t)r * CONV + g * 8;
            cpa16(sb + Y_CH + d, g_vkhi + s + offC, 16);
            cpa16(sb + Y_CL + d, g_vklo + s + offC, 16);
            cpa16(sb + Y_BH + d, g_vkhi + s + offB, 16);
            cpa16(sb + Y_BL + d, g_vklo + s + offB, 16);
            cpa16(sb + Y_XH + d, g_vkhi + s + offX, 16);
            cpa16(sb + Y_XL + d, g_vklo + s + offX, 16);
        }
        const size_t stbase = (((size_t)b * NC + c) * HH + h) * (PP * PP);
        if (tid < 512) {
            const int r = tid >> 3, g = tid & 7;    // r = n row 0..63
            const uint32_t d = swz128(r, g);
            const size_t s = stbase + (size_t)r * PP + g * 8;
            cpa16(sb + Y_SH + d, g_shi + s, 16);
            cpa16(sb + Y_SL + d, g_slo + s, 16);
        }
        cpa_commit();
    }

    if (tid < CHUNK) {
        sAcs[tid] = g_acs[(((size_t)b * HH + h) * NC + c) * CHUNK + tid];
        sDt[tid]  = g_dt[((size_t)b * LL + c * CHUNK + tid) * HH + h];
    }
    cpa_wait<0>();
    __syncthreads();

    const int warp = tid >> 5, lane = tid & 31;    // warp 0..15
    const int wm = (warp >> 2) * 32;               // m tile base (4 groups of 32)
    const int wn32 = (warp & 3) * 32;
    const int wn16 = (warp & 3) * 16;
    const int gid = lane >> 2, tig = lane & 3;

    const int a_r = lane & 15, a_g = lane >> 4;
    const int b_r = (lane & 7) + ((lane & 16) >> 1), b_g = (lane >> 3) & 1;
    const int tB_kr = (lane & 7) + ((lane >> 3) & 1) * 8;
    const int tB_ng = (lane >> 4) & 1;

    // -------- pass 1b FIRST: Yo = C . S^T --------
    float accY[2][2][4];
#pragma unroll
    for (int i = 0; i < 2; i++)
#pragma unroll
        for (int j = 0; j < 2; j++)
#pragma unroll
            for (int k = 0; k < 4; k++) accY[i][j][k] = 0.f;

#pragma unroll
    for (int ks = 0; ks < 4; ks++) {
        uint32_t ah[2][4], al[2][4], bh[4], bl[4];
        const int ag = 2 * ks + a_g;
        const int krb = ks * 16 + tB_kr;
#pragma unroll
        for (int mt = 0; mt < 2; mt++)
            ldsm_x4(ah[mt], sb + Y_CH + swz128(wm + mt * 16 + a_r, ag));
        ldsm_x4_t(bh, sb + Y_SH + swz128(krb, (wn16 >> 3) + tB_ng));
#pragma unroll
        for (int mt = 0; mt < 2; mt++)
#pragma unroll
            for (int nt = 0; nt < 2; nt++)
                mma16816(accY[mt][nt], ah[mt], bh[nt * 2], bh[nt * 2 + 1]);
#pragma unroll
        for (int mt = 0; mt < 2; mt++)
            ldsm_x4(al[mt], sb + Y_CL + swz128(wm + mt * 16 + a_r, ag));
#pragma unroll
        for (int mt = 0; mt < 2; mt++)
#pragma unroll
            for (int nt = 0; nt < 2; nt++)
                mma16816(accY[mt][nt], al[mt], bh[nt * 2], bh[nt * 2 + 1]);
        ldsm_x4_t(bl, sb + Y_SL + swz128(krb, (wn16 >> 3) + tB_ng));
#pragma unroll
        for (int mt = 0; mt < 2; mt++)
#pragma unroll
            for (int nt = 0; nt < 2; nt++)
                mma16816(accY[mt][nt], ah[mt], bl[nt * 2], bl[nt * 2 + 1]);
    }

#pragma unroll
    for (int mt = 0; mt < 2; mt++) {
        const float e0 = expf(sAcs[wm + mt * 16 + gid]);
        const float e1 = expf(sAcs[wm + mt * 16 + gid + 8]);
#pragma unroll
        for (int nt = 0; nt < 2; nt++) {
            accY[mt][nt][0] *= e0; accY[mt][nt][1] *= e0;
            accY[mt][nt][2] *= e1; accY[mt][nt][3] *= e1;
        }
    }

    // -------- pass 1a: G = C . Bt^T --------
    {
        float accG[2][4][4];
#pragma unroll
        for (int i = 0; i < 2; i++)
#pragma unroll
            for (int j = 0; j < 4; j++)
#pragma unroll
                for (int k = 0; k < 4; k++) accG[i][j][k] = 0.f;

#pragma unroll
        for (int ks = 0; ks < 4; ks++) {
            uint32_t ah[2][4], al[2][4], bh[2][4], bl[2][4];
            const int ag = 2 * ks + a_g, bg = 2 * ks + b_g;
#pragma unroll
            for (int mt = 0; mt < 2; mt++)
                ldsm_x4(ah[mt], sb + Y_CH + swz128(wm + mt * 16 + a_r, ag));
#pragma unroll
            for (int p = 0; p < 2; p++)
                ldsm_x4(bh[p], sb + Y_BH + swz128(wn32 + p * 16 + b_r, bg));
#pragma unroll
            for (int mt = 0; mt < 2; mt++)
#pragma unroll
                for (int nt = 0; nt < 4; nt++)
                    mma16816(accG[mt][nt], ah[mt], bh[nt >> 1][(nt & 1) * 2], bh[nt >> 1][(nt & 1) * 2 + 1]);
#pragma unroll
            for (int mt = 0; mt < 2; mt++)
                ldsm_x4(al[mt], sb + Y_CL + swz128(wm + mt * 16 + a_r, ag));
#pragma unroll
            for (int mt = 0; mt < 2; mt++)
#pragma unroll
                for (int nt = 0; nt < 4; nt++)
                    mma16816(accG[mt][nt], al[mt], bh[nt >> 1][(nt & 1) * 2], bh[nt >> 1][(nt & 1) * 2 + 1]);
#pragma unroll
            for (int p = 0; p < 2; p++)
                ldsm_x4(bl[p], sb + Y_BL + swz128(wn32 + p * 16 + b_r, bg));
#pragma unroll
            for (int mt = 0; mt < 2; mt++)
#pragma unroll
                for (int nt = 0; nt < 4; nt++)
                    mma16816(accG[mt][nt], ah[mt], bl[nt >> 1][(nt & 1) * 2], bl[nt >> 1][(nt & 1) * 2 + 1]);
        }

        __syncthreads();   // all warps done reading C/B before overlay

#pragma unroll
        for (int mt = 0; mt < 2; mt++) {
            const int l0 = wm + mt * 16 + gid;
            const int l1 = l0 + 8;
            const float A0 = sAcs[l0], A1 = sAcs[l1];
#pragma unroll
            for (int nt = 0; nt < 4; nt++) {
                const int s0 = wn32 + nt * 8 + tig * 2;
                const int s1 = s0 + 1;
                const float As0 = sAcs[s0], As1 = sAcs[s1];
                const float d0 = sDt[s0], d1 = sDt[s1];
                float g00 = (s0 <= l0) ? accG[mt][nt][0] * expf(A0 - As0) * d0 : 0.f;
                float g01 = (s1 <= l0) ? accG[mt][nt][1] * expf(A0 - As1) * d1 : 0.f;
                float g10 = (s0 <= l1) ? accG[mt][nt][2] * expf(A1 - As0) * d0 : 0.f;
                float g11 = (s1 <= l1) ? accG[mt][nt][3] * expf(A1 - As1) * d1 : 0.f;
                uint32_t hp, lp;
                const uint32_t a0 = swz256(l0, s0 >> 3) + ((s0 & 7) << 1);
                split_pair(g00, g01, hp, lp);
                asm volatile("st.shared.b32 [%0], %1;" :: "r"(sb + Y_GH + a0), "r"(hp));
                asm volatile("st.shared.b32 [%0], %1;" :: "r"(sb + Y_GL + a0), "r"(lp));
                const uint32_t a1 = swz256(l1, s0 >> 3) + ((s0 & 7) << 1);
                split_pair(g10, g11, hp, lp);
                asm volatile("st.shared.b32 [%0], %1;" :: "r"(sb + Y_GH + a1), "r"(hp));
                asm volatile("st.shared.b32 [%0], %1;" :: "r"(sb + Y_GL + a1), "r"(lp));
            }
        }
    }

    __syncthreads();

    // -------- pass 2: Y += G' . X^T  (X = raw v) --------
#pragma unroll
    for (int ks = 0; ks < 8; ks++) {
        uint32_t ah[2][4], al[2][4], bh[4], bl[4];
        const int ag = 2 * ks + a_g;
        const int krb = ks * 16 + tB_kr;
#pragma unroll
        for (int mt = 0; mt < 2; mt++)
            ldsm_x4(ah[mt], sb + Y_GH + swz256(wm + mt * 16 + a_r, ag));
        ldsm_x4_t(bh, sb + Y_XH + swz128(krb, (wn16 >> 3) + tB_ng));
#pragma unroll
        for (int mt = 0; mt < 2; mt++)
#pragma unroll
            for (int nt = 0; nt < 2; nt++)
                mma16816(accY[mt][nt], ah[mt], bh[nt * 2], bh[nt * 2 + 1]);
#pragma unroll
        for (int mt = 0; mt < 2; mt++)
            ldsm_x4(al[mt], sb + Y_GL + swz256(wm + mt * 16 + a_r, ag));
#pragma unroll
        for (int mt = 0; mt < 2; mt++)
#pragma unroll
            for (int nt = 0; nt < 2; nt++)
                mma16816(accY[mt][nt], al[mt], bh[nt * 2], bh[nt * 2 + 1]);
        ldsm_x4_t(bl, sb + Y_XL + swz128(krb, (wn16 >> 3) + tB_ng));
#pragma unroll
        for (int mt = 0; mt < 2; mt++)
#pragma unroll
            for (int nt = 0; nt < 2; nt++)
                mma16816(accY[mt][nt], ah[mt], bl[nt * 2], bl[nt * 2 + 1]);
    }

#pragma unroll
    for (int mt = 0; mt < 2; mt++) {
        const int l0 = wm + mt * 16 + gid;
#pragma unroll
        for (int nt = 0; nt < 2; nt++) {
            const int p = wn16 + nt * 8 + tig * 2;
            const size_t y0 = ((size_t)b * LL + c * CHUNK + l0) * DD + h * PP + p;
            const size_t y1 = ((size_t)b * LL + c * CHUNK + l0 + 8) * DD + h * PP + p;
            *reinterpret_cast<float2*>(&g_y[y0]) = make_float2(accY[mt][nt][0], accY[mt][nt][1]);
            *reinterpret_cast<float2*>(&g_y[y1]) = make_float2(accY[mt][nt][2], accY[mt][nt][3]);
        }
    }
}

// ============================================================
// Pass D: RMSNorm + swish gate -> bf16 hi/lo; warp-per-row
// ============================================================
__global__ __launch_bounds__(256) void normgate_kernel(const float* __restrict__ gnorm_w) {
    const int r = blockIdx.x * 8 + (threadIdx.x >> 5);   // row = (b*L + l)*H + h
    const int lane = threadIdx.x & 31;
    const int h = r % HH;
    const size_t bl = (size_t)r / HH;
    const size_t yb = bl * DD + (size_t)h * PP;
    const float y0 = g_y[yb + lane];
    const float y1 = g_y[yb + lane + 32];
    float s = y0 * y0 + y1 * y1;
#pragma unroll
    for (int o = 16; o > 0; o >>= 1) s += __shfl_xor_sync(0xffffffffu, s, o);
    const float rms = rsqrtf(s / (float)PP + EPS);
    const size_t gb = bl * PROJ + CONV + (size_t)h * PP;
#pragma unroll
    for (int q = 0; q < 2; q++) {
        const int p = lane + q * 32;
        const float yv = (q == 0) ? y0 : y1;
        const float gv = g_proj[gb + p];
        const float out = yv * rms * gnorm_w[p] * (gv * sigmoidf_(gv));
        __nv_bfloat16 hi = __float2bfloat16(out);
        g_yhi[yb + p] = hi;
        g_ylo[yb + p] = __float2bfloat16(out - __bfloat162float(hi));
    }
}

// ============================================================
// launch
// ============================================================
extern "C" void kernel_launch(void* const* d_in, const int* in_sizes, int n_in,
                              void* d_out, int out_size) {
    const float* hidden   = (const float*)d_in[0];
    const float* W_vkqgdt = (const float*)d_in[1];
    const float* conv_w   = (const float*)d_in[2];
    const float* conv_b   = (const float*)d_in[3];
    const float* dt_bias  = (const float*)d_in[4];
    const float* A_logb   = (const float*)d_in[5];
    const float* gnorm_w  = (const float*)d_in[6];
    const float* W_o      = (const float*)d_in[7];
    float* out = (float*)d_out;

    float* proj_ptr;
    cudaGetSymbolAddress((void**)&proj_ptr, g_proj);
    __nv_bfloat16 *hhi, *hlo, *whi, *wlo, *ohi, *olo, *yhi, *ylo;
    cudaGetSymbolAddress((void**)&hhi, g_hhi);
    cudaGetSymbolAddress((void**)&hlo, g_hlo);
    cudaGetSymbolAddress((void**)&whi, g_whi);
    cudaGetSymbolAddress((void**)&wlo, g_wlo);
    cudaGetSymbolAddress((void**)&ohi, g_ohi);
    cudaGetSymbolAddress((void**)&olo, g_olo);
    cudaGetSymbolAddress((void**)&yhi, g_yhi);
    cudaGetSymbolAddress((void**)&ylo, g_ylo);

    cudaFuncSetAttribute(gemm_mma, cudaFuncAttributeMaxDynamicSharedMemorySize, GEMM_SMEM);
    cudaFuncSetAttribute(chunk_state_mma, cudaFuncAttributeMaxDynamicSharedMemorySize, CS_SMEM);
    cudaFuncSetAttribute(y_mma, cudaFuncAttributeMaxDynamicSharedMemorySize, Y_SMEM);

    // 0) split inputs
    {
        const int n4a = (BB * LL * DD) / 4;
        split_kernel<<<(n4a + 255) / 256, 256>>>(hidden, hhi, hlo, n4a);
        const int n4w = (PROJ * DD) / 4;
        split_kernel<<<(n4w + 255) / 256, 256>>>(W_vkqgdt, whi, wlo, n4w);
        const int n4o = (DD * DD) / 4;
        split_kernel<<<(n4o + 255) / 256, 256>>>(W_o, ohi, olo, n4o);
    }

    // 1) in-projection
    gemm_mma<<<dim3((PROJ + 127) / 128, (BB * LL) / 128), 256, GEMM_SMEM>>>(
        proj_ptr, hhi, hlo, whi, wlo, PROJ, DD);

    // 2) conv + silu (emits bf16 hi/lo), dt
    {
        const size_t tot = (size_t)BB * LL * CONV;
        conv_silu_kernel<<<(unsigned)((tot + 255) / 256), 256>>>(conv_w, conv_b);
        dt_kernel<<<(BB * LL * HH + 255) / 256, 256>>>(dt_bias, A_logb);
    }

    // 3) SSD (tensor-core)
    chunk_state_mma<<<dim3(HH, NC, BB), 256, CS_SMEM>>>();
    state_scan_kernel<<<BB * HH * 8, 256>>>();
    y_mma<<<dim3(HH, NC, BB), 512, Y_SMEM>>>();

    // 4) norm + gate (warp-per-row, emits bf16 hi/lo)
    normgate_kernel<<<BB * LL * HH / 8, 256>>>(gnorm_w);

    // 5) out-projection
    gemm_mma<<<dim3(DD / 128, (BB * LL) / 128), 256, GEMM_SMEM>>>(
        out, yhi, ylo, ohi, olo, DD, DD);
}

// round 17
// speedup vs baseline: 1.0911x; 1.0257x over previous
#include <cuda_runtime.h>
#include <cuda_bf16.h>
#include <math.h>
#include <stdint.h>

// ---------------- problem constants ----------------
#define BB      2
#define LL      2048
#define HH      32
#define KVH     8
#define PP      64
#define DD      2048           // HH*PP
#define CONV    3072           // (HH+2*KVH)*PP
#define PROJ    5152           // CONV + DD + HH
#define CHUNK   128
#define NC      16             // LL/CHUNK
#define EPS     1e-5f

// ---------------- scratch (device globals; no allocation allowed) ----------------
__device__ __align__(16) float g_proj[(size_t)BB * LL * PROJ];
__device__ __align__(16) float g_dt  [(size_t)BB * LL * HH];
__device__ __align__(16) float g_adt [(size_t)BB * LL * HH];
__device__ __align__(16) float g_acs [(size_t)BB * HH * NC * CHUNK];
__device__ __align__(16) float g_tot [(size_t)BB * HH * NC];
__device__ __align__(16) float g_states[(size_t)BB * NC * HH * PP * PP];
__device__ __align__(16) float g_y   [(size_t)BB * LL * DD];

// chunk-start states pre-split to bf16 hi/lo by the scan
__device__ __align__(16) __nv_bfloat16 g_shi[(size_t)BB * NC * HH * PP * PP];
__device__ __align__(16) __nv_bfloat16 g_slo[(size_t)BB * NC * HH * PP * PP];

// post-conv vkq stored directly as bf16 hi/lo
__device__ __align__(16) __nv_bfloat16 g_vkhi[(size_t)BB * LL * CONV], g_vklo[(size_t)BB * LL * CONV];

// split-precision bf16 operands for tensor-core GEMMs
__device__ __align__(16) __nv_bfloat16 g_hhi[(size_t)BB * LL * DD], g_hlo[(size_t)BB * LL * DD];
__device__ __align__(16) __nv_bfloat16 g_whi[(size_t)PROJ * DD],    g_wlo[(size_t)PROJ * DD];
__device__ __align__(16) __nv_bfloat16 g_ohi[(size_t)DD * DD],      g_olo[(size_t)DD * DD];
__device__ __align__(16) __nv_bfloat16 g_yhi[(size_t)BB * LL * DD], g_ylo[(size_t)BB * LL * DD];

// ---------------- helpers ----------------
__device__ __forceinline__ float sigmoidf_(float x) { return 1.f / (1.f + expf(-x)); }
__device__ __forceinline__ float softplusf_(float x) { return (x > 20.f) ? x : log1pf(expf(x)); }

__device__ __forceinline__ uint32_t smem_u32(const void* p) {
    uint32_t a;
    asm("{ .reg .u64 t; cvta.to.shared.u64 t, %1; cvt.u32.u64 %0, t; }" : "=r"(a) : "l"(p));
    return a;
}
__device__ __forceinline__ void cpa16(uint32_t dst, const void* src, int srcsize) {
    asm volatile("cp.async.cg.shared.global [%0], [%1], 16, %2;"
                 :: "r"(dst), "l"(src), "r"(srcsize));
}
__device__ __forceinline__ void cpa_commit() { asm volatile("cp.async.commit_group;"); }
template <int N> __device__ __forceinline__ void cpa_wait() {
    asm volatile("cp.async.wait_group %0;" :: "n"(N));
}
__device__ __forceinline__ void ldsm_x4(uint32_t* r, uint32_t a) {
    asm volatile("ldmatrix.sync.aligned.m8n8.x4.shared.b16 {%0,%1,%2,%3}, [%4];"
                 : "=r"(r[0]), "=r"(r[1]), "=r"(r[2]), "=r"(r[3]) : "r"(a));
}
__device__ __forceinline__ void ldsm_x4_t(uint32_t* r, uint32_t a) {
    asm volatile("ldmatrix.sync.aligned.m8n8.x4.trans.shared.b16 {%0,%1,%2,%3}, [%4];"
                 : "=r"(r[0]), "=r"(r[1]), "=r"(r[2]), "=r"(r[3]) : "r"(a));
}
__device__ __forceinline__ void mma16816(float* c, const uint32_t* a, uint32_t b0, uint32_t b1) {
    asm volatile("mma.sync.aligned.m16n8k16.row.col.f32.bf16.bf16.f32 "
                 "{%0,%1,%2,%3}, {%4,%5,%6,%7}, {%8,%9}, {%0,%1,%2,%3};"
                 : "+f"(c[0]), "+f"(c[1]), "+f"(c[2]), "+f"(c[3])
                 : "r"(a[0]), "r"(a[1]), "r"(a[2]), "r"(a[3]), "r"(b0), "r"(b1));
}
__device__ __forceinline__ void split_pair(float f0, float f1, uint32_t& hp, uint32_t& lp) {
    __nv_bfloat16 h0 = __float2bfloat16(f0);
    __nv_bfloat16 h1 = __float2bfloat16(f1);
    __nv_bfloat16 l0 = __float2bfloat16(f0 - __bfloat162float(h0));
    __nv_bfloat16 l1 = __float2bfloat16(f1 - __bfloat162float(h1));
    hp = (uint32_t)__bfloat16_as_ushort(h0) | ((uint32_t)__bfloat16_as_ushort(h1) << 16);
    lp = (uint32_t)__bfloat16_as_ushort(l0) | ((uint32_t)__bfloat16_as_ushort(l1) << 16);
}
// swizzles: rows of 128B (64 bf16) / 256B (128 bf16); 16B group permute
__device__ __forceinline__ uint32_t swz128(int r, int g) { return (uint32_t)(r * 128 + ((g ^ (r & 7)) << 4)); }
__device__ __forceinline__ uint32_t swz256(int r, int g) { return (uint32_t)(r * 256 + ((g ^ (r & 7)) << 4)); }

// reconstruct fp32 = hi + lo from bf16 pair source, scale, re-split to smem
__device__ __forceinline__ void split_row32_rec(uint32_t dH, uint32_t dL,
                                                const __nv_bfloat16* __restrict__ hsrc,
                                                const __nv_bfloat16* __restrict__ lsrc,
                                                int r, int c0, float scale) {
#pragma unroll
    for (int c = 0; c < 32; c += 8) {
        uint4 hv = *reinterpret_cast<const uint4*>(hsrc + c);
        uint4 lv = *reinterpret_cast<const uint4*>(lsrc + c);
        const uint32_t hw[4] = {hv.x, hv.y, hv.z, hv.w};
        const uint32_t lw[4] = {lv.x, lv.y, lv.z, lv.w};
        uint32_t hp[4], lp[4];
#pragma unroll
        for (int j = 0; j < 4; j++) {
            float f0 = __bfloat162float(__ushort_as_bfloat16((unsigned short)(hw[j] & 0xFFFF)))
                     + __bfloat162float(__ushort_as_bfloat16((unsigned short)(lw[j] & 0xFFFF)));
            float f1 = __bfloat162float(__ushort_as_bfloat16((unsigned short)(hw[j] >> 16)))
                     + __bfloat162float(__ushort_as_bfloat16((unsigned short)(lw[j] >> 16)));
            split_pair(f0 * scale, f1 * scale, hp[j], lp[j]);
        }
        const int col = c0 + c;     // multiple of 8
        const uint32_t a = swz128(r, col >> 3);
        asm volatile("st.shared.v4.b32 [%0], {%1,%2,%3,%4};"
                     :: "r"(dH + a), "r"(hp[0]), "r"(hp[1]), "r"(hp[2]), "r"(hp[3]));
        asm volatile("st.shared.v4.b32 [%0], {%1,%2,%3,%4};"
                     :: "r"(dL + a), "r"(lp[0]), "r"(lp[1]), "r"(lp[2]), "r"(lp[3]));
    }
}

// ============================================================
// fp32 -> (bf16 hi, bf16 lo) split, vectorized x4
// ============================================================
__global__ void split_kernel(const float* __restrict__ src,
                             __nv_bfloat16* __restrict__ hi,
                             __nv_bfloat16* __restrict__ lo, int n4) {
    const int i = blockIdx.x * blockDim.x + threadIdx.x;
    if (i >= n4) return;
    const float4 v = reinterpret_cast<const float4*>(src)[i];
    uint32_t h0, l0, h1, l1;
    split_pair(v.x, v.y, h0, l0);
    split_pair(v.z, v.w, h1, l1);
    reinterpret_cast<uint2*>(hi)[i] = make_uint2(h0, h1);
    reinterpret_cast<uint2*>(lo)[i] = make_uint2(l0, l1);
}

// ============================================================
// mma.sync bf16 split-precision GEMM (R7 passing config, frozen)
// ============================================================
#define TILE_BYTES 8192
#define STAGE_BYTES (4 * TILE_BYTES)
#define NSTAGE 3
#define GEMM_SMEM (NSTAGE * STAGE_BYTES)

__device__ __forceinline__ uint32_t sw_off(int r, int g) {
    return (uint32_t)(r * 64 + ((g ^ ((r >> 1) & 3)) << 4));
}

__device__ __forceinline__ void load_stage(
    uint32_t sb, const __nv_bfloat16* __restrict__ Ahi, const __nv_bfloat16* __restrict__ Alo,
    const __nv_bfloat16* __restrict__ Bhi, const __nv_bfloat16* __restrict__ Blo,
    int mBase, int nBase, int Nd, int Kd, int kBase, int tid) {
#pragma unroll
    for (int t = 0; t < 2; t++) {
        const int idx = tid + (t << 8);
        const int r = idx >> 2;
        const int g = idx & 3;
        const uint32_t off = sw_off(r, g);
        const size_t srcA = (size_t)(mBase + r) * Kd + kBase + g * 8;
        cpa16(sb + off, Ahi + srcA, 16);
        cpa16(sb + TILE_BYTES + off, Alo + srcA, 16);
        const int brow = nBase + r;
        const int ok = (brow < Nd) ? 16 : 0;
        const size_t srcB = (size_t)(ok ? brow : (Nd - 1)) * Kd + kBase + g * 8;
        cpa16(sb + 2 * TILE_BYTES + off, Bhi + srcB, ok);
        cpa16(sb + 3 * TILE_BYTES + off, Blo + srcB, ok);
    }
}

__global__ __launch_bounds__(256, 2) void gemm_mma(
    float* __restrict__ C,
    const __nv_bfloat16* __restrict__ Ahi, const __nv_bfloat16* __restrict__ Alo,
    const __nv_bfloat16* __restrict__ Bhi, const __nv_bfloat16* __restrict__ Blo,
    int Nd, int Kd) {
    extern __shared__ __align__(16) char dsm[];
    const int tid  = threadIdx.x;
    const int warp = tid >> 5;
    const int lane = tid & 31;
    const int mBase = blockIdx.y << 7;
    const int nBase = blockIdx.x << 7;
    const int wm = (warp >> 2) << 6;
    const int wn = (warp & 3) << 5;

    const uint32_t smem0 = smem_u32(dsm);

    float acc[4][4][4];
#pragma unroll
    for (int i = 0; i < 4; i++)
#pragma unroll
        for (int j = 0; j < 4; j++)
#pragma unroll
            for (int k = 0; k < 4; k++) acc[i][j][k] = 0.f;

    const int a_r = lane & 15;
    const int a_gsel = lane >> 4;
    const int b_r = (lane & 7) + ((lane & 16) >> 1);
    const int b_gsel = (lane >> 3) & 1;

    const int nk = Kd >> 5;
    load_stage(smem0, Ahi, Alo, Bhi, Blo, mBase, nBase, Nd, Kd, 0, tid);
    cpa_commit();
    load_stage(smem0 + STAGE_BYTES, Ahi, Alo, Bhi, Blo, mBase, nBase, Nd, Kd, 32, tid);
    cpa_commit();

    int bufc = 0;
    for (int s = 0; s < nk; s++) {
        if (s == nk - 1) cpa_wait<0>(); else cpa_wait<1>();
        __syncthreads();
        if (s + 2 < nk) {
            int bufn = bufc + 2; if (bufn >= NSTAGE) bufn -= NSTAGE;
            load_stage(smem0 + bufn * STAGE_BYTES, Ahi, Alo, Bhi, Blo,
                       mBase, nBase, Nd, Kd, (s + 2) << 5, tid);
            cpa_commit();
        }

        const uint32_t sb = smem0 + bufc * STAGE_BYTES;
        const uint32_t tAh = sb, tAl = sb + TILE_BYTES;
        const uint32_t tBh = sb + 2 * TILE_BYTES, tBl = sb + 3 * TILE_BYTES;

#pragma unroll
        for (int ks = 0; ks < 2; ks++) {
            uint32_t a[4][4], b[2][4];
            const int ag = 2 * ks + a_gsel;
            const int bg = 2 * ks + b_gsel;
#pragma unroll
            for (int mt = 0; mt < 4; mt++)
                ldsm_x4(a[mt], tAh + sw_off(wm + mt * 16 + a_r, ag));
#pragma unroll
            for (int p = 0; p < 2; p++)
                ldsm_x4(b[p], tBh + sw_off(wn + p * 16 + b_r, bg));
#pragma unroll
            for (int mt = 0; mt < 4; mt++)
#pragma unroll
                for (int nt = 0; nt < 4; nt++)
                    mma16816(acc[mt][nt], a[mt], b[nt >> 1][(nt & 1) * 2], b[nt >> 1][(nt & 1) * 2 + 1]);
#pragma unroll
            for (int p = 0; p < 2; p++)
                ldsm_x4(b[p], tBl + sw_off(wn + p * 16 + b_r, bg));
#pragma unroll
            for (int mt = 0; mt < 4; mt++)
#pragma unroll
                for (int nt = 0; nt < 4; nt++)
                    mma16816(acc[mt][nt], a[mt], b[nt >> 1][(nt & 1) * 2], b[nt >> 1][(nt & 1) * 2 + 1]);
#pragma unroll
            for (int mt = 0; mt < 4; mt++)
                ldsm_x4(a[mt], tAl + sw_off(wm + mt * 16 + a_r, ag));
#pragma unroll
            for (int p = 0; p < 2; p++)
                ldsm_x4(b[p], tBh + sw_off(wn + p * 16 + b_r, bg));
#pragma unroll
            for (int mt = 0; mt < 4; mt++)
#pragma unroll
                for (int nt = 0; nt < 4; nt++)
                    mma16816(acc[mt][nt], a[mt], b[nt >> 1][(nt & 1) * 2], b[nt >> 1][(nt & 1) * 2 + 1]);
        }
        if (++bufc == NSTAGE) bufc = 0;
    }

    const int gid = lane >> 2, tig = lane & 3;
#pragma unroll
    for (int mt = 0; mt < 4; mt++) {
        const int row0 = mBase + wm + mt * 16 + gid;
#pragma unroll
        for (int nt = 0; nt < 4; nt++) {
            const int col = nBase + wn + nt * 8 + tig * 2;
            if (col < Nd) {
                float2 v01 = make_float2(acc[mt][nt][0], acc[mt][nt][1]);
                float2 v23 = make_float2(acc[mt][nt][2], acc[mt][nt][3]);
                *reinterpret_cast<float2*>(C + (size_t)row0 * Nd + col) = v01;
                *reinterpret_cast<float2*>(C + (size_t)(row0 + 8) * Nd + col) = v23;
            }
        }
    }
}

// ============================================================
// Conv (kernel=2, causal) + SiLU -> bf16 hi/lo, 4 channels/thread
// ============================================================
__global__ void conv_silu_kernel(const float* __restrict__ conv_w,
                                 const float* __restrict__ conv_b) {
    const int i = blockIdx.x * blockDim.x + threadIdx.x;       // over BB*LL*CONV/4
    if (i >= BB * LL * (CONV / 4)) return;
    const int c4 = (i % (CONV / 4)) * 4;
    const size_t bl = (size_t)(i / (CONV / 4));
    const int l = (int)(bl % LL);

    const float4 cur = *reinterpret_cast<const float4*>(&g_proj[bl * PROJ + c4]);
    float4 prev = make_float4(0.f, 0.f, 0.f, 0.f);
    if (l > 0)
        prev = *reinterpret_cast<const float4*>(&g_proj[(bl - 1) * PROJ + c4]);
    const float4 w01 = *reinterpret_cast<const float4*>(&conv_w[c4 * 2]);      // w[c4].xy, w[c4+1].xy
    const float4 w23 = *reinterpret_cast<const float4*>(&conv_w[c4 * 2 + 4]);  // w[c4+2], w[c4+3]
    const float4 bb4 = *reinterpret_cast<const float4*>(&conv_b[c4]);

    float o[4];
    {
        const float v0 = prev.x * w01.x + cur.x * w01.y + bb4.x;
        const float v1 = prev.y * w01.z + cur.y * w01.w + bb4.y;
        const float v2 = prev.z * w23.x + cur.z * w23.y + bb4.z;
        const float v3 = prev.w * w23.z + cur.w * w23.w + bb4.w;
        o[0] = v0 * sigmoidf_(v0);
        o[1] = v1 * sigmoidf_(v1);
        o[2] = v2 * sigmoidf_(v2);
        o[3] = v3 * sigmoidf_(v3);
    }
    uint32_t h0, l0, h1, l1;
    split_pair(o[0], o[1], h0, l0);
    split_pair(o[2], o[3], h1, l1);
    const size_t oidx = bl * CONV + c4;
    *reinterpret_cast<uint2*>(&g_vkhi[oidx]) = make_uint2(h0, h1);
    *reinterpret_cast<uint2*>(&g_vklo[oidx]) = make_uint2(l0, l1);
}

__global__ void dt_kernel(const float* __restrict__ dt_bias,
                          const float* __restrict__ A_log_bias) {
    const int idx = blockIdx.x * blockDim.x + threadIdx.x;
    if (idx >= BB * LL * HH) return;
    const int h = idx % HH;
    const size_t bl = idx / HH;
    const float raw = g_proj[bl * PROJ + (CONV + DD) + h];
    const float dtv = softplusf_(raw + dt_bias[h]);
    g_dt[idx] = dtv;
    g_adt[idx] = dtv * (-expf(A_log_bias[h]));
}

// ============================================================
// Pass A (mma): per-(b,c,h) parallel cumsum + local chunk state
// 256 threads, 8 warps (2 n-halves x 4 p-groups, warp tile 32x16).
// ============================================================
#define CS_KH   0
#define CS_KL   16384
#define CS_XH   32768
#define CS_XL   49152
#define CS_ACS  65536
#define CS_SMEM (65536 + 512)

__global__ __launch_bounds__(256) void chunk_state_mma() {
    extern __shared__ __align__(16) char dsm[];
    const uint32_t sb = smem_u32(dsm);
    float* sAcs = reinterpret_cast<float*>(dsm + CS_ACS);

    const int h = blockIdx.x, c = blockIdx.y, b = blockIdx.z;
    const int tid = threadIdx.x;
    const int kvh = h >> 2;

    // issue X tile loads immediately (overlap with cumsum)
    {
        const size_t rowbase = ((size_t)b * LL + c * CHUNK) * CONV + (size_t)kvh * PP;
        for (int i = tid; i < 1024; i += 256) {
            const int r = i >> 3, g = i & 7;
            const uint32_t d = swz128(r, g);
            const size_t s = rowbase + (size_t)r * CONV + g * 8;
            cpa16(sb + CS_XH + d, g_vkhi + s, 16);
            cpa16(sb + CS_XL + d, g_vklo + s, 16);
        }
        cpa_commit();
    }

    if (tid < CHUNK)
        sAcs[tid] = g_adt[((size_t)b * LL + c * CHUNK + tid) * HH + h];
    __syncthreads();
    // Hillis-Steele inclusive scan over 128 elements (all threads hit barriers)
#pragma unroll
    for (int off = 1; off < CHUNK; off <<= 1) {
        float v = 0.f, u = 0.f;
        if (tid < CHUNK) {
            v = sAcs[tid];
            u = (tid >= off) ? sAcs[tid - off] : 0.f;
        }
        __syncthreads();
        if (tid < CHUNK) sAcs[tid] = v + u;
        __syncthreads();
    }
    const float total = sAcs[CHUNK - 1];
    if (tid < CHUNK)
        g_acs[(((size_t)b * HH + h) * NC + c) * CHUNK + tid] = sAcs[tid];
    if (tid == 0)
        g_tot[((size_t)b * HH + h) * NC + c] = total;

    // K tile: reconstruct + scale by w*dt + split; half-row per thread
    {
        const int l = tid >> 1;
        const int c0 = (tid & 1) * 32;
        const size_t base = ((size_t)b * LL + c * CHUNK + l) * CONV;
        const float w = expf(total - sAcs[l]);
        const float dtv = g_dt[((size_t)b * LL + c * CHUNK + l) * HH + h];
        const size_t ko = base + KVH * PP + kvh * PP + c0;
        const float ws = w * dtv;
        split_row32_rec(sb + CS_KH, sb + CS_KL, g_vkhi + ko, g_vklo + ko, l, c0, ws);
    }
    cpa_wait<0>();
    __syncthreads();

    const int warp = tid >> 5, lane = tid & 31;     // warp 0..7
    const int wM = (warp >> 2);                     // n-half 0/1 (32 rows each)
    const int wn = (warp & 3) * 16;                 // p tile base
    const int tA_kr = (lane & 7) + ((lane >> 4) & 1) * 8;
    const int tA_mg = (lane >> 3) & 1;
    const int tB_kr = (lane & 7) + ((lane >> 3) & 1) * 8;
    const int tB_ng = (lane >> 4) & 1;

    float acc[2][2][4];
#pragma unroll
    for (int i = 0; i < 2; i++)
#pragma unroll
        for (int j = 0; j < 2; j++)
#pragma unroll
            for (int k = 0; k < 4; k++) acc[i][j][k] = 0.f;

#pragma unroll
    for (int ks = 0; ks < 8; ks++) {
        const int kra = ks * 16 + tA_kr;
        const int krb = ks * 16 + tB_kr;
        uint32_t ah[2][4], al[2][4], bh[4], bl[4];
#pragma unroll
        for (int mt = 0; mt < 2; mt++)
            ldsm_x4_t(ah[mt], sb + CS_KH + swz128(kra, wM * 4 + mt * 2 + tA_mg));
        ldsm_x4_t(bh, sb + CS_XH + swz128(krb, (wn >> 3) + tB_ng));
#pragma unroll
        for (int mt = 0; mt < 2; mt++)
#pragma unroll
            for (int nt = 0; nt < 2; nt++)
                mma16816(acc[mt][nt], ah[mt], bh[nt * 2], bh[nt * 2 + 1]);
#pragma unroll
        for (int mt = 0; mt < 2; mt++)
            ldsm_x4_t(al[mt], sb + CS_KL + swz128(kra, wM * 4 + mt * 2 + tA_mg));
#pragma unroll
        for (int mt = 0; mt < 2; mt++)
#pragma unroll
            for (int nt = 0; nt < 2; nt++)
                mma16816(acc[mt][nt], al[mt], bh[nt * 2], bh[nt * 2 + 1]);
        ldsm_x4_t(bl, sb + CS_XL + swz128(krb, (wn >> 3) + tB_ng));
#pragma unroll
        for (int mt = 0; mt < 2; mt++)
#pragma unroll
            for (int nt = 0; nt < 2; nt++)
                mma16816(acc[mt][nt], ah[mt], bl[nt * 2], bl[nt * 2 + 1]);
    }

    const int gid = lane >> 2, tig = lane & 3;
    const size_t so = (((size_t)b * NC + c) * HH + h) * (PP * PP);
#pragma unroll
    for (int mt = 0; mt < 2; mt++) {
        const int n0 = wM * 32 + mt * 16 + gid;
#pragma unroll
        for (int nt = 0; nt < 2; nt++) {
            const int p = wn + nt * 8 + tig * 2;
            *reinterpret_cast<float2*>(&g_states[so + (size_t)n0 * PP + p]) =
                make_float2(acc[mt][nt][0], acc[mt][nt][1]);
            *reinterpret_cast<float2*>(&g_states[so + (size_t)(n0 + 8) * PP + p]) =
                make_float2(acc[mt][nt][2], acc[mt][nt][3]);
        }
    }
}

// ============================================================
// Pass B: inter-chunk scan; preloads all 16 chunk-local states
// (MLP=16) then scans from registers; emits bf16 hi/lo.
// ============================================================
__global__ void state_scan_kernel() {
    __shared__ float et[NC];
    const int bh = blockIdx.x >> 3;
    const int slab = blockIdx.x & 7;
    const int b = bh / HH, h = bh % HH;
    if (threadIdx.x < NC)
        et[threadIdx.x] = expf(g_tot[(size_t)bh * NC + threadIdx.x]);
    __syncthreads();
    const int e0 = slab * 512;
    for (int e = e0 + threadIdx.x; e < e0 + 512; e += blockDim.x) {
        const size_t base = ((size_t)b * NC * HH + h) * (PP * PP) + e;
        const size_t cstride = (size_t)HH * PP * PP;
        float loc[NC];
#pragma unroll
        for (int c = 0; c < NC; c++)
            loc[c] = g_states[base + (size_t)c * cstride];
        float S = 0.f;
#pragma unroll
        for (int c = 0; c < NC; c++) {
            const size_t idx = base + (size_t)c * cstride;
            const __nv_bfloat16 hi = __float2bfloat16(S);
            g_shi[idx] = hi;
            g_slo[idx] = __float2bfloat16(S - __bfloat162float(hi));
            S = et[c] * S + loc[c];
        }
    }
}

// ============================================================
// Pass C (mma): Y = (mask(C.B^T)·decay·dt) X + exp(Acs) C.S_start
// 512 threads, 16 warps (R15 passing config).
// ============================================================
#define Y_CH   0
#define Y_CL   16384
#define Y_BH   32768
#define Y_BL   49152
#define Y_XH   65536
#define Y_XL   81920
#define Y_SH   98304
#define Y_SL   106496
#define Y_GH   0            // overlays C (hi+lo)
#define Y_GL   32768        // overlays B (hi+lo)
#define Y_ACS  114688
#define Y_DT   (114688 + 512)
#define Y_SMEM (114688 + 1024 + 64)

__global__ __launch_bounds__(512) void y_mma() {
    extern __shared__ __align__(16) char dsm[];
    const uint32_t sb = smem_u32(dsm);
    float* sAcs = reinterpret_cast<float*>(dsm + Y_ACS);
    float* sDt  = reinterpret_cast<float*>(dsm + Y_DT);

    const int h = blockIdx.x, c = blockIdx.y, b = blockIdx.z;
    const int tid = threadIdx.x;
    const int kvh = h >> 2;

    // async tile loads: C, B, X, S hi/lo straight from bf16 arrays
    {
        const size_t rowbase = ((size_t)b * LL + c * CHUNK) * CONV;
        const uint32_t offC = 2 * KVH * PP + h * PP;
        const uint32_t offB = KVH * PP + kvh * PP;
        const uint32_t offX = kvh * PP;
        for (int i = tid; i < 1024; i += 512) {
            const int r = i >> 3, g = i & 7;
            const uint32_t d = swz128(r, g);
            const size_t s = rowbase + (size_t)r * CONV + g * 8;
            cpa16(sb + Y_CH + d, g_vkhi + s + offC, 16);
            cpa16(sb + Y_CL + d, g_vklo + s + offC, 16);
            cpa16(sb + Y_BH + d, g_vkhi + s + offB, 16);
            cpa16(sb + Y_BL + d, g_vklo + s + offB, 16);
            cpa16(sb + Y_XH + d, g_vkhi + s + offX, 16);
            cpa16(sb + Y_XL + d, g_vklo + s + offX, 16);
        }
        const size_t stbase = (((size_t)b * NC + c) * HH + h) * (PP * PP);
        if (tid < 512) {
            const int r = tid >> 3, g = tid & 7;    // r = n row 0..63
            const uint32_t d = swz128(r, g);
            const size_t s = stbase + (size_t)r * PP + g * 8;
            cpa16(sb + Y_SH + d, g_shi + s, 16);
            cpa16(sb + Y_SL + d, g_slo + s, 16);
        }
        cpa_commit();
    }

    if (tid < CHUNK) {
        sAcs[tid] = g_acs[(((size_t)b * HH + h) * NC + c) * CHUNK + tid];
        sDt[tid]  = g_dt[((size_t)b * LL + c * CHUNK + tid) * HH + h];
    }
    cpa_wait<0>();
    __syncthreads();

    const int warp = tid >> 5, lane = tid & 31;    // warp 0..15
    const int wm = (warp >> 2) * 32;               // m tile base (4 groups of 32)
    const int wn32 = (warp & 3) * 32;
    const int wn16 = (warp & 3) * 16;
    const int gid = lane >> 2, tig = lane & 3;

    const int a_r = lane & 15, a_g = lane >> 4;
    const int b_r = (lane & 7) + ((lane & 16) >> 1), b_g = (lane >> 3) & 1;
    const int tB_kr = (lane & 7) + ((lane >> 3) & 1) * 8;
    const int tB_ng = (lane >> 4) & 1;

    // -------- pass 1b FIRST: Yo = C . S^T --------
    float accY[2][2][4];
#pragma unroll
    for (int i = 0; i < 2; i++)
#pragma unroll
        for (int j = 0; j < 2; j++)
#pragma unroll
            for (int k = 0; k < 4; k++) accY[i][j][k] = 0.f;

#pragma unroll
    for (int ks = 0; ks < 4; ks++) {
        uint32_t ah[2][4], al[2][4], bh[4], bl[4];
        const int ag = 2 * ks + a_g;
        const int krb = ks * 16 + tB_kr;
#pragma unroll
        for (int mt = 0; mt < 2; mt++)
            ldsm_x4(ah[mt], sb + Y_CH + swz128(wm + mt * 16 + a_r, ag));
        ldsm_x4_t(bh, sb + Y_SH + swz128(krb, (wn16 >> 3) + tB_ng));
#pragma unroll
        for (int mt = 0; mt < 2; mt++)
#pragma unroll
            for (int nt = 0; nt < 2; nt++)
                mma16816(accY[mt][nt], ah[mt], bh[nt * 2], bh[nt * 2 + 1]);
#pragma unroll
        for (int mt = 0; mt < 2; mt++)
            ldsm_x4(al[mt], sb + Y_CL + swz128(wm + mt * 16 + a_r, ag));
#pragma unroll
        for (int mt = 0; mt < 2; mt++)
#pragma unroll
            for (int nt = 0; nt < 2; nt++)
                mma16816(accY[mt][nt], al[mt], bh[nt * 2], bh[nt * 2 + 1]);
        ldsm_x4_t(bl, sb + Y_SL + swz128(krb, (wn16 >> 3) + tB_ng));
#pragma unroll
        for (int mt = 0; mt < 2; mt++)
#pragma unroll
            for (int nt = 0; nt < 2; nt++)
                mma16816(accY[mt][nt], ah[mt], bl[nt * 2], bl[nt * 2 + 1]);
    }

#pragma unroll
    for (int mt = 0; mt < 2; mt++) {
        const float e0 = expf(sAcs[wm + mt * 16 + gid]);
        const float e1 = expf(sAcs[wm + mt * 16 + gid + 8]);
#pragma unroll
        for (int nt = 0; nt < 2; nt++) {
            accY[mt][nt][0] *= e0; accY[mt][nt][1] *= e0;
            accY[mt][nt][2] *= e1; accY[mt][nt][3] *= e1;
        }
    }

    // -------- pass 1a: G = C . Bt^T --------
    {
        float accG[2][4][4];
#pragma unroll
        for (int i = 0; i < 2; i++)
#pragma unroll
            for (int j = 0; j < 4; j++)
#pragma unroll
                for (int k = 0; k < 4; k++) accG[i][j][k] = 0.f;

#pragma unroll
        for (int ks = 0; ks < 4; ks++) {
            uint32_t ah[2][4], al[2][4], bh[2][4], bl[2][4];
            const int ag = 2 * ks + a_g, bg = 2 * ks + b_g;
#pragma unroll
            for (int mt = 0; mt < 2; mt++)
                ldsm_x4(ah[mt], sb + Y_CH + swz128(wm + mt * 16 + a_r, ag));
#pragma unroll
            for (int p = 0; p < 2; p++)
                ldsm_x4(bh[p], sb + Y_BH + swz128(wn32 + p * 16 + b_r, bg));
#pragma unroll
            for (int mt = 0; mt < 2; mt++)
#pragma unroll
                for (int nt = 0; nt < 4; nt++)
                    mma16816(accG[mt][nt], ah[mt], bh[nt >> 1][(nt & 1) * 2], bh[nt >> 1][(nt & 1) * 2 + 1]);
#pragma unroll
            for (int mt = 0; mt < 2; mt++)
                ldsm_x4(al[mt], sb + Y_CL + swz128(wm + mt * 16 + a_r, ag));
#pragma unroll
            for (int mt = 0; mt < 2; mt++)
#pragma unroll
                for (int nt = 0; nt < 4; nt++)
                    mma16816(accG[mt][nt], al[mt], bh[nt >> 1][(nt & 1) * 2], bh[nt >> 1][(nt & 1) * 2 + 1]);
#pragma unroll
            for (int p = 0; p < 2; p++)
                ldsm_x4(bl[p], sb + Y_BL + swz128(wn32 + p * 16 + b_r, bg));
#pragma unroll
            for (int mt = 0; mt < 2; mt++)
#pragma unroll
                for (int nt = 0; nt < 4; nt++)
                    mma16816(accG[mt][nt], ah[mt], bl[nt >> 1][(nt & 1) * 2], bl[nt >> 1][(nt & 1) * 2 + 1]);
        }

        __syncthreads();   // all warps done reading C/B before overlay

#pragma unroll
        for (int mt = 0; mt < 2; mt++) {
            const int l0 = wm + mt * 16 + gid;
            const int l1 = l0 + 8;
            const float A0 = sAcs[l0], A1 = sAcs[l1];
#pragma unroll
            for (int nt = 0; nt < 4; nt++) {
                const int s0 = wn32 + nt * 8 + tig * 2;
                const int s1 = s0 + 1;
                const float As0 = sAcs[s0], As1 = sAcs[s1];
                const float d0 = sDt[s0], d1 = sDt[s1];
                float g00 = (s0 <= l0) ? accG[mt][nt][0] * expf(A0 - As0) * d0 : 0.f;
                float g01 = (s1 <= l0) ? accG[mt][nt][1] * expf(A0 - As1) * d1 : 0.f;
                float g10 = (s0 <= l1) ? accG[mt][nt][2] * expf(A1 - As0) * d0 : 0.f;
                float g11 = (s1 <= l1) ? accG[mt][nt][3] * expf(A1 - As1) * d1 : 0.f;
                uint32_t hp, lp;
                const uint32_t a0 = swz256(l0, s0 >> 3) + ((s0 & 7) << 1);
                split_pair(g00, g01, hp, lp);
                asm volatile("st.shared.b32 [%0], %1;" :: "r"(sb + Y_GH + a0), "r"(hp));
                asm volatile("st.shared.b32 [%0], %1;" :: "r"(sb + Y_GL + a0), "r"(lp));
                const uint32_t a1 = swz256(l1, s0 >> 3) + ((s0 & 7) << 1);
                split_pair(g10, g11, hp, lp);
                asm volatile("st.shared.b32 [%0], %1;" :: "r"(sb + Y_GH + a1), "r"(hp));
                asm volatile("st.shared.b32 [%0], %1;" :: "r"(sb + Y_GL + a1), "r"(lp));
            }
        }
    }

    __syncthreads();

    // -------- pass 2: Y += G' . X^T  (X = raw v) --------
#pragma unroll
    for (int ks = 0; ks < 8; ks++) {
        uint32_t ah[2][4], al[2][4], bh[4], bl[4];
        const int ag = 2 * ks + a_g;
        const int krb = ks * 16 + tB_kr;
#pragma unroll
        for (int mt = 0; mt < 2; mt++)
            ldsm_x4(ah[mt], sb + Y_GH + swz256(wm + mt * 16 + a_r, ag));
        ldsm_x4_t(bh, sb + Y_XH + swz128(krb, (wn16 >> 3) + tB_ng));
#pragma unroll
        for (int mt = 0; mt < 2; mt++)
#pragma unroll
            for (int nt = 0; nt < 2; nt++)
                mma16816(accY[mt][nt], ah[mt], bh[nt * 2], bh[nt * 2 + 1]);
#pragma unroll
        for (int mt = 0; mt < 2; mt++)
            ldsm_x4(al[mt], sb + Y_GL + swz256(wm + mt * 16 + a_r, ag));
#pragma unroll
        for (int mt = 0; mt < 2; mt++)
#pragma unroll
            for (int nt = 0; nt < 2; nt++)
                mma16816(accY[mt][nt], al[mt], bh[nt * 2], bh[nt * 2 + 1]);
        ldsm_x4_t(bl, sb + Y_XL + swz128(krb, (wn16 >> 3) + tB_ng));
#pragma unroll
        for (int mt = 0; mt < 2; mt++)
#pragma unroll
            for (int nt = 0; nt < 2; nt++)
                mma16816(accY[mt][nt], ah[mt], bl[nt * 2], bl[nt * 2 + 1]);
    }

#pragma unroll
    for (int mt = 0; mt < 2; mt++) {
        const int l0 = wm + mt * 16 + gid;
#pragma unroll
        for (int nt = 0; nt < 2; nt++) {
            const int p = wn16 + nt * 8 + tig * 2;
            const size_t y0 = ((size_t)b * LL + c * CHUNK + l0) * DD + h * PP + p;
            const size_t y1 = ((size_t)b * LL + c * CHUNK + l0 + 8) * DD + h * PP + p;
            *reinterpret_cast<float2*>(&g_y[y0]) = make_float2(accY[mt][nt][0], accY[mt][nt][1]);
            *reinterpret_cast<float2*>(&g_y[y1]) = make_float2(accY[mt][nt][2], accY[mt][nt][3]);
        }
    }
}

// ============================================================
// Pass D: RMSNorm + swish gate -> bf16 hi/lo; warp-per-row
// ============================================================
__global__ __launch_bounds__(256) void normgate_kernel(const float* __restrict__ gnorm_w) {
    const int r = blockIdx.x * 8 + (threadIdx.x >> 5);   // row = (b*L + l)*H + h
    const int lane = threadIdx.x & 31;
    const int h = r % HH;
    const size_t bl = (size_t)r / HH;
    const size_t yb = bl * DD + (size_t)h * PP;
    const float y0 = g_y[yb + lane];
    const float y1 = g_y[yb + lane + 32];
    float s = y0 * y0 + y1 * y1;
#pragma unroll
    for (int o = 16; o > 0; o >>= 1) s += __shfl_xor_sync(0xffffffffu, s, o);
    const float rms = rsqrtf(s / (float)PP + EPS);
    const size_t gb = bl * PROJ + CONV + (size_t)h * PP;
#pragma unroll
    for (int q = 0; q < 2; q++) {
        const int p = lane + q * 32;
        const float yv = (q == 0) ? y0 : y1;
        const float gv = g_proj[gb + p];
        const float out = yv * rms * gnorm_w[p] * (gv * sigmoidf_(gv));
        __nv_bfloat16 hi = __float2bfloat16(out);
        g_yhi[yb + p] = hi;
        g_ylo[yb + p] = __float2bfloat16(out - __bfloat162float(hi));
    }
}

// ============================================================
// launch
// ============================================================
extern "C" void kernel_launch(void* const* d_in, const int* in_sizes, int n_in,
                              void* d_out, int out_size) {
    const float* hidden   = (const float*)d_in[0];
    const float* W_vkqgdt = (const float*)d_in[1];
    const float* conv_w   = (const float*)d_in[2];
    const float* conv_b   = (const float*)d_in[3];
    const float* dt_bias  = (const float*)d_in[4];
    const float* A_logb   = (const float*)d_in[5];
    const float* gnorm_w  = (const float*)d_in[6];
    const float* W_o      = (const float*)d_in[7];
    float* out = (float*)d_out;

    float* proj_ptr;
    cudaGetSymbolAddress((void**)&proj_ptr, g_proj);
    __nv_bfloat16 *hhi, *hlo, *whi, *wlo, *ohi, *olo, *yhi, *ylo;
    cudaGetSymbolAddress((void**)&hhi, g_hhi);
    cudaGetSymbolAddress((void**)&hlo, g_hlo);
    cudaGetSymbolAddress((void**)&whi, g_whi);
    cudaGetSymbolAddress((void**)&wlo, g_wlo);
    cudaGetSymbolAddress((void**)&ohi, g_ohi);
    cudaGetSymbolAddress((void**)&olo, g_olo);
    cudaGetSymbolAddress((void**)&yhi, g_yhi);
    cudaGetSymbolAddress((void**)&ylo, g_ylo);

    cudaFuncSetAttribute(gemm_mma, cudaFuncAttributeMaxDynamicSharedMemorySize, GEMM_SMEM);
    cudaFuncSetAttribute(chunk_state_mma, cudaFuncAttributeMaxDynamicSharedMemorySize, CS_SMEM);
    cudaFuncSetAttribute(y_mma, cudaFuncAttributeMaxDynamicSharedMemorySize, Y_SMEM);

    // 0) split inputs
    {
        const int n4a = (BB * LL * DD) / 4;
        split_kernel<<<(n4a + 255) / 256, 256>>>(hidden, hhi, hlo, n4a);
        const int n4w = (PROJ * DD) / 4;
        split_kernel<<<(n4w + 255) / 256, 256>>>(W_vkqgdt, whi, wlo, n4w);
        const int n4o = (DD * DD) / 4;
        split_kernel<<<(n4o + 255) / 256, 256>>>(W_o, ohi, olo, n4o);
    }

    // 1) in-projection
    gemm_mma<<<dim3((PROJ + 127) / 128, (BB * LL) / 128), 256, GEMM_SMEM>>>(
        proj_ptr, hhi, hlo, whi, wlo, PROJ, DD);

    // 2) conv + silu (vectorized x4, emits bf16 hi/lo), dt
    {
        const int tot4 = BB * LL * (CONV / 4);
        conv_silu_kernel<<<(tot4 + 255) / 256, 256>>>(conv_w, conv_b);
        dt_kernel<<<(BB * LL * HH + 255) / 256, 256>>>(dt_bias, A_logb);
    }

    // 3) SSD (tensor-core)
    chunk_state_mma<<<dim3(HH, NC, BB), 256, CS_SMEM>>>();
    state_scan_kernel<<<BB * HH * 8, 256>>>();
    y_mma<<<dim3(HH, NC, BB), 512, Y_SMEM>>>();

    // 4) norm + gate (warp-per-row, emits bf16 hi/lo)
    normgate_kernel<<<BB * LL * HH / 8, 256>>>(gnorm_w);

    // 5) out-projection
    gemm_mma<<<dim3(DD / 128, (BB * LL) / 128), 256, GEMM_SMEM>>>(
        out, yhi, ylo, ohi, olo, DD, DD);
}